// round 3
// baseline (speedup 1.0000x reference)
#include <cuda_runtime.h>
#include <math.h>

// Problem constants
#define T_STEPS 100
#define BATCH   4096
#define NH      128
#define NG      512
#define NPC     256
#define NHD     12
#define NB      256
#define KIN     268   // NPC + NHD

// Output layout: tuple (hd, pc, bn, hs, cs) flattened in order
#define HD_OFF  ((size_t)0)
#define PC_OFF  ((size_t)T_STEPS * BATCH * NHD)
#define BN_OFF  (PC_OFF + (size_t)T_STEPS * BATCH * NPC)
#define HS_OFF  (BN_OFF + (size_t)T_STEPS * BATCH * NB)
#define CS_OFF  (HS_OFF + (size_t)T_STEPS * BATCH * NH)

__device__ __forceinline__ float sigf(float v) { return 1.0f / (1.0f + expf(-v)); }

// ===========================================================================
// Phase 1: recurrence. Each CTA owns 32 batch rows for all 100 steps.
// Per step: gates[32,512] = h[32,128] @ W_hh^T + x-term + bias; elementwise.
// 256 threads, thread tile 8 rows x 8 cols (cols = 4*tx+e + 256*g).
// ===========================================================================
#define R_HS    (32*128)
#define R_CS    (32*128)
#define R_WT    (16*516)    // W_hh k-tile transposed, padded stride 516
#define R_GATES (32*512)    // also reused for initS (32*268 fits)
#define R_X     (32*4)
#define R_WIH   (512*3)
#define R_BIAS  (512)
#define R_SMEM_FLOATS (R_HS + R_CS + R_WT + R_GATES + R_X + R_WIH + R_BIAS)

__global__ void __launch_bounds__(256, 1)
recur_kernel(const float* __restrict__ x,
             const float* __restrict__ init_pc,
             const float* __restrict__ init_hd,
             const float* __restrict__ W_state, const float* __restrict__ b_state,
             const float* __restrict__ W_cell,  const float* __restrict__ b_cell,
             const float* __restrict__ W_ih,    const float* __restrict__ W_hh,
             const float* __restrict__ b_ih,    const float* __restrict__ b_hh,
             float* __restrict__ out)
{
    extern __shared__ float sm[];
    float* hS    = sm;
    float* cS    = hS + R_HS;
    float* wT    = cS + R_CS;      // [16][516] during steps; [64][129] during init
    float* gS    = wT + R_WT;      // gates [32][512]; initS [32][268] during init
    float* xS    = gS + R_GATES;   // [32][4]
    float* wihS  = xS + R_X;       // [512][3]
    float* biasS = wihS + R_WIH;   // [512] = b_ih + b_hh

    const int tid = threadIdx.x;
    const int tx  = tid & 63;
    const int ty  = tid >> 6;
    const int r0  = ty * 8;
    const int gb0 = blockIdx.x * 32;

    // preload W_ih and combined bias
    for (int i = tid; i < 512 * 3; i += 256) wihS[i] = W_ih[i];
    for (int i = tid; i < 512; i += 256)     biasS[i] = b_ih[i] + b_hh[i];

    // ---- init: concat(init_pc, init_hd) for our 32 rows -> gS region ----
    float* initS = gS;  // [32][268]
    for (int i = tid; i < 32 * KIN; i += 256) {
        int r = i / KIN, k = i - r * KIN;
        float v = (k < 256) ? init_pc[(size_t)(gb0 + r) * 256 + k]
                            : init_hd[(size_t)(gb0 + r) * 12 + (k - 256)];
        initS[r * KIN + k] = v;
    }
    __syncthreads();

    // ---- h0 = init @ W_state^T + b_state ; c0 likewise with W_cell ----
    for (int p = 0; p < 2; ++p) {
        const float* W  = p ? W_cell : W_state;
        const float* bb = p ? b_cell : b_state;
        float acc[16];
        #pragma unroll
        for (int o = 0; o < 16; ++o) acc[o] = 0.0f;

        for (int kt = 0; kt < KIN; kt += 64) {
            int len = KIN - kt; if (len > 64) len = 64;
            // transposed tile wT[kk][n], stride 129 (conflict-free)
            for (int i = tid; i < 128 * 64; i += 256) {
                int n = i >> 6, kk = i & 63;
                if (kk < len) wT[kk * 129 + n] = W[n * KIN + kt + kk];
            }
            __syncthreads();
            for (int kk = 0; kk < len; ++kk) {
                #pragma unroll
                for (int o = 0; o < 16; ++o) {
                    int idx = o * 256 + tid;
                    int r = idx >> 7, n = idx & 127;
                    acc[o] += initS[r * KIN + kt + kk] * wT[kk * 129 + n];
                }
            }
            __syncthreads();
        }
        float* dst = p ? cS : hS;
        #pragma unroll
        for (int o = 0; o < 16; ++o) {
            int idx = o * 256 + tid;
            int r = idx >> 7, n = idx & 127;
            dst[r * 128 + n] = acc[o] + bb[n];
        }
        __syncthreads();
    }

    // ---- time loop ----
    for (int t = 0; t < T_STEPS; ++t) {
        if (tid < 96) {
            int r = tid / 3, cc = tid - r * 3;
            xS[r * 4 + cc] = x[((size_t)t * BATCH + gb0 + r) * 3 + cc];
        }
        __syncthreads();

        float acc[8][8];
        #pragma unroll
        for (int i = 0; i < 8; ++i)
            #pragma unroll
            for (int j = 0; j < 8; ++j) acc[i][j] = 0.0f;

        // gates = h @ W_hh^T  (K = 128 in 8 tiles of 16)
        for (int kt = 0; kt < 128; kt += 16) {
            #pragma unroll
            for (int it = 0; it < 8; ++it) {
                int idx = it * 256 + tid;       // 2048 float4 quads
                int n = idx >> 2, q = idx & 3;
                float4 w = *(const float4*)&W_hh[n * 128 + kt + 4 * q];
                wT[(4 * q + 0) * 516 + n] = w.x;
                wT[(4 * q + 1) * 516 + n] = w.y;
                wT[(4 * q + 2) * 516 + n] = w.z;
                wT[(4 * q + 3) * 516 + n] = w.w;
            }
            __syncthreads();
            #pragma unroll
            for (int k4 = 0; k4 < 16; k4 += 4) {
                float4 ha[8];
                #pragma unroll
                for (int i = 0; i < 8; ++i)
                    ha[i] = *(const float4*)&hS[(r0 + i) * 128 + kt + k4];
                #pragma unroll
                for (int e = 0; e < 4; ++e) {
                    int kk = k4 + e;
                    float4 w0 = *(const float4*)&wT[kk * 516 + 4 * tx];
                    float4 w1 = *(const float4*)&wT[kk * 516 + 256 + 4 * tx];
                    #pragma unroll
                    for (int i = 0; i < 8; ++i) {
                        float a = (e == 0) ? ha[i].x : (e == 1) ? ha[i].y
                                : (e == 2) ? ha[i].z : ha[i].w;
                        acc[i][0] += a * w0.x; acc[i][1] += a * w0.y;
                        acc[i][2] += a * w0.z; acc[i][3] += a * w0.w;
                        acc[i][4] += a * w1.x; acc[i][5] += a * w1.y;
                        acc[i][6] += a * w1.z; acc[i][7] += a * w1.w;
                    }
                }
            }
            __syncthreads();
        }

        // add x @ W_ih^T + bias, write gates to smem
        #pragma unroll
        for (int g = 0; g < 2; ++g) {
            int nb = 4 * tx + 256 * g;
            float wc[4][3], bc[4];
            #pragma unroll
            for (int e = 0; e < 4; ++e) {
                wc[e][0] = wihS[(nb + e) * 3 + 0];
                wc[e][1] = wihS[(nb + e) * 3 + 1];
                wc[e][2] = wihS[(nb + e) * 3 + 2];
                bc[e]    = biasS[nb + e];
            }
            #pragma unroll
            for (int i = 0; i < 8; ++i) {
                int r = r0 + i;
                float x0 = xS[r * 4 + 0], x1 = xS[r * 4 + 1], x2 = xS[r * 4 + 2];
                float4 v;
                v.x = acc[i][g * 4 + 0] + x0 * wc[0][0] + x1 * wc[0][1] + x2 * wc[0][2] + bc[0];
                v.y = acc[i][g * 4 + 1] + x0 * wc[1][0] + x1 * wc[1][1] + x2 * wc[1][2] + bc[1];
                v.z = acc[i][g * 4 + 2] + x0 * wc[2][0] + x1 * wc[2][1] + x2 * wc[2][2] + bc[2];
                v.w = acc[i][g * 4 + 3] + x0 * wc[3][0] + x1 * wc[3][1] + x2 * wc[3][2] + bc[3];
                *(float4*)&gS[r * 512 + nb] = v;
            }
        }
        __syncthreads();

        // elementwise LSTM update; write hs/cs outputs
        #pragma unroll
        for (int o = 0; o < 16; ++o) {
            int idx = o * 256 + tid;
            int r = idx >> 7, j = idx & 127;
            float ig = sigf(gS[r * 512 + j]);
            float fg = sigf(gS[r * 512 + 128 + j]);
            float gg = tanhf(gS[r * 512 + 256 + j]);
            float og = sigf(gS[r * 512 + 384 + j]);
            float c = fg * cS[r * 128 + j] + ig * gg;
            float h = og * tanhf(c);
            cS[r * 128 + j] = c;
            hS[r * 128 + j] = h;
            size_t row = (size_t)t * BATCH + gb0 + r;
            out[HS_OFF + row * 128 + j] = h;
            out[CS_OFF + row * 128 + j] = c;
        }
        __syncthreads();
    }
}

// ===========================================================================
// Phase 2a: bn = tanh(HS @ W_bn^T).  M = 409600 in tiles of 128. 512 threads.
// Thread tile 8x8; cols n = 4*tx+e + 128*g. W tile transposed with XOR
// swizzle (s = ((k>>2)&7)<<2 on column bits 2..4) -> conflict-free LDS+STS.
// ===========================================================================
#define BN_A (128*128)
#define BN_W (128*260)

__global__ void __launch_bounds__(512, 1)
bn_kernel(const float* __restrict__ W_bn, float* __restrict__ out)
{
    extern __shared__ float sm[];
    float* As = sm;             // [128][128]
    float* Wt = sm + BN_A;      // [128][260], columns swizzled

    const int tid = threadIdx.x;
    const int tx  = tid & 31;
    const int ty  = tid >> 5;
    const int r0  = ty * 8;
    const size_t grow = (size_t)blockIdx.x * 128;
    const float* hsrc = out + HS_OFF + grow * 128;

    for (int it = 0; it < 8; ++it) {
        int idx = it * 512 + tid;     // 4096 float4
        ((float4*)As)[idx] = ((const float4*)hsrc)[idx];
    }
    for (int it = 0; it < 16; ++it) {
        int idx = it * 512 + tid;     // 8192 quads of W_bn [256][128]
        int q = (idx & 7) | (((idx >> 8) & 3) << 3);       // 0..31
        int n = ((idx >> 3) & 31) | (((idx >> 10) & 7) << 5); // 0..255
        float4 w = ((const float4*)W_bn)[n * 32 + q];
        int p = n ^ ((q & 7) << 2);
        Wt[(4 * q + 0) * 260 + p] = w.x;
        Wt[(4 * q + 1) * 260 + p] = w.y;
        Wt[(4 * q + 2) * 260 + p] = w.z;
        Wt[(4 * q + 3) * 260 + p] = w.w;
    }
    __syncthreads();

    float acc[8][8];
    #pragma unroll
    for (int i = 0; i < 8; ++i)
        #pragma unroll
        for (int j = 0; j < 8; ++j) acc[i][j] = 0.0f;

    for (int k4 = 0; k4 < 128; k4 += 4) {
        float4 ha[8];
        #pragma unroll
        for (int i = 0; i < 8; ++i)
            ha[i] = *(const float4*)&As[(r0 + i) * 128 + k4];
        #pragma unroll
        for (int e = 0; e < 4; ++e) {
            int k = k4 + e;
            int cb = (4 * tx) ^ (((k >> 2) & 7) << 2);
            float4 w0 = *(const float4*)&Wt[k * 260 + cb];
            float4 w1 = *(const float4*)&Wt[k * 260 + cb + 128];
            #pragma unroll
            for (int i = 0; i < 8; ++i) {
                float a = (e == 0) ? ha[i].x : (e == 1) ? ha[i].y
                        : (e == 2) ? ha[i].z : ha[i].w;
                acc[i][0] += a * w0.x; acc[i][1] += a * w0.y;
                acc[i][2] += a * w0.z; acc[i][3] += a * w0.w;
                acc[i][4] += a * w1.x; acc[i][5] += a * w1.y;
                acc[i][6] += a * w1.z; acc[i][7] += a * w1.w;
            }
        }
    }

    #pragma unroll
    for (int i = 0; i < 8; ++i) {
        size_t row = grow + r0 + i;
        #pragma unroll
        for (int g = 0; g < 2; ++g) {
            float4 v;
            v.x = tanhf(acc[i][g * 4 + 0]);
            v.y = tanhf(acc[i][g * 4 + 1]);
            v.z = tanhf(acc[i][g * 4 + 2]);
            v.w = tanhf(acc[i][g * 4 + 3]);
            *(float4*)&out[BN_OFF + row * 256 + 4 * tx + 128 * g] = v;
        }
    }
}

// ===========================================================================
// Phase 2b: pc = bn @ W_pc^T + b_pc  and  hd = bn @ W_hd^T + b_hd.
// M tiles of 128, K = 256 in 4 tiles of 64. 512 threads, same layout as bn.
// ===========================================================================
#define PC_BN  (128*256)
#define PC_WT  (64*260)
#define PC_WHD (12*257)
#define PC_SMEM_FLOATS (PC_BN + PC_WT + PC_WHD + 256 + 16)

__global__ void __launch_bounds__(512, 1)
pchd_kernel(const float* __restrict__ W_pc, const float* __restrict__ b_pc,
            const float* __restrict__ W_hd, const float* __restrict__ b_hd,
            float* __restrict__ out)
{
    extern __shared__ float sm[];
    float* bnS  = sm;                   // [128][256]
    float* Wt   = bnS + PC_BN;          // [64][260], columns swizzled
    float* whdS = Wt + PC_WT;           // [12][257]
    float* bpcS = whdS + PC_WHD;        // [256]
    float* bhdS = bpcS + 256;           // [12]

    const int tid = threadIdx.x;
    const int tx  = tid & 31;
    const int ty  = tid >> 5;
    const int r0  = ty * 8;
    const size_t grow = (size_t)blockIdx.x * 128;
    const float* bsrc = out + BN_OFF + grow * 256;

    for (int it = 0; it < 16; ++it) {
        int idx = it * 512 + tid;   // 8192 float4
        ((float4*)bnS)[idx] = ((const float4*)bsrc)[idx];
    }
    for (int i = tid; i < 12 * 256; i += 512) {
        int j = i >> 8, k = i & 255;
        whdS[j * 257 + k] = W_hd[i];
    }
    for (int i = tid; i < 256; i += 512) bpcS[i] = b_pc[i];
    if (tid < 12) bhdS[tid] = b_hd[tid];
    __syncthreads();

    float acc[8][8];
    #pragma unroll
    for (int i = 0; i < 8; ++i)
        #pragma unroll
        for (int j = 0; j < 8; ++j) acc[i][j] = 0.0f;

    for (int kt = 0; kt < 256; kt += 64) {
        for (int it = 0; it < 8; ++it) {
            int idx = it * 512 + tid;   // 4096 quads of this K-tile
            int q = (idx & 7) | (((idx >> 8) & 1) << 3);        // 0..15
            int n = ((idx >> 3) & 31) | (((idx >> 9) & 7) << 5); // 0..255
            float4 w = ((const float4*)W_pc)[n * 64 + (kt >> 2) + q];
            int p = n ^ ((q & 7) << 2);
            Wt[(4 * q + 0) * 260 + p] = w.x;
            Wt[(4 * q + 1) * 260 + p] = w.y;
            Wt[(4 * q + 2) * 260 + p] = w.z;
            Wt[(4 * q + 3) * 260 + p] = w.w;
        }
        __syncthreads();
        for (int k4 = 0; k4 < 64; k4 += 4) {
            float4 ha[8];
            #pragma unroll
            for (int i = 0; i < 8; ++i)
                ha[i] = *(const float4*)&bnS[(r0 + i) * 256 + kt + k4];
            #pragma unroll
            for (int e = 0; e < 4; ++e) {
                int k = k4 + e;
                int cb = (4 * tx) ^ (((k >> 2) & 7) << 2);
                float4 w0 = *(const float4*)&Wt[k * 260 + cb];
                float4 w1 = *(const float4*)&Wt[k * 260 + cb + 128];
                #pragma unroll
                for (int i = 0; i < 8; ++i) {
                    float a = (e == 0) ? ha[i].x : (e == 1) ? ha[i].y
                            : (e == 2) ? ha[i].z : ha[i].w;
                    acc[i][0] += a * w0.x; acc[i][1] += a * w0.y;
                    acc[i][2] += a * w0.z; acc[i][3] += a * w0.w;
                    acc[i][4] += a * w1.x; acc[i][5] += a * w1.y;
                    acc[i][6] += a * w1.z; acc[i][7] += a * w1.w;
                }
            }
        }
        __syncthreads();
    }

    // pc epilogue
    #pragma unroll
    for (int i = 0; i < 8; ++i) {
        size_t row = grow + r0 + i;
        #pragma unroll
        for (int g = 0; g < 2; ++g) {
            int nb = 4 * tx + 128 * g;
            float4 v;
            v.x = acc[i][g * 4 + 0] + bpcS[nb + 0];
            v.y = acc[i][g * 4 + 1] + bpcS[nb + 1];
            v.z = acc[i][g * 4 + 2] + bpcS[nb + 2];
            v.w = acc[i][g * 4 + 3] + bpcS[nb + 3];
            *(float4*)&out[PC_OFF + row * 256 + nb] = v;
        }
    }

    // hd: 128 rows x 12 cols = 1536 outputs, 3 per thread
    #pragma unroll
    for (int o = 0; o < 3; ++o) {
        int oidx = o * 512 + tid;
        int r = oidx / 12, j = oidx - r * 12;
        float a = 0.0f;
        #pragma unroll 4
        for (int k = 0; k < 256; ++k)
            a += bnS[r * 256 + k] * whdS[j * 257 + k];
        out[HD_OFF + (grow + r) * 12 + j] = a + bhdS[j];
    }
}

// ===========================================================================
extern "C" void kernel_launch(void* const* d_in, const int* in_sizes, int n_in,
                              void* d_out, int out_size)
{
    const float* x       = (const float*)d_in[0];
    const float* init_pc = (const float*)d_in[1];
    const float* init_hd = (const float*)d_in[2];
    const float* W_state = (const float*)d_in[3];
    const float* b_state = (const float*)d_in[4];
    const float* W_cell  = (const float*)d_in[5];
    const float* b_cell  = (const float*)d_in[6];
    const float* W_ih    = (const float*)d_in[7];
    const float* W_hh    = (const float*)d_in[8];
    const float* b_ih    = (const float*)d_in[9];
    const float* b_hh    = (const float*)d_in[10];
    const float* W_bn    = (const float*)d_in[11];
    const float* W_pc    = (const float*)d_in[12];
    const float* b_pc    = (const float*)d_in[13];
    const float* W_hd    = (const float*)d_in[14];
    const float* b_hd    = (const float*)d_in[15];
    float* out = (float*)d_out;

    size_t smR = (size_t)R_SMEM_FLOATS * sizeof(float);            // ~140 KB
    size_t smB = (size_t)(BN_A + BN_W) * sizeof(float);            // ~199 KB
    size_t smP = (size_t)PC_SMEM_FLOATS * sizeof(float);           // ~211 KB

    cudaFuncSetAttribute(recur_kernel, cudaFuncAttributeMaxDynamicSharedMemorySize, (int)smR);
    cudaFuncSetAttribute(bn_kernel,    cudaFuncAttributeMaxDynamicSharedMemorySize, (int)smB);
    cudaFuncSetAttribute(pchd_kernel,  cudaFuncAttributeMaxDynamicSharedMemorySize, (int)smP);

    recur_kernel<<<BATCH / 32, 256, smR>>>(x, init_pc, init_hd,
                                           W_state, b_state, W_cell, b_cell,
                                           W_ih, W_hh, b_ih, b_hh, out);
    bn_kernel<<<(T_STEPS * BATCH) / 128, 512, smB>>>(W_bn, out);
    pchd_kernel<<<(T_STEPS * BATCH) / 128, 512, smP>>>(W_pc, b_pc, W_hd, b_hd, out);
}

// round 9
// speedup vs baseline: 1.2373x; 1.2373x over previous
#include <cuda_runtime.h>
#include <cuda_bf16.h>
#include <math.h>
#include <stdint.h>

// Problem constants
#define T_STEPS 100
#define BATCH   4096
#define NH      128
#define NG      512
#define NPC     256
#define NHD     12
#define NB      256
#define KIN     268   // NPC + NHD

// Output layout: tuple (hd, pc, bn, hs, cs) flattened in order
#define HD_OFF  ((size_t)0)
#define PC_OFF  ((size_t)T_STEPS * BATCH * NHD)
#define BN_OFF  (PC_OFF + (size_t)T_STEPS * BATCH * NPC)
#define HS_OFF  (BN_OFF + (size_t)T_STEPS * BATCH * NB)
#define CS_OFF  (HS_OFF + (size_t)T_STEPS * BATCH * NH)

__device__ __forceinline__ float sigf(float v) { return 1.0f / (1.0f + expf(-v)); }

__device__ __forceinline__ uint32_t smem_u32(const void* p) {
    uint32_t a;
    asm("{ .reg .u64 t; cvta.to.shared.u64 t, %1; cvt.u32.u64 %0, t; }"
        : "=r"(a) : "l"(p));
    return a;
}

// ---- base-PTX tensor ops (compile for compute_103, no 'a' features) ----
#define LDSM_X4(R, addr) \
    asm volatile("ldmatrix.sync.aligned.m8n8.x4.shared.b16 {%0,%1,%2,%3}, [%4];" \
        : "=r"((R)[0]), "=r"((R)[1]), "=r"((R)[2]), "=r"((R)[3]) : "r"(addr))

#define MMA_BF16(D, A, b0, b1) \
    asm volatile("mma.sync.aligned.m16n8k16.row.col.f32.bf16.bf16.f32 " \
        "{%0,%1,%2,%3}, {%4,%5,%6,%7}, {%8,%9}, {%0,%1,%2,%3};" \
        : "+f"((D)[0]), "+f"((D)[1]), "+f"((D)[2]), "+f"((D)[3]) \
        : "r"((A)[0]), "r"((A)[1]), "r"((A)[2]), "r"((A)[3]), "r"(b0), "r"(b1))

// 8 fp32 -> bf16 hi/lo split, stored as two uint4 at 16B-aligned smem offsets
__device__ __forceinline__ void split8_store(char* sm, uint32_t hi_off, uint32_t lo_off,
                                             const float* v) {
    uint32_t H[4], L[4];
    #pragma unroll
    for (int i = 0; i < 4; ++i) {
        __nv_bfloat16 h0 = __float2bfloat16(v[2 * i]);
        __nv_bfloat16 h1 = __float2bfloat16(v[2 * i + 1]);
        __nv_bfloat16 l0 = __float2bfloat16(v[2 * i]     - __bfloat162float(h0));
        __nv_bfloat16 l1 = __float2bfloat16(v[2 * i + 1] - __bfloat162float(h1));
        H[i] = (uint32_t)__bfloat16_as_ushort(h0) | ((uint32_t)__bfloat16_as_ushort(h1) << 16);
        L[i] = (uint32_t)__bfloat16_as_ushort(l0) | ((uint32_t)__bfloat16_as_ushort(l1) << 16);
    }
    *(uint4*)(sm + hi_off) = make_uint4(H[0], H[1], H[2], H[3]);
    *(uint4*)(sm + lo_off) = make_uint4(L[0], L[1], L[2], L[3]);
}

// 2 fp32 -> hi/lo bf16x2 pair stores (4B each)
__device__ __forceinline__ void split2_store(char* sm, uint32_t hi_off, uint32_t lo_off,
                                             float a, float b) {
    __nv_bfloat16 ha = __float2bfloat16(a), hb = __float2bfloat16(b);
    __nv_bfloat16 la = __float2bfloat16(a - __bfloat162float(ha));
    __nv_bfloat16 lb = __float2bfloat16(b - __bfloat162float(hb));
    *(uint32_t*)(sm + hi_off) = (uint32_t)__bfloat16_as_ushort(ha) | ((uint32_t)__bfloat16_as_ushort(hb) << 16);
    *(uint32_t*)(sm + lo_off) = (uint32_t)__bfloat16_as_ushort(la) | ((uint32_t)__bfloat16_as_ushort(lb) << 16);
}

// ===========================================================================
// Phase 1: recurrence (unchanged from passing R3 kernel)
// ===========================================================================
#define R_HS    (32*128)
#define R_CS    (32*128)
#define R_WT    (16*516)
#define R_GATES (32*512)
#define R_X     (32*4)
#define R_WIH   (512*3)
#define R_BIAS  (512)
#define R_SMEM_FLOATS (R_HS + R_CS + R_WT + R_GATES + R_X + R_WIH + R_BIAS)

__global__ void __launch_bounds__(256, 1)
recur_kernel(const float* __restrict__ x,
             const float* __restrict__ init_pc,
             const float* __restrict__ init_hd,
             const float* __restrict__ W_state, const float* __restrict__ b_state,
             const float* __restrict__ W_cell,  const float* __restrict__ b_cell,
             const float* __restrict__ W_ih,    const float* __restrict__ W_hh,
             const float* __restrict__ b_ih,    const float* __restrict__ b_hh,
             float* __restrict__ out)
{
    extern __shared__ float sm[];
    float* hS    = sm;
    float* cS    = hS + R_HS;
    float* wT    = cS + R_CS;
    float* gS    = wT + R_WT;
    float* xS    = gS + R_GATES;
    float* wihS  = xS + R_X;
    float* biasS = wihS + R_WIH;

    const int tid = threadIdx.x;
    const int tx  = tid & 63;
    const int ty  = tid >> 6;
    const int r0  = ty * 8;
    const int gb0 = blockIdx.x * 32;

    for (int i = tid; i < 512 * 3; i += 256) wihS[i] = W_ih[i];
    for (int i = tid; i < 512; i += 256)     biasS[i] = b_ih[i] + b_hh[i];

    float* initS = gS;
    for (int i = tid; i < 32 * KIN; i += 256) {
        int r = i / KIN, k = i - r * KIN;
        float v = (k < 256) ? init_pc[(size_t)(gb0 + r) * 256 + k]
                            : init_hd[(size_t)(gb0 + r) * 12 + (k - 256)];
        initS[r * KIN + k] = v;
    }
    __syncthreads();

    for (int p = 0; p < 2; ++p) {
        const float* W  = p ? W_cell : W_state;
        const float* bb = p ? b_cell : b_state;
        float acc[16];
        #pragma unroll
        for (int o = 0; o < 16; ++o) acc[o] = 0.0f;

        for (int kt = 0; kt < KIN; kt += 64) {
            int len = KIN - kt; if (len > 64) len = 64;
            for (int i = tid; i < 128 * 64; i += 256) {
                int n = i >> 6, kk = i & 63;
                if (kk < len) wT[kk * 129 + n] = W[n * KIN + kt + kk];
            }
            __syncthreads();
            for (int kk = 0; kk < len; ++kk) {
                #pragma unroll
                for (int o = 0; o < 16; ++o) {
                    int idx = o * 256 + tid;
                    int r = idx >> 7, n = idx & 127;
                    acc[o] += initS[r * KIN + kt + kk] * wT[kk * 129 + n];
                }
            }
            __syncthreads();
        }
        float* dst = p ? cS : hS;
        #pragma unroll
        for (int o = 0; o < 16; ++o) {
            int idx = o * 256 + tid;
            int r = idx >> 7, n = idx & 127;
            dst[r * 128 + n] = acc[o] + bb[n];
        }
        __syncthreads();
    }

    for (int t = 0; t < T_STEPS; ++t) {
        if (tid < 96) {
            int r = tid / 3, cc = tid - r * 3;
            xS[r * 4 + cc] = x[((size_t)t * BATCH + gb0 + r) * 3 + cc];
        }
        __syncthreads();

        float acc[8][8];
        #pragma unroll
        for (int i = 0; i < 8; ++i)
            #pragma unroll
            for (int j = 0; j < 8; ++j) acc[i][j] = 0.0f;

        for (int kt = 0; kt < 128; kt += 16) {
            #pragma unroll
            for (int it = 0; it < 8; ++it) {
                int idx = it * 256 + tid;
                int n = idx >> 2, q = idx & 3;
                float4 w = *(const float4*)&W_hh[n * 128 + kt + 4 * q];
                wT[(4 * q + 0) * 516 + n] = w.x;
                wT[(4 * q + 1) * 516 + n] = w.y;
                wT[(4 * q + 2) * 516 + n] = w.z;
                wT[(4 * q + 3) * 516 + n] = w.w;
            }
            __syncthreads();
            #pragma unroll
            for (int k4 = 0; k4 < 16; k4 += 4) {
                float4 ha[8];
                #pragma unroll
                for (int i = 0; i < 8; ++i)
                    ha[i] = *(const float4*)&hS[(r0 + i) * 128 + kt + k4];
                #pragma unroll
                for (int e = 0; e < 4; ++e) {
                    int kk = k4 + e;
                    float4 w0 = *(const float4*)&wT[kk * 516 + 4 * tx];
                    float4 w1 = *(const float4*)&wT[kk * 516 + 256 + 4 * tx];
                    #pragma unroll
                    for (int i = 0; i < 8; ++i) {
                        float a = (e == 0) ? ha[i].x : (e == 1) ? ha[i].y
                                : (e == 2) ? ha[i].z : ha[i].w;
                        acc[i][0] += a * w0.x; acc[i][1] += a * w0.y;
                        acc[i][2] += a * w0.z; acc[i][3] += a * w0.w;
                        acc[i][4] += a * w1.x; acc[i][5] += a * w1.y;
                        acc[i][6] += a * w1.z; acc[i][7] += a * w1.w;
                    }
                }
            }
            __syncthreads();
        }

        #pragma unroll
        for (int g = 0; g < 2; ++g) {
            int nb = 4 * tx + 256 * g;
            float wc[4][3], bc[4];
            #pragma unroll
            for (int e = 0; e < 4; ++e) {
                wc[e][0] = wihS[(nb + e) * 3 + 0];
                wc[e][1] = wihS[(nb + e) * 3 + 1];
                wc[e][2] = wihS[(nb + e) * 3 + 2];
                bc[e]    = biasS[nb + e];
            }
            #pragma unroll
            for (int i = 0; i < 8; ++i) {
                int r = r0 + i;
                float x0 = xS[r * 4 + 0], x1 = xS[r * 4 + 1], x2 = xS[r * 4 + 2];
                float4 v;
                v.x = acc[i][g * 4 + 0] + x0 * wc[0][0] + x1 * wc[0][1] + x2 * wc[0][2] + bc[0];
                v.y = acc[i][g * 4 + 1] + x0 * wc[1][0] + x1 * wc[1][1] + x2 * wc[1][2] + bc[1];
                v.z = acc[i][g * 4 + 2] + x0 * wc[2][0] + x1 * wc[2][1] + x2 * wc[2][2] + bc[2];
                v.w = acc[i][g * 4 + 3] + x0 * wc[3][0] + x1 * wc[3][1] + x2 * wc[3][2] + bc[3];
                *(float4*)&gS[r * 512 + nb] = v;
            }
        }
        __syncthreads();

        #pragma unroll
        for (int o = 0; o < 16; ++o) {
            int idx = o * 256 + tid;
            int r = idx >> 7, j = idx & 127;
            float ig = sigf(gS[r * 512 + j]);
            float fg = sigf(gS[r * 512 + 128 + j]);
            float gg = tanhf(gS[r * 512 + 256 + j]);
            float og = sigf(gS[r * 512 + 384 + j]);
            float c = fg * cS[r * 128 + j] + ig * gg;
            float h = og * tanhf(c);
            cS[r * 128 + j] = c;
            hS[r * 128 + j] = h;
            size_t row = (size_t)t * BATCH + gb0 + r;
            out[HS_OFF + row * 128 + j] = h;
            out[CS_OFF + row * 128 + j] = c;
        }
        __syncthreads();
    }
}

// ===========================================================================
// Phase 2: fused bn + pc + hd via mma.sync bf16 (split hi/lo, 3-term).
// 1 CTA per 64-row M-tile (6400 CTAs), 256 threads = 8 warps.
// warp tile = 16 rows x 128 cols:  mw = wid&3 (row group), nh = wid>>2 (N half)
// B tiles stored [n][k] row-major -> NON-trans ldmatrix gives the row.col
// B fragment directly (thread t: n = t/4, k = 2*(t%4)+{0,1}).
// ===========================================================================
#define MT 64
#define SA_STR  136   // bf16 elems per row (128 + 8 pad)  -> 272 B (16 mod 128)
#define SW_STR  136
#define SBN_STR 264   // 256 + 8 pad -> 528 B
#define SPC_STR 72    // 64 + 8 pad -> 144 B
#define SHD_STR 264

#define O_A_HI   0u
#define O_A_LO   (O_A_HI + MT*SA_STR*2)          // 17408
#define O_WBN_HI (O_A_LO + MT*SA_STR*2)          // 34816
#define O_WBN_LO (O_WBN_HI + 256*SW_STR*2)       // 104448
#define O_WHD_HI (O_WBN_LO + 256*SW_STR*2)       // 174080
#define O_WHD_LO (O_WHD_HI + 16*SHD_STR*2)       // 182528
#define SMEM_PH2 (O_WHD_LO + 16*SHD_STR*2)       // 190976

// stage-B overlay (A / W_bn regions are dead after stage A)
#define O_BN_HI  0u
#define O_BN_LO  (O_BN_HI + MT*SBN_STR*2)        // 33792
#define O_WPC_HI (O_BN_LO + MT*SBN_STR*2)        // 67584
#define O_WPC_LO (O_WPC_HI + 256*SPC_STR*2)      // 104448, ends 141312 < O_WHD_HI

__global__ void __launch_bounds__(256, 1)
phase2_kernel(const float* __restrict__ W_bn,
              const float* __restrict__ W_pc, const float* __restrict__ b_pc,
              const float* __restrict__ W_hd, const float* __restrict__ b_hd,
              float* __restrict__ out)
{
    extern __shared__ char smc[];
    const uint32_t sb = smem_u32(smc);
    const int tid  = threadIdx.x;
    const int wid  = tid >> 5;
    const int lane = tid & 31;
    const int mw   = wid & 3;
    const int nh   = wid >> 2;
    const int rowA = 16 * mw;
    const size_t grow = (size_t)blockIdx.x * MT;

    // per-lane ldmatrix address components
    const int aRow    = lane & 15;           // A frag: row within 16
    const int aSeg    = (lane >> 4) * 16;    // A frag: k-half byte offset
    const int m4      = lane >> 3;           // x4: matrix index
    // B matrices: mat0=[n0-7,k0-7] mat1=[n0-7,k8-15] mat2=[n8-15,k0-7] mat3=[n8-15,k8-15]
    const int bRowOff = 8 * (m4 >> 1) + (lane & 7); // n offset within 16-n group
    const int bColOff = 8 * (m4 & 1);               // k offset within chunk

    // ---- prologue: load + split HS tile, W_bn, W_hd ----
    {
        uint4 z = make_uint4(0, 0, 0, 0);
        for (int i = tid; i < (16 * SHD_STR * 2 * 2) / 16; i += 256)
            ((uint4*)(smc + O_WHD_HI))[i] = z;   // zero both W_hd hi+lo (contiguous)
    }
    // HS [MT][128]
    for (int b = tid; b < MT * 16; b += 256) {
        int r = b >> 4, c0 = (b & 15) << 3;
        float v[8];
        const float* s = out + HS_OFF + (grow + r) * 128 + c0;
        *(float4*)&v[0] = *(const float4*)s;
        *(float4*)&v[4] = *(const float4*)(s + 4);
        split8_store(smc, O_A_HI + r * SA_STR * 2 + c0 * 2,
                          O_A_LO + r * SA_STR * 2 + c0 * 2, v);
    }
    // W_bn [256][128]
    for (int b = tid; b < 256 * 16; b += 256) {
        int r = b >> 4, c0 = (b & 15) << 3;
        float v[8];
        const float* s = W_bn + (size_t)r * 128 + c0;
        *(float4*)&v[0] = *(const float4*)s;
        *(float4*)&v[4] = *(const float4*)(s + 4);
        split8_store(smc, O_WBN_HI + r * SW_STR * 2 + c0 * 2,
                          O_WBN_LO + r * SW_STR * 2 + c0 * 2, v);
    }
    __syncthreads();   // zero of W_hd complete before row writes
    // W_hd [12][256] into padded [16][SHD_STR]
    for (int b = tid; b < 12 * 32; b += 256) {
        int r = b >> 5, c0 = (b & 31) << 3;
        float v[8];
        const float* s = W_hd + (size_t)r * 256 + c0;
        *(float4*)&v[0] = *(const float4*)s;
        *(float4*)&v[4] = *(const float4*)(s + 4);
        split8_store(smc, O_WHD_HI + r * SHD_STR * 2 + c0 * 2,
                          O_WHD_LO + r * SHD_STR * 2 + c0 * 2, v);
    }
    __syncthreads();

    float acc[16][4];
    #pragma unroll
    for (int j = 0; j < 16; ++j)
        #pragma unroll
        for (int q = 0; q < 4; ++q) acc[j][q] = 0.0f;

    // ---- stage A: D[MT,256] = HS @ W_bn^T  (K=128, 8 chunks) ----
    for (int kc = 0; kc < 8; ++kc) {
        int k0 = kc * 16;
        uint32_t aH[4], aL[4];
        uint32_t adA = sb + O_A_HI + (rowA + aRow) * SA_STR * 2 + k0 * 2 + aSeg;
        LDSM_X4(aH, adA);
        LDSM_X4(aL, adA + (O_A_LO - O_A_HI));
        #pragma unroll
        for (int j = 0; j < 16; j += 2) {
            uint32_t adB = sb + O_WBN_HI + (nh * 128 + 8 * j + bRowOff) * SW_STR * 2
                         + (k0 + bColOff) * 2;
            uint32_t bH[4], bL[4];
            LDSM_X4(bH, adB);
            LDSM_X4(bL, adB + (O_WBN_LO - O_WBN_HI));
            MMA_BF16(acc[j],   aH, bH[0], bH[1]);
            MMA_BF16(acc[j],   aH, bL[0], bL[1]);
            MMA_BF16(acc[j],   aL, bH[0], bH[1]);
            MMA_BF16(acc[j+1], aH, bH[2], bH[3]);
            MMA_BF16(acc[j+1], aH, bL[2], bL[3]);
            MMA_BF16(acc[j+1], aL, bH[2], bH[3]);
        }
    }
    __syncthreads();   // all smem reads of A/W_bn done -> overlay is safe

    // ---- stage A epilogue: tanh -> bn gmem + split-bf16 bn smem ----
    {
        int rl = rowA + (lane >> 2);
        #pragma unroll
        for (int j = 0; j < 16; ++j) {
            int c = nh * 128 + 8 * j + 2 * (lane & 3);
            float v00 = tanhf(acc[j][0]), v01 = tanhf(acc[j][1]);
            float v10 = tanhf(acc[j][2]), v11 = tanhf(acc[j][3]);
            float2* o0 = (float2*)&out[BN_OFF + (grow + rl) * 256 + c];
            float2* o1 = (float2*)&out[BN_OFF + (grow + rl + 8) * 256 + c];
            *o0 = make_float2(v00, v01);
            *o1 = make_float2(v10, v11);
            split2_store(smc, O_BN_HI + rl * SBN_STR * 2 + c * 2,
                              O_BN_LO + rl * SBN_STR * 2 + c * 2, v00, v01);
            split2_store(smc, O_BN_HI + (rl + 8) * SBN_STR * 2 + c * 2,
                              O_BN_LO + (rl + 8) * SBN_STR * 2 + c * 2, v10, v11);
        }
    }
    __syncthreads();   // bn smem tile complete

    // ---- stage B part 1: hd accum (nh==0 warps), W_hd fully resident ----
    float ahd[2][4];
    #pragma unroll
    for (int j = 0; j < 2; ++j)
        #pragma unroll
        for (int q = 0; q < 4; ++q) ahd[j][q] = 0.0f;

    if (nh == 0) {
        for (int kc = 0; kc < 16; ++kc) {
            int k0 = kc * 16;
            uint32_t aH[4], aL[4];
            uint32_t adA = sb + O_BN_HI + (rowA + aRow) * SBN_STR * 2 + k0 * 2 + aSeg;
            LDSM_X4(aH, adA);
            LDSM_X4(aL, adA + (O_BN_LO - O_BN_HI));
            uint32_t adB = sb + O_WHD_HI + bRowOff * SHD_STR * 2 + (k0 + bColOff) * 2;
            uint32_t bH[4], bL[4];
            LDSM_X4(bH, adB);
            LDSM_X4(bL, adB + (O_WHD_LO - O_WHD_HI));
            MMA_BF16(ahd[0], aH, bH[0], bH[1]);
            MMA_BF16(ahd[0], aH, bL[0], bL[1]);
            MMA_BF16(ahd[0], aL, bH[0], bH[1]);
            MMA_BF16(ahd[1], aH, bH[2], bH[3]);
            MMA_BF16(ahd[1], aH, bL[2], bL[3]);
            MMA_BF16(ahd[1], aL, bH[2], bH[3]);
        }
    }

    // ---- stage B part 2: pc = bn @ W_pc^T (K=256, stream 4 chunks of 64) ----
    #pragma unroll
    for (int j = 0; j < 16; ++j)
        #pragma unroll
        for (int q = 0; q < 4; ++q) acc[j][q] = 0.0f;

    for (int kc2 = 0; kc2 < 4; ++kc2) {
        __syncthreads();   // previous chunk's ldmatrix reads complete
        for (int b = tid; b < 256 * 8; b += 256) {
            int r = b >> 3, c0 = (b & 7) << 3;
            float v[8];
            const float* s = W_pc + (size_t)r * 256 + kc2 * 64 + c0;
            *(float4*)&v[0] = *(const float4*)s;
            *(float4*)&v[4] = *(const float4*)(s + 4);
            split8_store(smc, O_WPC_HI + r * SPC_STR * 2 + c0 * 2,
                              O_WPC_LO + r * SPC_STR * 2 + c0 * 2, v);
        }
        __syncthreads();
        for (int kc = 0; kc < 4; ++kc) {
            int kk = kc2 * 64 + kc * 16;
            uint32_t aH[4], aL[4];
            uint32_t adA = sb + O_BN_HI + (rowA + aRow) * SBN_STR * 2 + kk * 2 + aSeg;
            LDSM_X4(aH, adA);
            LDSM_X4(aL, adA + (O_BN_LO - O_BN_HI));
            #pragma unroll
            for (int j = 0; j < 16; j += 2) {
                uint32_t adB = sb + O_WPC_HI + (nh * 128 + 8 * j + bRowOff) * SPC_STR * 2
                             + (kc * 16 + bColOff) * 2;
                uint32_t bH[4], bL[4];
                LDSM_X4(bH, adB);
                LDSM_X4(bL, adB + (O_WPC_LO - O_WPC_HI));
                MMA_BF16(acc[j],   aH, bH[0], bH[1]);
                MMA_BF16(acc[j],   aH, bL[0], bL[1]);
                MMA_BF16(acc[j],   aL, bH[0], bH[1]);
                MMA_BF16(acc[j+1], aH, bH[2], bH[3]);
                MMA_BF16(acc[j+1], aH, bL[2], bL[3]);
                MMA_BF16(acc[j+1], aL, bH[2], bH[3]);
            }
        }
    }

    // ---- pc epilogue ----
    {
        int rl = rowA + (lane >> 2);
        #pragma unroll
        for (int j = 0; j < 16; ++j) {
            int c = nh * 128 + 8 * j + 2 * (lane & 3);
            float b0 = __ldg(&b_pc[c]), b1 = __ldg(&b_pc[c + 1]);
            float2* o0 = (float2*)&out[PC_OFF + (grow + rl) * 256 + c];
            float2* o1 = (float2*)&out[PC_OFF + (grow + rl + 8) * 256 + c];
            *o0 = make_float2(acc[j][0] + b0, acc[j][1] + b1);
            *o1 = make_float2(acc[j][2] + b0, acc[j][3] + b1);
        }
    }

    // ---- hd epilogue (nh==0 warps, cols 0..11 valid) ----
    if (nh == 0) {
        int rl = rowA + (lane >> 2);
        #pragma unroll
        for (int j = 0; j < 2; ++j) {
            int cb = 8 * j + 2 * (lane & 3);
            float* o0 = out + HD_OFF + (grow + rl) * 12;
            float* o1 = out + HD_OFF + (grow + rl + 8) * 12;
            if (cb < 12) {
                float bb = __ldg(&b_hd[cb]);
                o0[cb] = ahd[j][0] + bb;
                o1[cb] = ahd[j][2] + bb;
            }
            if (cb + 1 < 12) {
                float bb = __ldg(&b_hd[cb + 1]);
                o0[cb + 1] = ahd[j][1] + bb;
                o1[cb + 1] = ahd[j][3] + bb;
            }
        }
    }
}

// ===========================================================================
extern "C" void kernel_launch(void* const* d_in, const int* in_sizes, int n_in,
                              void* d_out, int out_size)
{
    const float* x       = (const float*)d_in[0];
    const float* init_pc = (const float*)d_in[1];
    const float* init_hd = (const float*)d_in[2];
    const float* W_state = (const float*)d_in[3];
    const float* b_state = (const float*)d_in[4];
    const float* W_cell  = (const float*)d_in[5];
    const float* b_cell  = (const float*)d_in[6];
    const float* W_ih    = (const float*)d_in[7];
    const float* W_hh    = (const float*)d_in[8];
    const float* b_ih    = (const float*)d_in[9];
    const float* b_hh    = (const float*)d_in[10];
    const float* W_bn    = (const float*)d_in[11];
    const float* W_pc    = (const float*)d_in[12];
    const float* b_pc    = (const float*)d_in[13];
    const float* W_hd    = (const float*)d_in[14];
    const float* b_hd    = (const float*)d_in[15];
    float* out = (float*)d_out;

    size_t smR = (size_t)R_SMEM_FLOATS * sizeof(float);
    cudaFuncSetAttribute(recur_kernel,  cudaFuncAttributeMaxDynamicSharedMemorySize, (int)smR);
    cudaFuncSetAttribute(phase2_kernel, cudaFuncAttributeMaxDynamicSharedMemorySize, (int)SMEM_PH2);

    recur_kernel<<<BATCH / 32, 256, smR>>>(x, init_pc, init_hd,
                                           W_state, b_state, W_cell, b_cell,
                                           W_ih, W_hh, b_ih, b_hh, out);
    phase2_kernel<<<(T_STEPS * BATCH) / MT, 256, SMEM_PH2>>>(
        W_bn, W_pc, b_pc, W_hd, b_hd, out);
}

// round 10
// speedup vs baseline: 1.9429x; 1.5703x over previous
#include <cuda_runtime.h>
#include <cuda_bf16.h>
#include <cuda_fp16.h>
#include <math.h>
#include <stdint.h>

// Problem constants
#define T_STEPS 100
#define BATCH   4096
#define NH      128
#define NG      512
#define NPC     256
#define NHD     12
#define NB      256
#define KIN     268   // NPC + NHD

// Output layout: tuple (hd, pc, bn, hs, cs) flattened in order
#define HD_OFF  ((size_t)0)
#define PC_OFF  ((size_t)T_STEPS * BATCH * NHD)
#define BN_OFF  (PC_OFF + (size_t)T_STEPS * BATCH * NPC)
#define HS_OFF  (BN_OFF + (size_t)T_STEPS * BATCH * NB)
#define CS_OFF  (HS_OFF + (size_t)T_STEPS * BATCH * NH)

__device__ __forceinline__ uint32_t smem_u32(const void* p) {
    uint32_t a;
    asm("{ .reg .u64 t; cvta.to.shared.u64 t, %1; cvt.u32.u64 %0, t; }"
        : "=r"(a) : "l"(p));
    return a;
}

// ---- base-PTX tensor ops (compile for compute_103, no 'a' features) ----
#define LDSM_X4(R, addr) \
    asm volatile("ldmatrix.sync.aligned.m8n8.x4.shared.b16 {%0,%1,%2,%3}, [%4];" \
        : "=r"((R)[0]), "=r"((R)[1]), "=r"((R)[2]), "=r"((R)[3]) : "r"(addr))

#define MMA_BF16(D, A, b0, b1) \
    asm volatile("mma.sync.aligned.m16n8k16.row.col.f32.bf16.bf16.f32 " \
        "{%0,%1,%2,%3}, {%4,%5,%6,%7}, {%8,%9}, {%0,%1,%2,%3};" \
        : "+f"((D)[0]), "+f"((D)[1]), "+f"((D)[2]), "+f"((D)[3]) \
        : "r"((A)[0]), "r"((A)[1]), "r"((A)[2]), "r"((A)[3]), "r"(b0), "r"(b1))

#define MMA_F16(D, A, b0, b1) \
    asm volatile("mma.sync.aligned.m16n8k16.row.col.f32.f16.f16.f32 " \
        "{%0,%1,%2,%3}, {%4,%5,%6,%7}, {%8,%9}, {%0,%1,%2,%3};" \
        : "+f"((D)[0]), "+f"((D)[1]), "+f"((D)[2]), "+f"((D)[3]) \
        : "r"((A)[0]), "r"((A)[1]), "r"((A)[2]), "r"((A)[3]), "r"(b0), "r"(b1))

// fast activations (accurate to ~1e-6, safe at +-inf)
__device__ __forceinline__ float fsig(float v)  { return 1.0f / (1.0f + __expf(-v)); }
__device__ __forceinline__ float ftanh(float v) { return 1.0f - 2.0f / (__expf(2.0f * v) + 1.0f); }

// ---- bf16 hi/lo split helpers (phase 2) ----
__device__ __forceinline__ void split8_store(char* sm, uint32_t hi_off, uint32_t lo_off,
                                             const float* v) {
    uint32_t H[4], L[4];
    #pragma unroll
    for (int i = 0; i < 4; ++i) {
        __nv_bfloat16 h0 = __float2bfloat16(v[2 * i]);
        __nv_bfloat16 h1 = __float2bfloat16(v[2 * i + 1]);
        __nv_bfloat16 l0 = __float2bfloat16(v[2 * i]     - __bfloat162float(h0));
        __nv_bfloat16 l1 = __float2bfloat16(v[2 * i + 1] - __bfloat162float(h1));
        H[i] = (uint32_t)__bfloat16_as_ushort(h0) | ((uint32_t)__bfloat16_as_ushort(h1) << 16);
        L[i] = (uint32_t)__bfloat16_as_ushort(l0) | ((uint32_t)__bfloat16_as_ushort(l1) << 16);
    }
    *(uint4*)(sm + hi_off) = make_uint4(H[0], H[1], H[2], H[3]);
    *(uint4*)(sm + lo_off) = make_uint4(L[0], L[1], L[2], L[3]);
}

__device__ __forceinline__ void split2_store(char* sm, uint32_t hi_off, uint32_t lo_off,
                                             float a, float b) {
    __nv_bfloat16 ha = __float2bfloat16(a), hb = __float2bfloat16(b);
    __nv_bfloat16 la = __float2bfloat16(a - __bfloat162float(ha));
    __nv_bfloat16 lb = __float2bfloat16(b - __bfloat162float(hb));
    *(uint32_t*)(sm + hi_off) = (uint32_t)__bfloat16_as_ushort(ha) | ((uint32_t)__bfloat16_as_ushort(hb) << 16);
    *(uint32_t*)(sm + lo_off) = (uint32_t)__bfloat16_as_ushort(la) | ((uint32_t)__bfloat16_as_ushort(lb) << 16);
}

// ---- fp16 hi/lo split helpers (recurrence) ----
__device__ __forceinline__ void split8h(char* sm, uint32_t hi_off, uint32_t lo_off,
                                        const float* v) {
    uint32_t H[4], L[4];
    #pragma unroll
    for (int i = 0; i < 4; ++i) {
        __half h0 = __float2half_rn(v[2 * i]);
        __half h1 = __float2half_rn(v[2 * i + 1]);
        __half l0 = __float2half_rn(v[2 * i]     - __half2float(h0));
        __half l1 = __float2half_rn(v[2 * i + 1] - __half2float(h1));
        H[i] = (uint32_t)__half_as_ushort(h0) | ((uint32_t)__half_as_ushort(h1) << 16);
        L[i] = (uint32_t)__half_as_ushort(l0) | ((uint32_t)__half_as_ushort(l1) << 16);
    }
    *(uint4*)(sm + hi_off) = make_uint4(H[0], H[1], H[2], H[3]);
    *(uint4*)(sm + lo_off) = make_uint4(L[0], L[1], L[2], L[3]);
}

__device__ __forceinline__ void split2h(char* sm, uint32_t hi_off, uint32_t lo_off,
                                        float a, float b) {
    __half ha = __float2half_rn(a), hb = __float2half_rn(b);
    __half la = __float2half_rn(a - __half2float(ha));
    __half lb = __float2half_rn(b - __half2float(hb));
    *(uint32_t*)(sm + hi_off) = (uint32_t)__half_as_ushort(ha) | ((uint32_t)__half_as_ushort(hb) << 16);
    *(uint32_t*)(sm + lo_off) = (uint32_t)__half_as_ushort(la) | ((uint32_t)__half_as_ushort(lb) << 16);
}

__device__ __forceinline__ uint32_t pack2h(float a, float b) {
    return (uint32_t)__half_as_ushort(__float2half_rn(a))
         | ((uint32_t)__half_as_ushort(__float2half_rn(b)) << 16);
}

// ===========================================================================
// Phase 1: recurrence via mma.sync fp16 (2-term split: Ah*B + Al*B).
// 1 CTA per 32 batch rows, 128 CTAs, 256 threads = 8 warps.
// Warp (w): mrow = w&1 picks 16 rows; jgrp = w>>1 picks j in [32*jgrp, +32).
// Warp computes ALL FOUR gates for its (16 rows x 32 j) -> in-register LSTM
// update, c-state resident in registers for all 100 steps.
// W_hh fp16 resident in smem, XOR-swizzled rows (256B row, ^(n&7)<<4).
// ===========================================================================
#define RS_WH    0                        // [512][128] fp16 swz = 131072
#define RS_AHI   131072                   // [32][128] fp16 swz = 8192
#define RS_ALO   (RS_AHI + 8192)
#define RS_WIH   (RS_ALO + 8192)          // float4[512]: {w0,w1,w2,bias}
#define RS_XS    (RS_WIH + 8192)          // float4[2][32]
#define RS_HC    (RS_XS + 1024)           // fp32 h0/c0 scratch [2][32][128]
#define RS_TOTAL (RS_HC + 32768)          // 189440
// init-phase overlay inside RS_WH region:
#define RS_INITS 0                        // [32][268] fp32 = 34304
#define RS_WT    34816                    // [64][129] fp32 = 33024 (ends 67840)

__global__ void __launch_bounds__(256, 1)
recur_tc(const float* __restrict__ x,
         const float* __restrict__ init_pc,
         const float* __restrict__ init_hd,
         const float* __restrict__ W_state, const float* __restrict__ b_state,
         const float* __restrict__ W_cell,  const float* __restrict__ b_cell,
         const float* __restrict__ W_ih,    const float* __restrict__ W_hh,
         const float* __restrict__ b_ih,    const float* __restrict__ b_hh,
         float* __restrict__ out)
{
    extern __shared__ char smc[];
    const uint32_t sb = smem_u32(smc);
    const int tid  = threadIdx.x;
    const int wid  = tid >> 5;
    const int lane = tid & 31;
    const int mrow = wid & 1;
    const int jgrp = wid >> 1;
    const int gb0  = blockIdx.x * 32;

    // ---------------- init: h0/c0 SIMT GEMM (K=268), runs once ----------------
    {
        float* initS = (float*)(smc + RS_INITS);       // [32][268]
        float* wT    = (float*)(smc + RS_WT);          // [64][129]
        float* hS    = (float*)(smc + RS_HC);          // [32][128]
        float* cS    = hS + 32 * 128;

        for (int i = tid; i < 32 * KIN; i += 256) {
            int r = i / KIN, k = i - r * KIN;
            float v = (k < 256) ? init_pc[(size_t)(gb0 + r) * 256 + k]
                                : init_hd[(size_t)(gb0 + r) * 12 + (k - 256)];
            initS[r * KIN + k] = v;
        }
        __syncthreads();

        for (int p = 0; p < 2; ++p) {
            const float* W  = p ? W_cell : W_state;
            const float* bb = p ? b_cell : b_state;
            float acc[16];
            #pragma unroll
            for (int o = 0; o < 16; ++o) acc[o] = 0.0f;

            for (int kt = 0; kt < KIN; kt += 64) {
                int len = KIN - kt; if (len > 64) len = 64;
                for (int i = tid; i < 128 * 64; i += 256) {
                    int n = i >> 6, kk = i & 63;
                    if (kk < len) wT[kk * 129 + n] = W[n * KIN + kt + kk];
                }
                __syncthreads();
                for (int kk = 0; kk < len; ++kk) {
                    #pragma unroll
                    for (int o = 0; o < 16; ++o) {
                        int idx = o * 256 + tid;
                        int r = idx >> 7, n = idx & 127;
                        acc[o] += initS[r * KIN + kt + kk] * wT[kk * 129 + n];
                    }
                }
                __syncthreads();
            }
            float* dst = p ? cS : hS;
            #pragma unroll
            for (int o = 0; o < 16; ++o) {
                int idx = o * 256 + tid;
                int r = idx >> 7, n = idx & 127;
                dst[r * 128 + n] = acc[o] + bb[n];
            }
            __syncthreads();
        }
    }
    // initS/wT dead; RS_WH region now free for W_hh fp16.

    // ---------------- load W_hh fp16 (swizzled), wih+bias, x[0], h0 split ----
    for (int i = tid; i < 512 * 32; i += 256) {
        int row = i >> 5, q = i & 31;
        float4 w = *(const float4*)&W_hh[row * 128 + 4 * q];
        uint2 h4 = make_uint2(pack2h(w.x, w.y), pack2h(w.z, w.w));
        uint32_t off = ((uint32_t)(8 * q)) ^ (uint32_t)((row & 7) << 4);
        *(uint2*)(smc + RS_WH + row * 256 + off) = h4;
    }
    for (int n = tid; n < 512; n += 256) {
        ((float4*)(smc + RS_WIH))[n] =
            make_float4(W_ih[n * 3 + 0], W_ih[n * 3 + 1], W_ih[n * 3 + 2],
                        b_ih[n] + b_hh[n]);
    }
    if (tid < 96) {
        int r = tid / 3, c = tid - 3 * r;
        ((float*)(smc + RS_XS))[r * 4 + c] = x[((size_t)0 * BATCH + gb0 + r) * 3 + c];
    }
    {
        const float* hS = (const float*)(smc + RS_HC);
        for (int i = tid; i < 512; i += 256) {           // 32*128/8 groups
            int row = i >> 4, c0 = (i & 15) * 8;
            uint32_t off = row * 256 + (((uint32_t)(c0 * 2)) ^ (uint32_t)((row & 7) << 4));
            split8h(smc, RS_AHI + off, RS_ALO + off, &hS[row * 128 + c0]);
        }
    }

    // ---------------- per-lane constants ----------------
    const int r1  = 16 * mrow + (lane >> 2);       // epilogue rows r1, r1+8
    const int j0b = jgrp * 32 + 2 * (lane & 3);    // epilogue col base (per b: +8b)

    // A-fragment addressing
    const int aRowL = 16 * mrow + (lane & 15);
    const uint32_t aBaseH = sb + RS_AHI + aRowL * 256;
    const uint32_t aBaseL = sb + RS_ALO + aRowL * 256;
    const uint32_t aXor   = (uint32_t)((aRowL & 7) << 4);
    const uint32_t aSeg   = (uint32_t)((lane >> 4) * 16);
    // B-fragment addressing
    const int m4 = lane >> 3;
    const int bRowOff = 8 * (m4 >> 1) + (lane & 7);
    const uint32_t bSeg = (uint32_t)((m4 & 1) * 16);
    uint32_t bBase[4][2], bXor[4][2];
    #pragma unroll
    for (int g = 0; g < 4; ++g)
        #pragma unroll
        for (int p = 0; p < 2; ++p) {
            int n = g * 128 + jgrp * 32 + 16 * p + bRowOff;
            bBase[g][p] = sb + RS_WH + n * 256;
            bXor[g][p]  = (uint32_t)((n & 7) << 4);
        }

    // c-state registers
    float cc[4][4];
    {
        const float* cS = (const float*)(smc + RS_HC) + 32 * 128;
        #pragma unroll
        for (int b = 0; b < 4; ++b) {
            int j0 = j0b + 8 * b;
            cc[b][0] = cS[r1 * 128 + j0];
            cc[b][1] = cS[r1 * 128 + j0 + 1];
            cc[b][2] = cS[(r1 + 8) * 128 + j0];
            cc[b][3] = cS[(r1 + 8) * 128 + j0 + 1];
        }
    }
    __syncthreads();   // W/A/x loads visible; enter time loop

    // ---------------- time loop ----------------
    for (int t = 0; t < T_STEPS; ++t) {
        float acc[16][4];
        #pragma unroll
        for (int j = 0; j < 16; ++j)
            #pragma unroll
            for (int q = 0; q < 4; ++q) acc[j][q] = 0.0f;

        #pragma unroll
        for (int kc = 0; kc < 8; ++kc) {
            uint32_t ao = (uint32_t)(kc * 32) + aSeg;
            uint32_t aH[4], aL[4];
            LDSM_X4(aH, aBaseH + (ao ^ aXor));
            LDSM_X4(aL, aBaseL + (ao ^ aXor));
            uint32_t bo = (uint32_t)(kc * 32) + bSeg;
            #pragma unroll
            for (int g = 0; g < 4; ++g)
                #pragma unroll
                for (int p = 0; p < 2; ++p) {
                    uint32_t bf[4];
                    LDSM_X4(bf, bBase[g][p] + (bo ^ bXor[g][p]));
                    int tau = g * 4 + 2 * p;
                    MMA_F16(acc[tau],     aH, bf[0], bf[1]);
                    MMA_F16(acc[tau],     aL, bf[0], bf[1]);
                    MMA_F16(acc[tau + 1], aH, bf[2], bf[3]);
                    MMA_F16(acc[tau + 1], aL, bf[2], bf[3]);
                }
        }
        __syncthreads();    // all A reads done -> safe to overwrite A below

        // ---- in-register LSTM epilogue ----
        const float4* xs4 = (const float4*)(smc + RS_XS) + (t & 1) * 32;
        float4 xv1 = xs4[r1];
        float4 xv2 = xs4[r1 + 8];
        size_t row1 = (size_t)t * BATCH + gb0 + r1;
        size_t row2 = row1 + 8;

        #pragma unroll
        for (int b = 0; b < 4; ++b) {
            int j0 = j0b + 8 * b;
            float4 wq[4][2];
            #pragma unroll
            for (int g = 0; g < 4; ++g) {
                wq[g][0] = ((const float4*)(smc + RS_WIH))[g * 128 + j0];
                wq[g][1] = ((const float4*)(smc + RS_WIH))[g * 128 + j0 + 1];
            }
            float hv[4];
            #pragma unroll
            for (int q = 0; q < 4; ++q) {
                int cp = q & 1;
                float4 xv = (q >= 2) ? xv2 : xv1;
                float pre[4];
                #pragma unroll
                for (int g = 0; g < 4; ++g)
                    pre[g] = acc[g * 4 + b][q]
                           + xv.x * wq[g][cp].x + xv.y * wq[g][cp].y
                           + xv.z * wq[g][cp].z + wq[g][cp].w;
                float ig = fsig(pre[0]), fg = fsig(pre[1]);
                float gg = ftanh(pre[2]), og = fsig(pre[3]);
                float cn = fg * cc[b][q] + ig * gg;
                cc[b][q] = cn;
                hv[q] = og * ftanh(cn);
            }
            *(float2*)&out[HS_OFF + row1 * 128 + j0] = make_float2(hv[0], hv[1]);
            *(float2*)&out[HS_OFF + row2 * 128 + j0] = make_float2(hv[2], hv[3]);
            *(float2*)&out[CS_OFF + row1 * 128 + j0] = make_float2(cc[b][0], cc[b][1]);
            *(float2*)&out[CS_OFF + row2 * 128 + j0] = make_float2(cc[b][2], cc[b][3]);
            // next step's A (h split fp16) at swizzled offsets
            uint32_t o1 = r1 * 256 + (((uint32_t)(j0 * 2)) ^ (uint32_t)((r1 & 7) << 4));
            split2h(smc, RS_AHI + o1, RS_ALO + o1, hv[0], hv[1]);
            split2h(smc, RS_AHI + o1 + 2048, RS_ALO + o1 + 2048, hv[2], hv[3]);
        }
        if (t + 1 < T_STEPS && tid < 96) {
            int r = tid / 3, c = tid - 3 * r;
            ((float*)(smc + RS_XS))[((t + 1) & 1) * 128 + r * 4 + c] =
                x[((size_t)(t + 1) * BATCH + gb0 + r) * 3 + c];
        }
        __syncthreads();    // h-split + xS visible for next iteration
    }
}

// ===========================================================================
// Phase 2: fused bn + pc + hd via mma.sync bf16 (split hi/lo, 3-term).
// Unchanged from R9 (passing, rel_err 6.7e-6 contribution).
// ===========================================================================
#define MT 64
#define SA_STR  136
#define SW_STR  136
#define SBN_STR 264
#define SPC_STR 72
#define SHD_STR 264

#define O_A_HI   0u
#define O_A_LO   (O_A_HI + MT*SA_STR*2)
#define O_WBN_HI (O_A_LO + MT*SA_STR*2)
#define O_WBN_LO (O_WBN_HI + 256*SW_STR*2)
#define O_WHD_HI (O_WBN_LO + 256*SW_STR*2)
#define O_WHD_LO (O_WHD_HI + 16*SHD_STR*2)
#define SMEM_PH2 (O_WHD_LO + 16*SHD_STR*2)

#define O_BN_HI  0u
#define O_BN_LO  (O_BN_HI + MT*SBN_STR*2)
#define O_WPC_HI (O_BN_LO + MT*SBN_STR*2)
#define O_WPC_LO (O_WPC_HI + 256*SPC_STR*2)

__global__ void __launch_bounds__(256, 1)
phase2_kernel(const float* __restrict__ W_bn,
              const float* __restrict__ W_pc, const float* __restrict__ b_pc,
              const float* __restrict__ W_hd, const float* __restrict__ b_hd,
              float* __restrict__ out)
{
    extern __shared__ char smc[];
    const uint32_t sb = smem_u32(smc);
    const int tid  = threadIdx.x;
    const int wid  = tid >> 5;
    const int lane = tid & 31;
    const int mw   = wid & 3;
    const int nh   = wid >> 2;
    const int rowA = 16 * mw;
    const size_t grow = (size_t)blockIdx.x * MT;

    const int aRow    = lane & 15;
    const int aSeg    = (lane >> 4) * 16;
    const int m4      = lane >> 3;
    const int bRowOff = 8 * (m4 >> 1) + (lane & 7);
    const int bColOff = 8 * (m4 & 1);

    {
        uint4 z = make_uint4(0, 0, 0, 0);
        for (int i = tid; i < (16 * SHD_STR * 2 * 2) / 16; i += 256)
            ((uint4*)(smc + O_WHD_HI))[i] = z;
    }
    for (int b = tid; b < MT * 16; b += 256) {
        int r = b >> 4, c0 = (b & 15) << 3;
        float v[8];
        const float* s = out + HS_OFF + (grow + r) * 128 + c0;
        *(float4*)&v[0] = *(const float4*)s;
        *(float4*)&v[4] = *(const float4*)(s + 4);
        split8_store(smc, O_A_HI + r * SA_STR * 2 + c0 * 2,
                          O_A_LO + r * SA_STR * 2 + c0 * 2, v);
    }
    for (int b = tid; b < 256 * 16; b += 256) {
        int r = b >> 4, c0 = (b & 15) << 3;
        float v[8];
        const float* s = W_bn + (size_t)r * 128 + c0;
        *(float4*)&v[0] = *(const float4*)s;
        *(float4*)&v[4] = *(const float4*)(s + 4);
        split8_store(smc, O_WBN_HI + r * SW_STR * 2 + c0 * 2,
                          O_WBN_LO + r * SW_STR * 2 + c0 * 2, v);
    }
    __syncthreads();
    for (int b = tid; b < 12 * 32; b += 256) {
        int r = b >> 5, c0 = (b & 31) << 3;
        float v[8];
        const float* s = W_hd + (size_t)r * 256 + c0;
        *(float4*)&v[0] = *(const float4*)s;
        *(float4*)&v[4] = *(const float4*)(s + 4);
        split8_store(smc, O_WHD_HI + r * SHD_STR * 2 + c0 * 2,
                          O_WHD_LO + r * SHD_STR * 2 + c0 * 2, v);
    }
    __syncthreads();

    float acc[16][4];
    #pragma unroll
    for (int j = 0; j < 16; ++j)
        #pragma unroll
        for (int q = 0; q < 4; ++q) acc[j][q] = 0.0f;

    for (int kc = 0; kc < 8; ++kc) {
        int k0 = kc * 16;
        uint32_t aH[4], aL[4];
        uint32_t adA = sb + O_A_HI + (rowA + aRow) * SA_STR * 2 + k0 * 2 + aSeg;
        LDSM_X4(aH, adA);
        LDSM_X4(aL, adA + (O_A_LO - O_A_HI));
        #pragma unroll
        for (int j = 0; j < 16; j += 2) {
            uint32_t adB = sb + O_WBN_HI + (nh * 128 + 8 * j + bRowOff) * SW_STR * 2
                         + (k0 + bColOff) * 2;
            uint32_t bH[4], bL[4];
            LDSM_X4(bH, adB);
            LDSM_X4(bL, adB + (O_WBN_LO - O_WBN_HI));
            MMA_BF16(acc[j],   aH, bH[0], bH[1]);
            MMA_BF16(acc[j],   aH, bL[0], bL[1]);
            MMA_BF16(acc[j],   aL, bH[0], bH[1]);
            MMA_BF16(acc[j+1], aH, bH[2], bH[3]);
            MMA_BF16(acc[j+1], aH, bL[2], bL[3]);
            MMA_BF16(acc[j+1], aL, bH[2], bH[3]);
        }
    }
    __syncthreads();

    {
        int rl = rowA + (lane >> 2);
        #pragma unroll
        for (int j = 0; j < 16; ++j) {
            int c = nh * 128 + 8 * j + 2 * (lane & 3);
            float v00 = tanhf(acc[j][0]), v01 = tanhf(acc[j][1]);
            float v10 = tanhf(acc[j][2]), v11 = tanhf(acc[j][3]);
            float2* o0 = (float2*)&out[BN_OFF + (grow + rl) * 256 + c];
            float2* o1 = (float2*)&out[BN_OFF + (grow + rl + 8) * 256 + c];
            *o0 = make_float2(v00, v01);
            *o1 = make_float2(v10, v11);
            split2_store(smc, O_BN_HI + rl * SBN_STR * 2 + c * 2,
                              O_BN_LO + rl * SBN_STR * 2 + c * 2, v00, v01);
            split2_store(smc, O_BN_HI + (rl + 8) * SBN_STR * 2 + c * 2,
                              O_BN_LO + (rl + 8) * SBN_STR * 2 + c * 2, v10, v11);
        }
    }
    __syncthreads();

    float ahd[2][4];
    #pragma unroll
    for (int j = 0; j < 2; ++j)
        #pragma unroll
        for (int q = 0; q < 4; ++q) ahd[j][q] = 0.0f;

    if (nh == 0) {
        for (int kc = 0; kc < 16; ++kc) {
            int k0 = kc * 16;
            uint32_t aH[4], aL[4];
            uint32_t adA = sb + O_BN_HI + (rowA + aRow) * SBN_STR * 2 + k0 * 2 + aSeg;
            LDSM_X4(aH, adA);
            LDSM_X4(aL, adA + (O_BN_LO - O_BN_HI));
            uint32_t adB = sb + O_WHD_HI + bRowOff * SHD_STR * 2 + (k0 + bColOff) * 2;
            uint32_t bH[4], bL[4];
            LDSM_X4(bH, adB);
            LDSM_X4(bL, adB + (O_WHD_LO - O_WHD_HI));
            MMA_BF16(ahd[0], aH, bH[0], bH[1]);
            MMA_BF16(ahd[0], aH, bL[0], bL[1]);
            MMA_BF16(ahd[0], aL, bH[0], bH[1]);
            MMA_BF16(ahd[1], aH, bH[2], bH[3]);
            MMA_BF16(ahd[1], aH, bL[2], bL[3]);
            MMA_BF16(ahd[1], aL, bH[2], bH[3]);
        }
    }

    #pragma unroll
    for (int j = 0; j < 16; ++j)
        #pragma unroll
        for (int q = 0; q < 4; ++q) acc[j][q] = 0.0f;

    for (int kc2 = 0; kc2 < 4; ++kc2) {
        __syncthreads();
        for (int b = tid; b < 256 * 8; b += 256) {
            int r = b >> 3, c0 = (b & 7) << 3;
            float v[8];
            const float* s = W_pc + (size_t)r * 256 + kc2 * 64 + c0;
            *(float4*)&v[0] = *(const float4*)s;
            *(float4*)&v[4] = *(const float4*)(s + 4);
            split8_store(smc, O_WPC_HI + r * SPC_STR * 2 + c0 * 2,
                              O_WPC_LO + r * SPC_STR * 2 + c0 * 2, v);
        }
        __syncthreads();
        for (int kc = 0; kc < 4; ++kc) {
            int kk = kc2 * 64 + kc * 16;
            uint32_t aH[4], aL[4];
            uint32_t adA = sb + O_BN_HI + (rowA + aRow) * SBN_STR * 2 + kk * 2 + aSeg;
            LDSM_X4(aH, adA);
            LDSM_X4(aL, adA + (O_BN_LO - O_BN_HI));
            #pragma unroll
            for (int j = 0; j < 16; j += 2) {
                uint32_t adB = sb + O_WPC_HI + (nh * 128 + 8 * j + bRowOff) * SPC_STR * 2
                             + (kc * 16 + bColOff) * 2;
                uint32_t bH[4], bL[4];
                LDSM_X4(bH, adB);
                LDSM_X4(bL, adB + (O_WPC_LO - O_WPC_HI));
                MMA_BF16(acc[j],   aH, bH[0], bH[1]);
                MMA_BF16(acc[j],   aH, bL[0], bL[1]);
                MMA_BF16(acc[j],   aL, bH[0], bH[1]);
                MMA_BF16(acc[j+1], aH, bH[2], bH[3]);
                MMA_BF16(acc[j+1], aH, bL[2], bL[3]);
                MMA_BF16(acc[j+1], aL, bH[2], bH[3]);
            }
        }
    }

    {
        int rl = rowA + (lane >> 2);
        #pragma unroll
        for (int j = 0; j < 16; ++j) {
            int c = nh * 128 + 8 * j + 2 * (lane & 3);
            float b0 = __ldg(&b_pc[c]), b1 = __ldg(&b_pc[c + 1]);
            float2* o0 = (float2*)&out[PC_OFF + (grow + rl) * 256 + c];
            float2* o1 = (float2*)&out[PC_OFF + (grow + rl + 8) * 256 + c];
            *o0 = make_float2(acc[j][0] + b0, acc[j][1] + b1);
            *o1 = make_float2(acc[j][2] + b0, acc[j][3] + b1);
        }
    }

    if (nh == 0) {
        int rl = rowA + (lane >> 2);
        #pragma unroll
        for (int j = 0; j < 2; ++j) {
            int cb = 8 * j + 2 * (lane & 3);
            float* o0 = out + HD_OFF + (grow + rl) * 12;
            float* o1 = out + HD_OFF + (grow + rl + 8) * 12;
            if (cb < 12) {
                float bb = __ldg(&b_hd[cb]);
                o0[cb] = ahd[j][0] + bb;
                o1[cb] = ahd[j][2] + bb;
            }
            if (cb + 1 < 12) {
                float bb = __ldg(&b_hd[cb + 1]);
                o0[cb + 1] = ahd[j][1] + bb;
                o1[cb + 1] = ahd[j][3] + bb;
            }
        }
    }
}

// ===========================================================================
extern "C" void kernel_launch(void* const* d_in, const int* in_sizes, int n_in,
                              void* d_out, int out_size)
{
    const float* x       = (const float*)d_in[0];
    const float* init_pc = (const float*)d_in[1];
    const float* init_hd = (const float*)d_in[2];
    const float* W_state = (const float*)d_in[3];
    const float* b_state = (const float*)d_in[4];
    const float* W_cell  = (const float*)d_in[5];
    const float* b_cell  = (const float*)d_in[6];
    const float* W_ih    = (const float*)d_in[7];
    const float* W_hh    = (const float*)d_in[8];
    const float* b_ih    = (const float*)d_in[9];
    const float* b_hh    = (const float*)d_in[10];
    const float* W_bn    = (const float*)d_in[11];
    const float* W_pc    = (const float*)d_in[12];
    const float* b_pc    = (const float*)d_in[13];
    const float* W_hd    = (const float*)d_in[14];
    const float* b_hd    = (const float*)d_in[15];
    float* out = (float*)d_out;

    cudaFuncSetAttribute(recur_tc,      cudaFuncAttributeMaxDynamicSharedMemorySize, (int)RS_TOTAL);
    cudaFuncSetAttribute(phase2_kernel, cudaFuncAttributeMaxDynamicSharedMemorySize, (int)SMEM_PH2);

    recur_tc<<<BATCH / 32, 256, RS_TOTAL>>>(x, init_pc, init_hd,
                                            W_state, b_state, W_cell, b_cell,
                                            W_ih, W_hh, b_ih, b_hh, out);
    phase2_kernel<<<(T_STEPS * BATCH) / MT, 256, SMEM_PH2>>>(
        W_bn, W_pc, b_pc, W_hd, b_hd, out);
}

// round 11
// speedup vs baseline: 2.6424x; 1.3600x over previous
#include <cuda_runtime.h>
#include <cuda_bf16.h>
#include <cuda_fp16.h>
#include <math.h>
#include <stdint.h>

// Problem constants
#define T_STEPS 100
#define BATCH   4096
#define NH      128
#define NG      512
#define NPC     256
#define NHD     12
#define NB      256
#define KIN     268   // NPC + NHD

// Output layout: tuple (hd, pc, bn, hs, cs) flattened in order
#define HD_OFF  ((size_t)0)
#define PC_OFF  ((size_t)T_STEPS * BATCH * NHD)
#define BN_OFF  (PC_OFF + (size_t)T_STEPS * BATCH * NPC)
#define HS_OFF  (BN_OFF + (size_t)T_STEPS * BATCH * NB)
#define CS_OFF  (HS_OFF + (size_t)T_STEPS * BATCH * NH)

__device__ __forceinline__ uint32_t smem_u32(const void* p) {
    uint32_t a;
    asm("{ .reg .u64 t; cvta.to.shared.u64 t, %1; cvt.u32.u64 %0, t; }"
        : "=r"(a) : "l"(p));
    return a;
}

// ---- base-PTX tensor ops (compile for compute_103, no 'a' features) ----
#define LDSM_X4(R, addr) \
    asm volatile("ldmatrix.sync.aligned.m8n8.x4.shared.b16 {%0,%1,%2,%3}, [%4];" \
        : "=r"((R)[0]), "=r"((R)[1]), "=r"((R)[2]), "=r"((R)[3]) : "r"(addr))

#define MMA_F16(D, A, b0, b1) \
    asm volatile("mma.sync.aligned.m16n8k16.row.col.f32.f16.f16.f32 " \
        "{%0,%1,%2,%3}, {%4,%5,%6,%7}, {%8,%9}, {%0,%1,%2,%3};" \
        : "+f"((D)[0]), "+f"((D)[1]), "+f"((D)[2]), "+f"((D)[3]) \
        : "r"((A)[0]), "r"((A)[1]), "r"((A)[2]), "r"((A)[3]), "r"(b0), "r"(b1))

// fast activations (accurate to ~1e-6, safe at +-inf)
__device__ __forceinline__ float fsig(float v)  { return 1.0f / (1.0f + __expf(-v)); }
__device__ __forceinline__ float ftanh(float v) { return 1.0f - 2.0f / (__expf(2.0f * v) + 1.0f); }

// ---- fp16 pack / hi-lo split helpers ----
__device__ __forceinline__ uint32_t pack2h(float a, float b) {
    return (uint32_t)__half_as_ushort(__float2half_rn(a))
         | ((uint32_t)__half_as_ushort(__float2half_rn(b)) << 16);
}

__device__ __forceinline__ void pack8h_store(char* sm, uint32_t off, const float* v) {
    *(uint4*)(sm + off) = make_uint4(pack2h(v[0], v[1]), pack2h(v[2], v[3]),
                                     pack2h(v[4], v[5]), pack2h(v[6], v[7]));
}

__device__ __forceinline__ void split8h(char* sm, uint32_t hi_off, uint32_t lo_off,
                                        const float* v) {
    uint32_t H[4], L[4];
    #pragma unroll
    for (int i = 0; i < 4; ++i) {
        __half h0 = __float2half_rn(v[2 * i]);
        __half h1 = __float2half_rn(v[2 * i + 1]);
        __half l0 = __float2half_rn(v[2 * i]     - __half2float(h0));
        __half l1 = __float2half_rn(v[2 * i + 1] - __half2float(h1));
        H[i] = (uint32_t)__half_as_ushort(h0) | ((uint32_t)__half_as_ushort(h1) << 16);
        L[i] = (uint32_t)__half_as_ushort(l0) | ((uint32_t)__half_as_ushort(l1) << 16);
    }
    *(uint4*)(sm + hi_off) = make_uint4(H[0], H[1], H[2], H[3]);
    *(uint4*)(sm + lo_off) = make_uint4(L[0], L[1], L[2], L[3]);
}

__device__ __forceinline__ void split2h(char* sm, uint32_t hi_off, uint32_t lo_off,
                                        float a, float b) {
    __half ha = __float2half_rn(a), hb = __float2half_rn(b);
    __half la = __float2half_rn(a - __half2float(ha));
    __half lb = __float2half_rn(b - __half2float(hb));
    *(uint32_t*)(sm + hi_off) = (uint32_t)__half_as_ushort(ha) | ((uint32_t)__half_as_ushort(hb) << 16);
    *(uint32_t*)(sm + lo_off) = (uint32_t)__half_as_ushort(la) | ((uint32_t)__half_as_ushort(lb) << 16);
}

// ===========================================================================
// Phase 1: recurrence via mma.sync fp16 (2-term split: Ah*B + Al*B).
// Unchanged from R10 (passing, contributes ~8e-5 rel_err).
// ===========================================================================
#define RS_WH    0                        // [512][128] fp16 swz = 131072
#define RS_AHI   131072                   // [32][128] fp16 swz = 8192
#define RS_ALO   (RS_AHI + 8192)
#define RS_WIH   (RS_ALO + 8192)          // float4[512]: {w0,w1,w2,bias}
#define RS_XS    (RS_WIH + 8192)          // float4[2][32]
#define RS_HC    (RS_XS + 1024)           // fp32 h0/c0 scratch [2][32][128]
#define RS_TOTAL (RS_HC + 32768)          // 189440
// init-phase overlay inside RS_WH region:
#define RS_INITS 0                        // [32][268] fp32
#define RS_WT    34816                    // [64][129] fp32

__global__ void __launch_bounds__(256, 1)
recur_tc(const float* __restrict__ x,
         const float* __restrict__ init_pc,
         const float* __restrict__ init_hd,
         const float* __restrict__ W_state, const float* __restrict__ b_state,
         const float* __restrict__ W_cell,  const float* __restrict__ b_cell,
         const float* __restrict__ W_ih,    const float* __restrict__ W_hh,
         const float* __restrict__ b_ih,    const float* __restrict__ b_hh,
         float* __restrict__ out)
{
    extern __shared__ char smc[];
    const uint32_t sb = smem_u32(smc);
    const int tid  = threadIdx.x;
    const int wid  = tid >> 5;
    const int lane = tid & 31;
    const int mrow = wid & 1;
    const int jgrp = wid >> 1;
    const int gb0  = blockIdx.x * 32;

    // ---------------- init: h0/c0 SIMT GEMM (K=268), runs once ----------------
    {
        float* initS = (float*)(smc + RS_INITS);
        float* wT    = (float*)(smc + RS_WT);
        float* hS    = (float*)(smc + RS_HC);
        float* cS    = hS + 32 * 128;

        for (int i = tid; i < 32 * KIN; i += 256) {
            int r = i / KIN, k = i - r * KIN;
            float v = (k < 256) ? init_pc[(size_t)(gb0 + r) * 256 + k]
                                : init_hd[(size_t)(gb0 + r) * 12 + (k - 256)];
            initS[r * KIN + k] = v;
        }
        __syncthreads();

        for (int p = 0; p < 2; ++p) {
            const float* W  = p ? W_cell : W_state;
            const float* bb = p ? b_cell : b_state;
            float acc[16];
            #pragma unroll
            for (int o = 0; o < 16; ++o) acc[o] = 0.0f;

            for (int kt = 0; kt < KIN; kt += 64) {
                int len = KIN - kt; if (len > 64) len = 64;
                for (int i = tid; i < 128 * 64; i += 256) {
                    int n = i >> 6, kk = i & 63;
                    if (kk < len) wT[kk * 129 + n] = W[n * KIN + kt + kk];
                }
                __syncthreads();
                for (int kk = 0; kk < len; ++kk) {
                    #pragma unroll
                    for (int o = 0; o < 16; ++o) {
                        int idx = o * 256 + tid;
                        int r = idx >> 7, n = idx & 127;
                        acc[o] += initS[r * KIN + kt + kk] * wT[kk * 129 + n];
                    }
                }
                __syncthreads();
            }
            float* dst = p ? cS : hS;
            #pragma unroll
            for (int o = 0; o < 16; ++o) {
                int idx = o * 256 + tid;
                int r = idx >> 7, n = idx & 127;
                dst[r * 128 + n] = acc[o] + bb[n];
            }
            __syncthreads();
        }
    }

    // ---------------- load W_hh fp16 (swizzled), wih+bias, x[0], h0 split ----
    for (int i = tid; i < 512 * 32; i += 256) {
        int row = i >> 5, q = i & 31;
        float4 w = *(const float4*)&W_hh[row * 128 + 4 * q];
        uint2 h4 = make_uint2(pack2h(w.x, w.y), pack2h(w.z, w.w));
        uint32_t off = ((uint32_t)(8 * q)) ^ (uint32_t)((row & 7) << 4);
        *(uint2*)(smc + RS_WH + row * 256 + off) = h4;
    }
    for (int n = tid; n < 512; n += 256) {
        ((float4*)(smc + RS_WIH))[n] =
            make_float4(W_ih[n * 3 + 0], W_ih[n * 3 + 1], W_ih[n * 3 + 2],
                        b_ih[n] + b_hh[n]);
    }
    if (tid < 96) {
        int r = tid / 3, c = tid - 3 * r;
        ((float*)(smc + RS_XS))[r * 4 + c] = x[((size_t)0 * BATCH + gb0 + r) * 3 + c];
    }
    {
        const float* hS = (const float*)(smc + RS_HC);
        for (int i = tid; i < 512; i += 256) {
            int row = i >> 4, c0 = (i & 15) * 8;
            uint32_t off = row * 256 + (((uint32_t)(c0 * 2)) ^ (uint32_t)((row & 7) << 4));
            split8h(smc, RS_AHI + off, RS_ALO + off, &hS[row * 128 + c0]);
        }
    }

    const int r1  = 16 * mrow + (lane >> 2);
    const int j0b = jgrp * 32 + 2 * (lane & 3);

    const int aRowL = 16 * mrow + (lane & 15);
    const uint32_t aBaseH = sb + RS_AHI + aRowL * 256;
    const uint32_t aBaseL = sb + RS_ALO + aRowL * 256;
    const uint32_t aXor   = (uint32_t)((aRowL & 7) << 4);
    const uint32_t aSeg   = (uint32_t)((lane >> 4) * 16);
    const int m4 = lane >> 3;
    const int bRowOff = 8 * (m4 >> 1) + (lane & 7);
    const uint32_t bSeg = (uint32_t)((m4 & 1) * 16);
    uint32_t bBase[4][2], bXor[4][2];
    #pragma unroll
    for (int g = 0; g < 4; ++g)
        #pragma unroll
        for (int p = 0; p < 2; ++p) {
            int n = g * 128 + jgrp * 32 + 16 * p + bRowOff;
            bBase[g][p] = sb + RS_WH + n * 256;
            bXor[g][p]  = (uint32_t)((n & 7) << 4);
        }

    float cc[4][4];
    {
        const float* cS = (const float*)(smc + RS_HC) + 32 * 128;
        #pragma unroll
        for (int b = 0; b < 4; ++b) {
            int j0 = j0b + 8 * b;
            cc[b][0] = cS[r1 * 128 + j0];
            cc[b][1] = cS[r1 * 128 + j0 + 1];
            cc[b][2] = cS[(r1 + 8) * 128 + j0];
            cc[b][3] = cS[(r1 + 8) * 128 + j0 + 1];
        }
    }
    __syncthreads();

    for (int t = 0; t < T_STEPS; ++t) {
        float acc[16][4];
        #pragma unroll
        for (int j = 0; j < 16; ++j)
            #pragma unroll
            for (int q = 0; q < 4; ++q) acc[j][q] = 0.0f;

        #pragma unroll
        for (int kc = 0; kc < 8; ++kc) {
            uint32_t ao = (uint32_t)(kc * 32) + aSeg;
            uint32_t aH[4], aL[4];
            LDSM_X4(aH, aBaseH + (ao ^ aXor));
            LDSM_X4(aL, aBaseL + (ao ^ aXor));
            uint32_t bo = (uint32_t)(kc * 32) + bSeg;
            #pragma unroll
            for (int g = 0; g < 4; ++g)
                #pragma unroll
                for (int p = 0; p < 2; ++p) {
                    uint32_t bf[4];
                    LDSM_X4(bf, bBase[g][p] + (bo ^ bXor[g][p]));
                    int tau = g * 4 + 2 * p;
                    MMA_F16(acc[tau],     aH, bf[0], bf[1]);
                    MMA_F16(acc[tau],     aL, bf[0], bf[1]);
                    MMA_F16(acc[tau + 1], aH, bf[2], bf[3]);
                    MMA_F16(acc[tau + 1], aL, bf[2], bf[3]);
                }
        }
        __syncthreads();

        const float4* xs4 = (const float4*)(smc + RS_XS) + (t & 1) * 32;
        float4 xv1 = xs4[r1];
        float4 xv2 = xs4[r1 + 8];
        size_t row1 = (size_t)t * BATCH + gb0 + r1;
        size_t row2 = row1 + 8;

        #pragma unroll
        for (int b = 0; b < 4; ++b) {
            int j0 = j0b + 8 * b;
            float4 wq[4][2];
            #pragma unroll
            for (int g = 0; g < 4; ++g) {
                wq[g][0] = ((const float4*)(smc + RS_WIH))[g * 128 + j0];
                wq[g][1] = ((const float4*)(smc + RS_WIH))[g * 128 + j0 + 1];
            }
            float hv[4];
            #pragma unroll
            for (int q = 0; q < 4; ++q) {
                int cp = q & 1;
                float4 xv = (q >= 2) ? xv2 : xv1;
                float pre[4];
                #pragma unroll
                for (int g = 0; g < 4; ++g)
                    pre[g] = acc[g * 4 + b][q]
                           + xv.x * wq[g][cp].x + xv.y * wq[g][cp].y
                           + xv.z * wq[g][cp].z + wq[g][cp].w;
                float ig = fsig(pre[0]), fg = fsig(pre[1]);
                float gg = ftanh(pre[2]), og = fsig(pre[3]);
                float cn = fg * cc[b][q] + ig * gg;
                cc[b][q] = cn;
                hv[q] = og * ftanh(cn);
            }
            *(float2*)&out[HS_OFF + row1 * 128 + j0] = make_float2(hv[0], hv[1]);
            *(float2*)&out[HS_OFF + row2 * 128 + j0] = make_float2(hv[2], hv[3]);
            *(float2*)&out[CS_OFF + row1 * 128 + j0] = make_float2(cc[b][0], cc[b][1]);
            *(float2*)&out[CS_OFF + row2 * 128 + j0] = make_float2(cc[b][2], cc[b][3]);
            uint32_t o1 = r1 * 256 + (((uint32_t)(j0 * 2)) ^ (uint32_t)((r1 & 7) << 4));
            split2h(smc, RS_AHI + o1, RS_ALO + o1, hv[0], hv[1]);
            split2h(smc, RS_AHI + o1 + 2048, RS_ALO + o1 + 2048, hv[2], hv[3]);
        }
        if (t + 1 < T_STEPS && tid < 96) {
            int r = tid / 3, c = tid - 3 * r;
            ((float*)(smc + RS_XS))[((t + 1) & 1) * 128 + r * 4 + c] =
                x[((size_t)(t + 1) * BATCH + gb0 + r) * 3 + c];
        }
        __syncthreads();
    }
}

// ===========================================================================
// Phase 2: fused bn + pc + hd via mma.sync fp16, 2-term (A split hi/lo,
// weights single fp16 copy). Smem 110 KB + launch_bounds(256,2) -> 2 CTAs/SM.
// ===========================================================================
#define MT 64
#define SA_STR  136   // fp16 elems/row -> 272 B (16 mod 128, conflict-free)
#define SW_STR  136
#define SBN_STR 264   // 528 B
#define SPC_STR 72    // 144 B
#define SHD_STR 264

#define P_A_HI  0u
#define P_A_LO  (P_A_HI + MT*SA_STR*2)     // 17408
#define P_WBN   (P_A_LO + MT*SA_STR*2)     // 34816
#define P_WHD   (P_WBN + 256*SW_STR*2)     // 104448
#define SMEM_PH2 (P_WHD + 16*SHD_STR*2)    // 112896

// stage-B overlay (A / W_bn regions dead after stage A)
#define P_BN_HI 0u
#define P_BN_LO (P_BN_HI + MT*SBN_STR*2)   // 33792
#define P_WPC   (P_BN_LO + MT*SBN_STR*2)   // 67584 .. 104448 (W_hd untouched)

__global__ void __launch_bounds__(256, 2)
phase2_kernel(const float* __restrict__ W_bn,
              const float* __restrict__ W_pc, const float* __restrict__ b_pc,
              const float* __restrict__ W_hd, const float* __restrict__ b_hd,
              float* __restrict__ out)
{
    extern __shared__ char smc[];
    const uint32_t sb = smem_u32(smc);
    const int tid  = threadIdx.x;
    const int wid  = tid >> 5;
    const int lane = tid & 31;
    const int mw   = wid & 3;
    const int nh   = wid >> 2;
    const int rowA = 16 * mw;
    const size_t grow = (size_t)blockIdx.x * MT;

    const int aRow    = lane & 15;
    const int aSeg    = (lane >> 4) * 16;
    const int m4      = lane >> 3;
    const int bRowOff = 8 * (m4 >> 1) + (lane & 7);
    const int bColOff = 8 * (m4 & 1);

    // ---- prologue: A split fp16; W_bn, W_hd single fp16 ----
    {
        uint4 z = make_uint4(0, 0, 0, 0);
        for (int i = tid; i < (16 * SHD_STR * 2) / 16; i += 256)
            ((uint4*)(smc + P_WHD))[i] = z;
    }
    for (int b = tid; b < MT * 16; b += 256) {
        int r = b >> 4, c0 = (b & 15) << 3;
        float v[8];
        const float* s = out + HS_OFF + (grow + r) * 128 + c0;
        *(float4*)&v[0] = *(const float4*)s;
        *(float4*)&v[4] = *(const float4*)(s + 4);
        split8h(smc, P_A_HI + r * SA_STR * 2 + c0 * 2,
                     P_A_LO + r * SA_STR * 2 + c0 * 2, v);
    }
    for (int b = tid; b < 256 * 16; b += 256) {
        int r = b >> 4, c0 = (b & 15) << 3;
        float v[8];
        const float* s = W_bn + (size_t)r * 128 + c0;
        *(float4*)&v[0] = *(const float4*)s;
        *(float4*)&v[4] = *(const float4*)(s + 4);
        pack8h_store(smc, P_WBN + r * SW_STR * 2 + c0 * 2, v);
    }
    __syncthreads();   // W_hd zero done before row writes
    for (int b = tid; b < 12 * 32; b += 256) {
        int r = b >> 5, c0 = (b & 31) << 3;
        float v[8];
        const float* s = W_hd + (size_t)r * 256 + c0;
        *(float4*)&v[0] = *(const float4*)s;
        *(float4*)&v[4] = *(const float4*)(s + 4);
        pack8h_store(smc, P_WHD + r * SHD_STR * 2 + c0 * 2, v);
    }
    __syncthreads();

    float acc[16][4];
    #pragma unroll
    for (int j = 0; j < 16; ++j)
        #pragma unroll
        for (int q = 0; q < 4; ++q) acc[j][q] = 0.0f;

    // ---- stage A: D[MT,256] = HS @ W_bn^T  (K=128, 8 chunks, 2-term) ----
    for (int kc = 0; kc < 8; ++kc) {
        int k0 = kc * 16;
        uint32_t aH[4], aL[4];
        uint32_t adA = sb + P_A_HI + (rowA + aRow) * SA_STR * 2 + k0 * 2 + aSeg;
        LDSM_X4(aH, adA);
        LDSM_X4(aL, adA + (P_A_LO - P_A_HI));
        #pragma unroll
        for (int j = 0; j < 16; j += 2) {
            uint32_t adB = sb + P_WBN + (nh * 128 + 8 * j + bRowOff) * SW_STR * 2
                         + (k0 + bColOff) * 2;
            uint32_t bf[4];
            LDSM_X4(bf, adB);
            MMA_F16(acc[j],   aH, bf[0], bf[1]);
            MMA_F16(acc[j],   aL, bf[0], bf[1]);
            MMA_F16(acc[j+1], aH, bf[2], bf[3]);
            MMA_F16(acc[j+1], aL, bf[2], bf[3]);
        }
    }
    __syncthreads();   // all A/W_bn reads done -> overlay safe

    // ---- stage A epilogue: tanh -> bn gmem + split-fp16 bn smem ----
    {
        int rl = rowA + (lane >> 2);
        #pragma unroll
        for (int j = 0; j < 16; ++j) {
            int c = nh * 128 + 8 * j + 2 * (lane & 3);
            float v00 = tanhf(acc[j][0]), v01 = tanhf(acc[j][1]);
            float v10 = tanhf(acc[j][2]), v11 = tanhf(acc[j][3]);
            *(float2*)&out[BN_OFF + (grow + rl) * 256 + c]     = make_float2(v00, v01);
            *(float2*)&out[BN_OFF + (grow + rl + 8) * 256 + c] = make_float2(v10, v11);
            split2h(smc, P_BN_HI + rl * SBN_STR * 2 + c * 2,
                         P_BN_LO + rl * SBN_STR * 2 + c * 2, v00, v01);
            split2h(smc, P_BN_HI + (rl + 8) * SBN_STR * 2 + c * 2,
                         P_BN_LO + (rl + 8) * SBN_STR * 2 + c * 2, v10, v11);
        }
    }
    __syncthreads();   // bn smem tile complete

    // ---- stage B part 1: hd accum (nh==0 warps), W_hd resident ----
    float ahd[2][4];
    #pragma unroll
    for (int j = 0; j < 2; ++j)
        #pragma unroll
        for (int q = 0; q < 4; ++q) ahd[j][q] = 0.0f;

    if (nh == 0) {
        for (int kc = 0; kc < 16; ++kc) {
            int k0 = kc * 16;
            uint32_t aH[4], aL[4];
            uint32_t adA = sb + P_BN_HI + (rowA + aRow) * SBN_STR * 2 + k0 * 2 + aSeg;
            LDSM_X4(aH, adA);
            LDSM_X4(aL, adA + (P_BN_LO - P_BN_HI));
            uint32_t adB = sb + P_WHD + bRowOff * SHD_STR * 2 + (k0 + bColOff) * 2;
            uint32_t bf[4];
            LDSM_X4(bf, adB);
            MMA_F16(ahd[0], aH, bf[0], bf[1]);
            MMA_F16(ahd[0], aL, bf[0], bf[1]);
            MMA_F16(ahd[1], aH, bf[2], bf[3]);
            MMA_F16(ahd[1], aL, bf[2], bf[3]);
        }
    }

    // ---- stage B part 2: pc = bn @ W_pc^T (K=256, stream 4 chunks of 64) ----
    #pragma unroll
    for (int j = 0; j < 16; ++j)
        #pragma unroll
        for (int q = 0; q < 4; ++q) acc[j][q] = 0.0f;

    for (int kc2 = 0; kc2 < 4; ++kc2) {
        __syncthreads();   // previous chunk's ldmatrix reads complete
        for (int b = tid; b < 256 * 8; b += 256) {
            int r = b >> 3, c0 = (b & 7) << 3;
            float v[8];
            const float* s = W_pc + (size_t)r * 256 + kc2 * 64 + c0;
            *(float4*)&v[0] = *(const float4*)s;
            *(float4*)&v[4] = *(const float4*)(s + 4);
            pack8h_store(smc, P_WPC + r * SPC_STR * 2 + c0 * 2, v);
        }
        __syncthreads();
        for (int kc = 0; kc < 4; ++kc) {
            int kk = kc2 * 64 + kc * 16;
            uint32_t aH[4], aL[4];
            uint32_t adA = sb + P_BN_HI + (rowA + aRow) * SBN_STR * 2 + kk * 2 + aSeg;
            LDSM_X4(aH, adA);
            LDSM_X4(aL, adA + (P_BN_LO - P_BN_HI));
            #pragma unroll
            for (int j = 0; j < 16; j += 2) {
                uint32_t adB = sb + P_WPC + (nh * 128 + 8 * j + bRowOff) * SPC_STR * 2
                             + (kc * 16 + bColOff) * 2;
                uint32_t bf[4];
                LDSM_X4(bf, adB);
                MMA_F16(acc[j],   aH, bf[0], bf[1]);
                MMA_F16(acc[j],   aL, bf[0], bf[1]);
                MMA_F16(acc[j+1], aH, bf[2], bf[3]);
                MMA_F16(acc[j+1], aL, bf[2], bf[3]);
            }
        }
    }

    // ---- pc epilogue ----
    {
        int rl = rowA + (lane >> 2);
        #pragma unroll
        for (int j = 0; j < 16; ++j) {
            int c = nh * 128 + 8 * j + 2 * (lane & 3);
            float b0 = __ldg(&b_pc[c]), b1 = __ldg(&b_pc[c + 1]);
            float2* o0 = (float2*)&out[PC_OFF + (grow + rl) * 256 + c];
            float2* o1 = (float2*)&out[PC_OFF + (grow + rl + 8) * 256 + c];
            *o0 = make_float2(acc[j][0] + b0, acc[j][1] + b1);
            *o1 = make_float2(acc[j][2] + b0, acc[j][3] + b1);
        }
    }

    // ---- hd epilogue (nh==0 warps, cols 0..11 valid) ----
    if (nh == 0) {
        int rl = rowA + (lane >> 2);
        #pragma unroll
        for (int j = 0; j < 2; ++j) {
            int cb = 8 * j + 2 * (lane & 3);
            float* o0 = out + HD_OFF + (grow + rl) * 12;
            float* o1 = out + HD_OFF + (grow + rl + 8) * 12;
            if (cb < 12) {
                float bb = __ldg(&b_hd[cb]);
                o0[cb] = ahd[j][0] + bb;
                o1[cb] = ahd[j][2] + bb;
            }
            if (cb + 1 < 12) {
                float bb = __ldg(&b_hd[cb + 1]);
                o0[cb + 1] = ahd[j][1] + bb;
                o1[cb + 1] = ahd[j][3] + bb;
            }
        }
    }
}

// ===========================================================================
extern "C" void kernel_launch(void* const* d_in, const int* in_sizes, int n_in,
                              void* d_out, int out_size)
{
    const float* x       = (const float*)d_in[0];
    const float* init_pc = (const float*)d_in[1];
    const float* init_hd = (const float*)d_in[2];
    const float* W_state = (const float*)d_in[3];
    const float* b_state = (const float*)d_in[4];
    const float* W_cell  = (const float*)d_in[5];
    const float* b_cell  = (const float*)d_in[6];
    const float* W_ih    = (const float*)d_in[7];
    const float* W_hh    = (const float*)d_in[8];
    const float* b_ih    = (const float*)d_in[9];
    const float* b_hh    = (const float*)d_in[10];
    const float* W_bn    = (const float*)d_in[11];
    const float* W_pc    = (const float*)d_in[12];
    const float* b_pc    = (const float*)d_in[13];
    const float* W_hd    = (const float*)d_in[14];
    const float* b_hd    = (const float*)d_in[15];
    float* out = (float*)d_out;

    cudaFuncSetAttribute(recur_tc,      cudaFuncAttributeMaxDynamicSharedMemorySize, (int)RS_TOTAL);
    cudaFuncSetAttribute(phase2_kernel, cudaFuncAttributeMaxDynamicSharedMemorySize, (int)SMEM_PH2);

    recur_tc<<<BATCH / 32, 256, RS_TOTAL>>>(x, init_pc, init_hd,
                                            W_state, b_state, W_cell, b_cell,
                                            W_ih, W_hh, b_ih, b_hh, out);
    phase2_kernel<<<(T_STEPS * BATCH) / MT, 256, SMEM_PH2>>>(
        W_bn, W_pc, b_pc, W_hd, b_hd, out);
}

// round 14
// speedup vs baseline: 3.1020x; 1.1739x over previous
#include <cuda_runtime.h>
#include <cuda_bf16.h>
#include <cuda_fp16.h>
#include <math.h>
#include <stdint.h>

// Problem constants
#define T_STEPS 100
#define BATCH   4096
#define NH      128
#define NG      512
#define NPC     256
#define NHD     12
#define NB      256
#define KIN     268   // NPC + NHD

// Output layout: tuple (hd, pc, bn, hs, cs) flattened in order
#define HD_OFF  ((size_t)0)
#define PC_OFF  ((size_t)T_STEPS * BATCH * NHD)
#define BN_OFF  (PC_OFF + (size_t)T_STEPS * BATCH * NPC)
#define HS_OFF  (BN_OFF + (size_t)T_STEPS * BATCH * NB)
#define CS_OFF  (HS_OFF + (size_t)T_STEPS * BATCH * NH)

__device__ __forceinline__ uint32_t smem_u32(const void* p) {
    uint32_t a;
    asm("{ .reg .u64 t; cvta.to.shared.u64 t, %1; cvt.u32.u64 %0, t; }"
        : "=r"(a) : "l"(p));
    return a;
}

// ---- base-PTX tensor ops (compile for compute_103, no 'a' features) ----
#define LDSM_X4(R, addr) \
    asm volatile("ldmatrix.sync.aligned.m8n8.x4.shared.b16 {%0,%1,%2,%3}, [%4];" \
        : "=r"((R)[0]), "=r"((R)[1]), "=r"((R)[2]), "=r"((R)[3]) : "r"(addr))

#define MMA_F16(D, A, b0, b1) \
    asm volatile("mma.sync.aligned.m16n8k16.row.col.f32.f16.f16.f32 " \
        "{%0,%1,%2,%3}, {%4,%5,%6,%7}, {%8,%9}, {%0,%1,%2,%3};" \
        : "+f"((D)[0]), "+f"((D)[1]), "+f"((D)[2]), "+f"((D)[3]) \
        : "r"((A)[0]), "r"((A)[1]), "r"((A)[2]), "r"((A)[3]), "r"(b0), "r"(b1))

// fast activations (accurate to ~1e-6, safe at +-inf)
__device__ __forceinline__ float fsig(float v)  { return 1.0f / (1.0f + __expf(-v)); }
__device__ __forceinline__ float ftanh(float v) { return 1.0f - 2.0f / (__expf(2.0f * v) + 1.0f); }

// ---- fp16 pack / hi-lo split helpers ----
__device__ __forceinline__ uint32_t pack2h(float a, float b) {
    return (uint32_t)__half_as_ushort(__float2half_rn(a))
         | ((uint32_t)__half_as_ushort(__float2half_rn(b)) << 16);
}

__device__ __forceinline__ void pack8h_store(char* sm, uint32_t off, const float* v) {
    *(uint4*)(sm + off) = make_uint4(pack2h(v[0], v[1]), pack2h(v[2], v[3]),
                                     pack2h(v[4], v[5]), pack2h(v[6], v[7]));
}

__device__ __forceinline__ void split8h(char* sm, uint32_t hi_off, uint32_t lo_off,
                                        const float* v) {
    uint32_t H[4], L[4];
    #pragma unroll
    for (int i = 0; i < 4; ++i) {
        __half h0 = __float2half_rn(v[2 * i]);
        __half h1 = __float2half_rn(v[2 * i + 1]);
        __half l0 = __float2half_rn(v[2 * i]     - __half2float(h0));
        __half l1 = __float2half_rn(v[2 * i + 1] - __half2float(h1));
        H[i] = (uint32_t)__half_as_ushort(h0) | ((uint32_t)__half_as_ushort(h1) << 16);
        L[i] = (uint32_t)__half_as_ushort(l0) | ((uint32_t)__half_as_ushort(l1) << 16);
    }
    *(uint4*)(sm + hi_off) = make_uint4(H[0], H[1], H[2], H[3]);
    *(uint4*)(sm + lo_off) = make_uint4(L[0], L[1], L[2], L[3]);
}

__device__ __forceinline__ void split2h(char* sm, uint32_t hi_off, uint32_t lo_off,
                                        float a, float b) {
    __half ha = __float2half_rn(a), hb = __float2half_rn(b);
    __half la = __float2half_rn(a - __half2float(ha));
    __half lb = __float2half_rn(b - __half2float(hb));
    *(uint32_t*)(sm + hi_off) = (uint32_t)__half_as_ushort(ha) | ((uint32_t)__half_as_ushort(hb) << 16);
    *(uint32_t*)(sm + lo_off) = (uint32_t)__half_as_ushort(la) | ((uint32_t)__half_as_ushort(lb) << 16);
}

// ===========================================================================
// Phase 1: recurrence via mma.sync fp16 (2-term split: Ah*B + Al*B).
// 512 threads = 16 warps (R12: doubled from 8 for latency hiding).
// Warp: mrow = wid&1 (16 rows), jgrp = wid>>1 (16 j-cols per gate, all 4 gates).
// In-register LSTM update; c-state resident in registers for all 100 steps.
// W_hh fp16 resident in smem, XOR-swizzled rows (256B row, ^(n&7)<<4).
// ===========================================================================
#define RS_WH    0                        // [512][128] fp16 swz = 131072
#define RS_AHI   131072                   // [32][128] fp16 swz = 8192
#define RS_ALO   (RS_AHI + 8192)
#define RS_WIH   (RS_ALO + 8192)          // float4[512]: {w0,w1,w2,bias}
#define RS_XS    (RS_WIH + 8192)          // float4[2][32]
#define RS_HC    (RS_XS + 1024)           // fp32 h0/c0 scratch [2][32][128]
#define RS_TOTAL (RS_HC + 32768)          // 189440
// init-phase overlay inside RS_WH region:
#define RS_INITS 0                        // [32][268] fp32
#define RS_WT    34816                    // [64][129] fp32

__global__ void __launch_bounds__(512, 1)
recur_tc(const float* __restrict__ x,
         const float* __restrict__ init_pc,
         const float* __restrict__ init_hd,
         const float* __restrict__ W_state, const float* __restrict__ b_state,
         const float* __restrict__ W_cell,  const float* __restrict__ b_cell,
         const float* __restrict__ W_ih,    const float* __restrict__ W_hh,
         const float* __restrict__ b_ih,    const float* __restrict__ b_hh,
         float* __restrict__ out)
{
    extern __shared__ char smc[];
    const uint32_t sb = smem_u32(smc);
    const int tid  = threadIdx.x;
    const int wid  = tid >> 5;
    const int lane = tid & 31;
    const int mrow = wid & 1;
    const int jgrp = wid >> 1;            // 0..7, 16 j-cols each
    const int gb0  = blockIdx.x * 32;

    // ---------------- init: h0/c0 SIMT GEMM (K=268), runs once ----------------
    {
        float* initS = (float*)(smc + RS_INITS);
        float* wT    = (float*)(smc + RS_WT);
        float* hS    = (float*)(smc + RS_HC);
        float* cS    = hS + 32 * 128;

        for (int i = tid; i < 32 * KIN; i += 512) {
            int r = i / KIN, k = i - r * KIN;
            float v = (k < 256) ? init_pc[(size_t)(gb0 + r) * 256 + k]
                                : init_hd[(size_t)(gb0 + r) * 12 + (k - 256)];
            initS[r * KIN + k] = v;
        }
        __syncthreads();

        for (int p = 0; p < 2; ++p) {
            const float* W  = p ? W_cell : W_state;
            const float* bb = p ? b_cell : b_state;
            float acc[8];
            #pragma unroll
            for (int o = 0; o < 8; ++o) acc[o] = 0.0f;

            for (int kt = 0; kt < KIN; kt += 64) {
                int len = KIN - kt; if (len > 64) len = 64;
                for (int i = tid; i < 128 * 64; i += 512) {
                    int n = i >> 6, kk = i & 63;
                    if (kk < len) wT[kk * 129 + n] = W[n * KIN + kt + kk];
                }
                __syncthreads();
                for (int kk = 0; kk < len; ++kk) {
                    #pragma unroll
                    for (int o = 0; o < 8; ++o) {
                        int idx = o * 512 + tid;
                        int r = idx >> 7, n = idx & 127;
                        acc[o] += initS[r * KIN + kt + kk] * wT[kk * 129 + n];
                    }
                }
                __syncthreads();
            }
            float* dst = p ? cS : hS;
            #pragma unroll
            for (int o = 0; o < 8; ++o) {
                int idx = o * 512 + tid;
                int r = idx >> 7, n = idx & 127;
                dst[r * 128 + n] = acc[o] + bb[n];
            }
            __syncthreads();
        }
    }

    // ---------------- load W_hh fp16 (swizzled), wih+bias, x[0], h0 split ----
    for (int i = tid; i < 512 * 32; i += 512) {
        int row = i >> 5, q = i & 31;
        float4 w = *(const float4*)&W_hh[row * 128 + 4 * q];
        uint2 h4 = make_uint2(pack2h(w.x, w.y), pack2h(w.z, w.w));
        uint32_t off = ((uint32_t)(8 * q)) ^ (uint32_t)((row & 7) << 4);
        *(uint2*)(smc + RS_WH + row * 256 + off) = h4;
    }
    {
        int n = tid;   // exactly 512 threads, one row each
        ((float4*)(smc + RS_WIH))[n] =
            make_float4(W_ih[n * 3 + 0], W_ih[n * 3 + 1], W_ih[n * 3 + 2],
                        b_ih[n] + b_hh[n]);
    }
    if (tid < 96) {
        int r = tid / 3, c = tid - 3 * r;
        ((float*)(smc + RS_XS))[r * 4 + c] = x[((size_t)0 * BATCH + gb0 + r) * 3 + c];
    }
    {
        const float* hS = (const float*)(smc + RS_HC);
        int i = tid;   // 512 groups of 8, one each
        int row = i >> 4, c0 = (i & 15) * 8;
        uint32_t off = row * 256 + (((uint32_t)(c0 * 2)) ^ (uint32_t)((row & 7) << 4));
        split8h(smc, RS_AHI + off, RS_ALO + off, &hS[row * 128 + c0]);
    }

    // ---------------- per-lane constants ----------------
    const int r1  = 16 * mrow + (lane >> 2);       // epilogue rows r1, r1+8
    const int j0a = jgrp * 16 + 2 * (lane & 3);    // epilogue col base (+8b)

    const int aRowL = 16 * mrow + (lane & 15);
    const uint32_t aBaseH = sb + RS_AHI + aRowL * 256;
    const uint32_t aBaseL = sb + RS_ALO + aRowL * 256;
    const uint32_t aXor   = (uint32_t)((aRowL & 7) << 4);
    const uint32_t aSeg   = (uint32_t)((lane >> 4) * 16);
    const int m4 = lane >> 3;
    const int bRowOff = 8 * (m4 >> 1) + (lane & 7);
    const uint32_t bSeg = (uint32_t)((m4 & 1) * 16);
    uint32_t bBase[4], bXor[4];
    #pragma unroll
    for (int g = 0; g < 4; ++g) {
        int n = g * 128 + jgrp * 16 + bRowOff;
        bBase[g] = sb + RS_WH + n * 256;
        bXor[g]  = (uint32_t)((n & 7) << 4);
    }

    // c-state registers
    float cc[2][4];
    {
        const float* cS = (const float*)(smc + RS_HC) + 32 * 128;
        #pragma unroll
        for (int b = 0; b < 2; ++b) {
            int j0 = j0a + 8 * b;
            cc[b][0] = cS[r1 * 128 + j0];
            cc[b][1] = cS[r1 * 128 + j0 + 1];
            cc[b][2] = cS[(r1 + 8) * 128 + j0];
            cc[b][3] = cS[(r1 + 8) * 128 + j0 + 1];
        }
    }
    __syncthreads();

    // ---------------- time loop ----------------
    for (int t = 0; t < T_STEPS; ++t) {
        float acc[8][4];
        #pragma unroll
        for (int j = 0; j < 8; ++j)
            #pragma unroll
            for (int q = 0; q < 4; ++q) acc[j][q] = 0.0f;

        #pragma unroll
        for (int kc = 0; kc < 8; ++kc) {
            uint32_t ao = (uint32_t)(kc * 32) + aSeg;
            uint32_t aH[4], aL[4];
            LDSM_X4(aH, aBaseH + (ao ^ aXor));
            LDSM_X4(aL, aBaseL + (ao ^ aXor));
            uint32_t bo = (uint32_t)(kc * 32) + bSeg;
            #pragma unroll
            for (int g = 0; g < 4; ++g) {
                uint32_t bf[4];
                LDSM_X4(bf, bBase[g] + (bo ^ bXor[g]));
                int tau = g * 2;
                MMA_F16(acc[tau],     aH, bf[0], bf[1]);
                MMA_F16(acc[tau],     aL, bf[0], bf[1]);
                MMA_F16(acc[tau + 1], aH, bf[2], bf[3]);
                MMA_F16(acc[tau + 1], aL, bf[2], bf[3]);
            }
        }
        __syncthreads();    // all A reads done -> safe to overwrite A below

        // ---- in-register LSTM epilogue ----
        const float4* xs4 = (const float4*)(smc + RS_XS) + (t & 1) * 32;
        float4 xv1 = xs4[r1];
        float4 xv2 = xs4[r1 + 8];
        size_t row1 = (size_t)t * BATCH + gb0 + r1;
        size_t row2 = row1 + 8;

        #pragma unroll
        for (int b = 0; b < 2; ++b) {
            int j0 = j0a + 8 * b;
            float4 wq[4][2];
            #pragma unroll
            for (int g = 0; g < 4; ++g) {
                wq[g][0] = ((const float4*)(smc + RS_WIH))[g * 128 + j0];
                wq[g][1] = ((const float4*)(smc + RS_WIH))[g * 128 + j0 + 1];
            }
            float hv[4];
            #pragma unroll
            for (int q = 0; q < 4; ++q) {
                int cp = q & 1;
                float4 xv = (q >= 2) ? xv2 : xv1;
                float pre[4];
                #pragma unroll
                for (int g = 0; g < 4; ++g)
                    pre[g] = acc[g * 2 + b][q]
                           + xv.x * wq[g][cp].x + xv.y * wq[g][cp].y
                           + xv.z * wq[g][cp].z + wq[g][cp].w;
                float ig = fsig(pre[0]), fg = fsig(pre[1]);
                float gg = ftanh(pre[2]), og = fsig(pre[3]);
                float cn = fg * cc[b][q] + ig * gg;
                cc[b][q] = cn;
                hv[q] = og * ftanh(cn);
            }
            *(float2*)&out[HS_OFF + row1 * 128 + j0] = make_float2(hv[0], hv[1]);
            *(float2*)&out[HS_OFF + row2 * 128 + j0] = make_float2(hv[2], hv[3]);
            *(float2*)&out[CS_OFF + row1 * 128 + j0] = make_float2(cc[b][0], cc[b][1]);
            *(float2*)&out[CS_OFF + row2 * 128 + j0] = make_float2(cc[b][2], cc[b][3]);
            uint32_t o1 = r1 * 256 + (((uint32_t)(j0 * 2)) ^ (uint32_t)((r1 & 7) << 4));
            split2h(smc, RS_AHI + o1, RS_ALO + o1, hv[0], hv[1]);
            split2h(smc, RS_AHI + o1 + 2048, RS_ALO + o1 + 2048, hv[2], hv[3]);
        }
        if (t + 1 < T_STEPS && tid < 96) {
            int r = tid / 3, c = tid - 3 * r;
            ((float*)(smc + RS_XS))[((t + 1) & 1) * 128 + r * 4 + c] =
                x[((size_t)(t + 1) * BATCH + gb0 + r) * 3 + c];
        }
        __syncthreads();
    }
}

// ===========================================================================
// Phase 2: fused bn + pc + hd via mma.sync fp16, 2-term (A split hi/lo,
// weights single fp16 copy). Unchanged from R11 (761 us, occ 24.5%).
// ===========================================================================
#define MT 64
#define SA_STR  136   // fp16 elems/row -> 272 B (16 mod 128, conflict-free)
#define SW_STR  136
#define SBN_STR 264   // 528 B
#define SPC_STR 72    // 144 B
#define SHD_STR 264

#define P_A_HI  0u
#define P_A_LO  (P_A_HI + MT*SA_STR*2)     // 17408
#define P_WBN   (P_A_LO + MT*SA_STR*2)     // 34816
#define P_WHD   (P_WBN + 256*SW_STR*2)     // 104448
#define SMEM_PH2 (P_WHD + 16*SHD_STR*2)    // 112896

// stage-B overlay (A / W_bn regions dead after stage A)
#define P_BN_HI 0u
#define P_BN_LO (P_BN_HI + MT*SBN_STR*2)   // 33792
#define P_WPC   (P_BN_LO + MT*SBN_STR*2)   // 67584 .. 104448 (W_hd untouched)

__global__ void __launch_bounds__(256, 2)
phase2_kernel(const float* __restrict__ W_bn,
              const float* __restrict__ W_pc, const float* __restrict__ b_pc,
              const float* __restrict__ W_hd, const float* __restrict__ b_hd,
              float* __restrict__ out)
{
    extern __shared__ char smc[];
    const uint32_t sb = smem_u32(smc);
    const int tid  = threadIdx.x;
    const int wid  = tid >> 5;
    const int lane = tid & 31;
    const int mw   = wid & 3;
    const int nh   = wid >> 2;
    const int rowA = 16 * mw;
    const size_t grow = (size_t)blockIdx.x * MT;

    const int aRow    = lane & 15;
    const int aSeg    = (lane >> 4) * 16;
    const int m4      = lane >> 3;
    const int bRowOff = 8 * (m4 >> 1) + (lane & 7);
    const int bColOff = 8 * (m4 & 1);

    // ---- prologue: A split fp16; W_bn, W_hd single fp16 ----
    {
        uint4 z = make_uint4(0, 0, 0, 0);
        for (int i = tid; i < (16 * SHD_STR * 2) / 16; i += 256)
            ((uint4*)(smc + P_WHD))[i] = z;
    }
    for (int b = tid; b < MT * 16; b += 256) {
        int r = b >> 4, c0 = (b & 15) << 3;
        float v[8];
        const float* s = out + HS_OFF + (grow + r) * 128 + c0;
        *(float4*)&v[0] = *(const float4*)s;
        *(float4*)&v[4] = *(const float4*)(s + 4);
        split8h(smc, P_A_HI + r * SA_STR * 2 + c0 * 2,
                     P_A_LO + r * SA_STR * 2 + c0 * 2, v);
    }
    for (int b = tid; b < 256 * 16; b += 256) {
        int r = b >> 4, c0 = (b & 15) << 3;
        float v[8];
        const float* s = W_bn + (size_t)r * 128 + c0;
        *(float4*)&v[0] = *(const float4*)s;
        *(float4*)&v[4] = *(const float4*)(s + 4);
        pack8h_store(smc, P_WBN + r * SW_STR * 2 + c0 * 2, v);
    }
    __syncthreads();   // W_hd zero done before row writes
    for (int b = tid; b < 12 * 32; b += 256) {
        int r = b >> 5, c0 = (b & 31) << 3;
        float v[8];
        const float* s = W_hd + (size_t)r * 256 + c0;
        *(float4*)&v[0] = *(const float4*)s;
        *(float4*)&v[4] = *(const float4*)(s + 4);
        pack8h_store(smc, P_WHD + r * SHD_STR * 2 + c0 * 2, v);
    }
    __syncthreads();

    float acc[16][4];
    #pragma unroll
    for (int j = 0; j < 16; ++j)
        #pragma unroll
        for (int q = 0; q < 4; ++q) acc[j][q] = 0.0f;

    // ---- stage A: D[MT,256] = HS @ W_bn^T  (K=128, 8 chunks, 2-term) ----
    for (int kc = 0; kc < 8; ++kc) {
        int k0 = kc * 16;
        uint32_t aH[4], aL[4];
        uint32_t adA = sb + P_A_HI + (rowA + aRow) * SA_STR * 2 + k0 * 2 + aSeg;
        LDSM_X4(aH, adA);
        LDSM_X4(aL, adA + (P_A_LO - P_A_HI));
        #pragma unroll
        for (int j = 0; j < 16; j += 2) {
            uint32_t adB = sb + P_WBN + (nh * 128 + 8 * j + bRowOff) * SW_STR * 2
                         + (k0 + bColOff) * 2;
            uint32_t bf[4];
            LDSM_X4(bf, adB);
            MMA_F16(acc[j],   aH, bf[0], bf[1]);
            MMA_F16(acc[j],   aL, bf[0], bf[1]);
            MMA_F16(acc[j+1], aH, bf[2], bf[3]);
            MMA_F16(acc[j+1], aL, bf[2], bf[3]);
        }
    }
    __syncthreads();   // all A/W_bn reads done -> overlay safe

    // ---- stage A epilogue: tanh -> bn gmem + split-fp16 bn smem ----
    {
        int rl = rowA + (lane >> 2);
        #pragma unroll
        for (int j = 0; j < 16; ++j) {
            int c = nh * 128 + 8 * j + 2 * (lane & 3);
            float v00 = tanhf(acc[j][0]), v01 = tanhf(acc[j][1]);
            float v10 = tanhf(acc[j][2]), v11 = tanhf(acc[j][3]);
            *(float2*)&out[BN_OFF + (grow + rl) * 256 + c]     = make_float2(v00, v01);
            *(float2*)&out[BN_OFF + (grow + rl + 8) * 256 + c] = make_float2(v10, v11);
            split2h(smc, P_BN_HI + rl * SBN_STR * 2 + c * 2,
                         P_BN_LO + rl * SBN_STR * 2 + c * 2, v00, v01);
            split2h(smc, P_BN_HI + (rl + 8) * SBN_STR * 2 + c * 2,
                         P_BN_LO + (rl + 8) * SBN_STR * 2 + c * 2, v10, v11);
        }
    }
    __syncthreads();   // bn smem tile complete

    // ---- stage B part 1: hd accum (nh==0 warps), W_hd resident ----
    float ahd[2][4];
    #pragma unroll
    for (int j = 0; j < 2; ++j)
        #pragma unroll
        for (int q = 0; q < 4; ++q) ahd[j][q] = 0.0f;

    if (nh == 0) {
        for (int kc = 0; kc < 16; ++kc) {
            int k0 = kc * 16;
            uint32_t aH[4], aL[4];
            uint32_t adA = sb + P_BN_HI + (rowA + aRow) * SBN_STR * 2 + k0 * 2 + aSeg;
            LDSM_X4(aH, adA);
            LDSM_X4(aL, adA + (P_BN_LO - P_BN_HI));
            uint32_t adB = sb + P_WHD + bRowOff * SHD_STR * 2 + (k0 + bColOff) * 2;
            uint32_t bf[4];
            LDSM_X4(bf, adB);
            MMA_F16(ahd[0], aH, bf[0], bf[1]);
            MMA_F16(ahd[0], aL, bf[0], bf[1]);
            MMA_F16(ahd[1], aH, bf[2], bf[3]);
            MMA_F16(ahd[1], aL, bf[2], bf[3]);
        }
    }

    // ---- stage B part 2: pc = bn @ W_pc^T (K=256, stream 4 chunks of 64) ----
    #pragma unroll
    for (int j = 0; j < 16; ++j)
        #pragma unroll
        for (int q = 0; q < 4; ++q) acc[j][q] = 0.0f;

    for (int kc2 = 0; kc2 < 4; ++kc2) {
        __syncthreads();   // previous chunk's ldmatrix reads complete
        for (int b = tid; b < 256 * 8; b += 256) {
            int r = b >> 3, c0 = (b & 7) << 3;
            float v[8];
            const float* s = W_pc + (size_t)r * 256 + kc2 * 64 + c0;
            *(float4*)&v[0] = *(const float4*)s;
            *(float4*)&v[4] = *(const float4*)(s + 4);
            pack8h_store(smc, P_WPC + r * SPC_STR * 2 + c0 * 2, v);
        }
        __syncthreads();
        for (int kc = 0; kc < 4; ++kc) {
            int kk = kc2 * 64 + kc * 16;
            uint32_t aH[4], aL[4];
            uint32_t adA = sb + P_BN_HI + (rowA + aRow) * SBN_STR * 2 + kk * 2 + aSeg;
            LDSM_X4(aH, adA);
            LDSM_X4(aL, adA + (P_BN_LO - P_BN_HI));
            #pragma unroll
            for (int j = 0; j < 16; j += 2) {
                uint32_t adB = sb + P_WPC + (nh * 128 + 8 * j + bRowOff) * SPC_STR * 2
                             + (kc * 16 + bColOff) * 2;
                uint32_t bf[4];
                LDSM_X4(bf, adB);
                MMA_F16(acc[j],   aH, bf[0], bf[1]);
                MMA_F16(acc[j],   aL, bf[0], bf[1]);
                MMA_F16(acc[j+1], aH, bf[2], bf[3]);
                MMA_F16(acc[j+1], aL, bf[2], bf[3]);
            }
        }
    }

    // ---- pc epilogue ----
    {
        int rl = rowA + (lane >> 2);
        #pragma unroll
        for (int j = 0; j < 16; ++j) {
            int c = nh * 128 + 8 * j + 2 * (lane & 3);
            float b0 = __ldg(&b_pc[c]), b1 = __ldg(&b_pc[c + 1]);
            float2* o0 = (float2*)&out[PC_OFF + (grow + rl) * 256 + c];
            float2* o1 = (float2*)&out[PC_OFF + (grow + rl + 8) * 256 + c];
            *o0 = make_float2(acc[j][0] + b0, acc[j][1] + b1);
            *o1 = make_float2(acc[j][2] + b0, acc[j][3] + b1);
        }
    }

    // ---- hd epilogue (nh==0 warps, cols 0..11 valid) ----
    if (nh == 0) {
        int rl = rowA + (lane >> 2);
        #pragma unroll
        for (int j = 0; j < 2; ++j) {
            int cb = 8 * j + 2 * (lane & 3);
            float* o0 = out + HD_OFF + (grow + rl) * 12;
            float* o1 = out + HD_OFF + (grow + rl + 8) * 12;
            if (cb < 12) {
                float bb = __ldg(&b_hd[cb]);
                o0[cb] = ahd[j][0] + bb;
                o1[cb] = ahd[j][2] + bb;
            }
            if (cb + 1 < 12) {
                float bb = __ldg(&b_hd[cb + 1]);
                o0[cb + 1] = ahd[j][1] + bb;
                o1[cb + 1] = ahd[j][3] + bb;
            }
        }
    }
}

// ===========================================================================
extern "C" void kernel_launch(void* const* d_in, const int* in_sizes, int n_in,
                              void* d_out, int out_size)
{
    const float* x       = (const float*)d_in[0];
    const float* init_pc = (const float*)d_in[1];
    const float* init_hd = (const float*)d_in[2];
    const float* W_state = (const float*)d_in[3];
    const float* b_state = (const float*)d_in[4];
    const float* W_cell  = (const float*)d_in[5];
    const float* b_cell  = (const float*)d_in[6];
    const float* W_ih    = (const float*)d_in[7];
    const float* W_hh    = (const float*)d_in[8];
    const float* b_ih    = (const float*)d_in[9];
    const float* b_hh    = (const float*)d_in[10];
    const float* W_bn    = (const float*)d_in[11];
    const float* W_pc    = (const float*)d_in[12];
    const float* b_pc    = (const float*)d_in[13];
    const float* W_hd    = (const float*)d_in[14];
    const float* b_hd    = (const float*)d_in[15];
    float* out = (float*)d_out;

    cudaFuncSetAttribute(recur_tc,      cudaFuncAttributeMaxDynamicSharedMemorySize, (int)RS_TOTAL);
    cudaFuncSetAttribute(phase2_kernel, cudaFuncAttributeMaxDynamicSharedMemorySize, (int)SMEM_PH2);

    recur_tc<<<BATCH / 32, 512, RS_TOTAL>>>(x, init_pc, init_hd,
                                            W_state, b_state, W_cell, b_cell,
                                            W_ih, W_hh, b_ih, b_hh, out);
    phase2_kernel<<<(T_STEPS * BATCH) / MT, 256, SMEM_PH2>>>(
        W_bn, W_pc, b_pc, W_hd, b_hd, out);
}

// round 15
// speedup vs baseline: 3.8055x; 1.2268x over previous
#include <cuda_runtime.h>
#include <cuda_bf16.h>
#include <cuda_fp16.h>
#include <math.h>
#include <stdint.h>

// Problem constants
#define T_STEPS 100
#define BATCH   4096
#define NH      128
#define NG      512
#define NPC     256
#define NHD     12
#define NB      256
#define KIN     268   // NPC + NHD

// Output layout: tuple (hd, pc, bn, hs, cs) flattened in order
#define HD_OFF  ((size_t)0)
#define PC_OFF  ((size_t)T_STEPS * BATCH * NHD)
#define BN_OFF  (PC_OFF + (size_t)T_STEPS * BATCH * NPC)
#define HS_OFF  (BN_OFF + (size_t)T_STEPS * BATCH * NB)
#define CS_OFF  (HS_OFF + (size_t)T_STEPS * BATCH * NH)

__device__ __forceinline__ uint32_t smem_u32(const void* p) {
    uint32_t a;
    asm("{ .reg .u64 t; cvta.to.shared.u64 t, %1; cvt.u32.u64 %0, t; }"
        : "=r"(a) : "l"(p));
    return a;
}

// ---- base-PTX tensor ops (compile for compute_103, no 'a' features) ----
#define LDSM_X4(R, addr) \
    asm volatile("ldmatrix.sync.aligned.m8n8.x4.shared.b16 {%0,%1,%2,%3}, [%4];" \
        : "=r"((R)[0]), "=r"((R)[1]), "=r"((R)[2]), "=r"((R)[3]) : "r"(addr))

#define MMA_F16(D, A, b0, b1) \
    asm volatile("mma.sync.aligned.m16n8k16.row.col.f32.f16.f16.f32 " \
        "{%0,%1,%2,%3}, {%4,%5,%6,%7}, {%8,%9}, {%0,%1,%2,%3};" \
        : "+f"((D)[0]), "+f"((D)[1]), "+f"((D)[2]), "+f"((D)[3]) \
        : "r"((A)[0]), "r"((A)[1]), "r"((A)[2]), "r"((A)[3]), "r"(b0), "r"(b1))

// fast activations: __expf + __fdividef only (2 MUFU each, ~1e-6 accuracy,
// safe at +-inf: rcp(inf)=0)
__device__ __forceinline__ float fsig(float v)  {
    float e = __expf(-v);
    return __fdividef(1.0f, 1.0f + e);
}
__device__ __forceinline__ float ftanh(float v) {
    float e = __expf(2.0f * v);
    return 1.0f - __fdividef(2.0f, e + 1.0f);
}

// ---- fp16 pack / hi-lo split helpers ----
__device__ __forceinline__ uint32_t pack2h(float a, float b) {
    return (uint32_t)__half_as_ushort(__float2half_rn(a))
         | ((uint32_t)__half_as_ushort(__float2half_rn(b)) << 16);
}

__device__ __forceinline__ void pack8h_store(char* sm, uint32_t off, const float* v) {
    *(uint4*)(sm + off) = make_uint4(pack2h(v[0], v[1]), pack2h(v[2], v[3]),
                                     pack2h(v[4], v[5]), pack2h(v[6], v[7]));
}

__device__ __forceinline__ void split8h(char* sm, uint32_t hi_off, uint32_t lo_off,
                                        const float* v) {
    uint32_t H[4], L[4];
    #pragma unroll
    for (int i = 0; i < 4; ++i) {
        __half h0 = __float2half_rn(v[2 * i]);
        __half h1 = __float2half_rn(v[2 * i + 1]);
        __half l0 = __float2half_rn(v[2 * i]     - __half2float(h0));
        __half l1 = __float2half_rn(v[2 * i + 1] - __half2float(h1));
        H[i] = (uint32_t)__half_as_ushort(h0) | ((uint32_t)__half_as_ushort(h1) << 16);
        L[i] = (uint32_t)__half_as_ushort(l0) | ((uint32_t)__half_as_ushort(l1) << 16);
    }
    *(uint4*)(sm + hi_off) = make_uint4(H[0], H[1], H[2], H[3]);
    *(uint4*)(sm + lo_off) = make_uint4(L[0], L[1], L[2], L[3]);
}

__device__ __forceinline__ void split2h(char* sm, uint32_t hi_off, uint32_t lo_off,
                                        float a, float b) {
    __half ha = __float2half_rn(a), hb = __float2half_rn(b);
    __half la = __float2half_rn(a - __half2float(ha));
    __half lb = __float2half_rn(b - __half2float(hb));
    *(uint32_t*)(sm + hi_off) = (uint32_t)__half_as_ushort(ha) | ((uint32_t)__half_as_ushort(hb) << 16);
    *(uint32_t*)(sm + lo_off) = (uint32_t)__half_as_ushort(la) | ((uint32_t)__half_as_ushort(lb) << 16);
}

// ===========================================================================
// Phase 1: recurrence via mma.sync fp16 (2-term split: Ah*B + Al*B).
// 512 threads = 16 warps. Warp: mrow = wid&1 (16 rows), jgrp = wid>>1
// (16 j-cols per gate, all 4 gates). In-register LSTM update; c-state
// resident in registers for all 100 steps. W_hh fp16 resident in smem,
// XOR-swizzled rows (256B row, ^(n&7)<<4).  (Unchanged structure from R14;
// activations now use __fdividef fast path.)
// ===========================================================================
#define RS_WH    0                        // [512][128] fp16 swz = 131072
#define RS_AHI   131072                   // [32][128] fp16 swz = 8192
#define RS_ALO   (RS_AHI + 8192)
#define RS_WIH   (RS_ALO + 8192)          // float4[512]: {w0,w1,w2,bias}
#define RS_XS    (RS_WIH + 8192)          // float4[2][32]
#define RS_HC    (RS_XS + 1024)           // fp32 h0/c0 scratch [2][32][128]
#define RS_TOTAL (RS_HC + 32768)          // 189440
// init-phase overlay inside RS_WH region:
#define RS_INITS 0                        // [32][268] fp32
#define RS_WT    34816                    // [64][129] fp32

__global__ void __launch_bounds__(512, 1)
recur_tc(const float* __restrict__ x,
         const float* __restrict__ init_pc,
         const float* __restrict__ init_hd,
         const float* __restrict__ W_state, const float* __restrict__ b_state,
         const float* __restrict__ W_cell,  const float* __restrict__ b_cell,
         const float* __restrict__ W_ih,    const float* __restrict__ W_hh,
         const float* __restrict__ b_ih,    const float* __restrict__ b_hh,
         float* __restrict__ out)
{
    extern __shared__ char smc[];
    const uint32_t sb = smem_u32(smc);
    const int tid  = threadIdx.x;
    const int wid  = tid >> 5;
    const int lane = tid & 31;
    const int mrow = wid & 1;
    const int jgrp = wid >> 1;            // 0..7, 16 j-cols each
    const int gb0  = blockIdx.x * 32;

    // ---------------- init: h0/c0 SIMT GEMM (K=268), runs once ----------------
    {
        float* initS = (float*)(smc + RS_INITS);
        float* wT    = (float*)(smc + RS_WT);
        float* hS    = (float*)(smc + RS_HC);
        float* cS    = hS + 32 * 128;

        for (int i = tid; i < 32 * KIN; i += 512) {
            int r = i / KIN, k = i - r * KIN;
            float v = (k < 256) ? init_pc[(size_t)(gb0 + r) * 256 + k]
                                : init_hd[(size_t)(gb0 + r) * 12 + (k - 256)];
            initS[r * KIN + k] = v;
        }
        __syncthreads();

        for (int p = 0; p < 2; ++p) {
            const float* W  = p ? W_cell : W_state;
            const float* bb = p ? b_cell : b_state;
            float acc[8];
            #pragma unroll
            for (int o = 0; o < 8; ++o) acc[o] = 0.0f;

            for (int kt = 0; kt < KIN; kt += 64) {
                int len = KIN - kt; if (len > 64) len = 64;
                for (int i = tid; i < 128 * 64; i += 512) {
                    int n = i >> 6, kk = i & 63;
                    if (kk < len) wT[kk * 129 + n] = W[n * KIN + kt + kk];
                }
                __syncthreads();
                for (int kk = 0; kk < len; ++kk) {
                    #pragma unroll
                    for (int o = 0; o < 8; ++o) {
                        int idx = o * 512 + tid;
                        int r = idx >> 7, n = idx & 127;
                        acc[o] += initS[r * KIN + kt + kk] * wT[kk * 129 + n];
                    }
                }
                __syncthreads();
            }
            float* dst = p ? cS : hS;
            #pragma unroll
            for (int o = 0; o < 8; ++o) {
                int idx = o * 512 + tid;
                int r = idx >> 7, n = idx & 127;
                dst[r * 128 + n] = acc[o] + bb[n];
            }
            __syncthreads();
        }
    }

    // ---------------- load W_hh fp16 (swizzled), wih+bias, x[0], h0 split ----
    for (int i = tid; i < 512 * 32; i += 512) {
        int row = i >> 5, q = i & 31;
        float4 w = *(const float4*)&W_hh[row * 128 + 4 * q];
        uint2 h4 = make_uint2(pack2h(w.x, w.y), pack2h(w.z, w.w));
        uint32_t off = ((uint32_t)(8 * q)) ^ (uint32_t)((row & 7) << 4);
        *(uint2*)(smc + RS_WH + row * 256 + off) = h4;
    }
    {
        int n = tid;   // exactly 512 threads, one row each
        ((float4*)(smc + RS_WIH))[n] =
            make_float4(W_ih[n * 3 + 0], W_ih[n * 3 + 1], W_ih[n * 3 + 2],
                        b_ih[n] + b_hh[n]);
    }
    if (tid < 96) {
        int r = tid / 3, c = tid - 3 * r;
        ((float*)(smc + RS_XS))[r * 4 + c] = x[((size_t)0 * BATCH + gb0 + r) * 3 + c];
    }
    {
        const float* hS = (const float*)(smc + RS_HC);
        int i = tid;   // 512 groups of 8, one each
        int row = i >> 4, c0 = (i & 15) * 8;
        uint32_t off = row * 256 + (((uint32_t)(c0 * 2)) ^ (uint32_t)((row & 7) << 4));
        split8h(smc, RS_AHI + off, RS_ALO + off, &hS[row * 128 + c0]);
    }

    // ---------------- per-lane constants ----------------
    const int r1  = 16 * mrow + (lane >> 2);       // epilogue rows r1, r1+8
    const int j0a = jgrp * 16 + 2 * (lane & 3);    // epilogue col base (+8b)

    const int aRowL = 16 * mrow + (lane & 15);
    const uint32_t aBaseH = sb + RS_AHI + aRowL * 256;
    const uint32_t aBaseL = sb + RS_ALO + aRowL * 256;
    const uint32_t aXor   = (uint32_t)((aRowL & 7) << 4);
    const uint32_t aSeg   = (uint32_t)((lane >> 4) * 16);
    const int m4 = lane >> 3;
    const int bRowOff = 8 * (m4 >> 1) + (lane & 7);
    const uint32_t bSeg = (uint32_t)((m4 & 1) * 16);
    uint32_t bBase[4], bXor[4];
    #pragma unroll
    for (int g = 0; g < 4; ++g) {
        int n = g * 128 + jgrp * 16 + bRowOff;
        bBase[g] = sb + RS_WH + n * 256;
        bXor[g]  = (uint32_t)((n & 7) << 4);
    }

    // c-state registers
    float cc[2][4];
    {
        const float* cS = (const float*)(smc + RS_HC) + 32 * 128;
        #pragma unroll
        for (int b = 0; b < 2; ++b) {
            int j0 = j0a + 8 * b;
            cc[b][0] = cS[r1 * 128 + j0];
            cc[b][1] = cS[r1 * 128 + j0 + 1];
            cc[b][2] = cS[(r1 + 8) * 128 + j0];
            cc[b][3] = cS[(r1 + 8) * 128 + j0 + 1];
        }
    }
    __syncthreads();

    // ---------------- time loop ----------------
    for (int t = 0; t < T_STEPS; ++t) {
        float acc[8][4];
        #pragma unroll
        for (int j = 0; j < 8; ++j)
            #pragma unroll
            for (int q = 0; q < 4; ++q) acc[j][q] = 0.0f;

        #pragma unroll
        for (int kc = 0; kc < 8; ++kc) {
            uint32_t ao = (uint32_t)(kc * 32) + aSeg;
            uint32_t aH[4], aL[4];
            LDSM_X4(aH, aBaseH + (ao ^ aXor));
            LDSM_X4(aL, aBaseL + (ao ^ aXor));
            uint32_t bo = (uint32_t)(kc * 32) + bSeg;
            #pragma unroll
            for (int g = 0; g < 4; ++g) {
                uint32_t bf[4];
                LDSM_X4(bf, bBase[g] + (bo ^ bXor[g]));
                int tau = g * 2;
                MMA_F16(acc[tau],     aH, bf[0], bf[1]);
                MMA_F16(acc[tau],     aL, bf[0], bf[1]);
                MMA_F16(acc[tau + 1], aH, bf[2], bf[3]);
                MMA_F16(acc[tau + 1], aL, bf[2], bf[3]);
            }
        }
        __syncthreads();    // all A reads done -> safe to overwrite A below

        // ---- in-register LSTM epilogue ----
        const float4* xs4 = (const float4*)(smc + RS_XS) + (t & 1) * 32;
        float4 xv1 = xs4[r1];
        float4 xv2 = xs4[r1 + 8];
        size_t row1 = (size_t)t * BATCH + gb0 + r1;
        size_t row2 = row1 + 8;

        #pragma unroll
        for (int b = 0; b < 2; ++b) {
            int j0 = j0a + 8 * b;
            float4 wq[4][2];
            #pragma unroll
            for (int g = 0; g < 4; ++g) {
                wq[g][0] = ((const float4*)(smc + RS_WIH))[g * 128 + j0];
                wq[g][1] = ((const float4*)(smc + RS_WIH))[g * 128 + j0 + 1];
            }
            float hv[4];
            #pragma unroll
            for (int q = 0; q < 4; ++q) {
                int cp = q & 1;
                float4 xv = (q >= 2) ? xv2 : xv1;
                float pre[4];
                #pragma unroll
                for (int g = 0; g < 4; ++g)
                    pre[g] = acc[g * 2 + b][q]
                           + xv.x * wq[g][cp].x + xv.y * wq[g][cp].y
                           + xv.z * wq[g][cp].z + wq[g][cp].w;
                float ig = fsig(pre[0]), fg = fsig(pre[1]);
                float gg = ftanh(pre[2]), og = fsig(pre[3]);
                float cn = fg * cc[b][q] + ig * gg;
                cc[b][q] = cn;
                hv[q] = og * ftanh(cn);
            }
            *(float2*)&out[HS_OFF + row1 * 128 + j0] = make_float2(hv[0], hv[1]);
            *(float2*)&out[HS_OFF + row2 * 128 + j0] = make_float2(hv[2], hv[3]);
            *(float2*)&out[CS_OFF + row1 * 128 + j0] = make_float2(cc[b][0], cc[b][1]);
            *(float2*)&out[CS_OFF + row2 * 128 + j0] = make_float2(cc[b][2], cc[b][3]);
            uint32_t o1 = r1 * 256 + (((uint32_t)(j0 * 2)) ^ (uint32_t)((r1 & 7) << 4));
            split2h(smc, RS_AHI + o1, RS_ALO + o1, hv[0], hv[1]);
            split2h(smc, RS_AHI + o1 + 2048, RS_ALO + o1 + 2048, hv[2], hv[3]);
        }
        if (t + 1 < T_STEPS && tid < 96) {
            int r = tid / 3, c = tid - 3 * r;
            ((float*)(smc + RS_XS))[((t + 1) & 1) * 128 + r * 4 + c] =
                x[((size_t)(t + 1) * BATCH + gb0 + r) * 3 + c];
        }
        __syncthreads();
    }
}

// ===========================================================================
// Phase 2: fused bn + pc + hd via mma.sync fp16, 1-TERM (A single fp16,
// weights single fp16). Halves MMA count and A-LDSM traffic vs R14
// (L1/MIO was the measured ceiling at 67%).
// ===========================================================================
#define MT 64
#define SA_STR  136   // fp16 elems/row -> 272 B (16 mod 128, conflict-free)
#define SW_STR  136
#define SBN_STR 264   // 528 B
#define SPC_STR 72    // 144 B
#define SHD_STR 264

#define P_A     0u
#define P_WBN   (P_A + MT*SA_STR*2)        // 17408
#define P_WHD   (P_WBN + 256*SW_STR*2)     // 87040
#define SMEM_PH2 (P_WHD + 16*SHD_STR*2)    // 95488

// stage-B overlay (A / W_bn regions dead after stage A)
#define P_BN    0u
#define P_WPC   (P_BN + MT*SBN_STR*2)      // 33792 .. 70656 (W_hd untouched)

__global__ void __launch_bounds__(256, 2)
phase2_kernel(const float* __restrict__ W_bn,
              const float* __restrict__ W_pc, const float* __restrict__ b_pc,
              const float* __restrict__ W_hd, const float* __restrict__ b_hd,
              float* __restrict__ out)
{
    extern __shared__ char smc[];
    const uint32_t sb = smem_u32(smc);
    const int tid  = threadIdx.x;
    const int wid  = tid >> 5;
    const int lane = tid & 31;
    const int mw   = wid & 3;
    const int nh   = wid >> 2;
    const int rowA = 16 * mw;
    const size_t grow = (size_t)blockIdx.x * MT;

    const int aRow    = lane & 15;
    const int aSeg    = (lane >> 4) * 16;
    const int m4      = lane >> 3;
    const int bRowOff = 8 * (m4 >> 1) + (lane & 7);
    const int bColOff = 8 * (m4 & 1);

    // ---- prologue: A, W_bn, W_hd single fp16 ----
    {
        uint4 z = make_uint4(0, 0, 0, 0);
        for (int i = tid; i < (16 * SHD_STR * 2) / 16; i += 256)
            ((uint4*)(smc + P_WHD))[i] = z;
    }
    for (int b = tid; b < MT * 16; b += 256) {
        int r = b >> 4, c0 = (b & 15) << 3;
        float v[8];
        const float* s = out + HS_OFF + (grow + r) * 128 + c0;
        *(float4*)&v[0] = *(const float4*)s;
        *(float4*)&v[4] = *(const float4*)(s + 4);
        pack8h_store(smc, P_A + r * SA_STR * 2 + c0 * 2, v);
    }
    for (int b = tid; b < 256 * 16; b += 256) {
        int r = b >> 4, c0 = (b & 15) << 3;
        float v[8];
        const float* s = W_bn + (size_t)r * 128 + c0;
        *(float4*)&v[0] = *(const float4*)s;
        *(float4*)&v[4] = *(const float4*)(s + 4);
        pack8h_store(smc, P_WBN + r * SW_STR * 2 + c0 * 2, v);
    }
    __syncthreads();   // W_hd zero done before row writes
    for (int b = tid; b < 12 * 32; b += 256) {
        int r = b >> 5, c0 = (b & 31) << 3;
        float v[8];
        const float* s = W_hd + (size_t)r * 256 + c0;
        *(float4*)&v[0] = *(const float4*)s;
        *(float4*)&v[4] = *(const float4*)(s + 4);
        pack8h_store(smc, P_WHD + r * SHD_STR * 2 + c0 * 2, v);
    }
    __syncthreads();

    float acc[16][4];
    #pragma unroll
    for (int j = 0; j < 16; ++j)
        #pragma unroll
        for (int q = 0; q < 4; ++q) acc[j][q] = 0.0f;

    // ---- stage A: D[MT,256] = HS @ W_bn^T  (K=128, 8 chunks, 1-term) ----
    for (int kc = 0; kc < 8; ++kc) {
        int k0 = kc * 16;
        uint32_t aF[4];
        LDSM_X4(aF, sb + P_A + (rowA + aRow) * SA_STR * 2 + k0 * 2 + aSeg);
        #pragma unroll
        for (int j = 0; j < 16; j += 2) {
            uint32_t adB = sb + P_WBN + (nh * 128 + 8 * j + bRowOff) * SW_STR * 2
                         + (k0 + bColOff) * 2;
            uint32_t bf[4];
            LDSM_X4(bf, adB);
            MMA_F16(acc[j],   aF, bf[0], bf[1]);
            MMA_F16(acc[j+1], aF, bf[2], bf[3]);
        }
    }
    __syncthreads();   // all A/W_bn reads done -> overlay safe

    // ---- stage A epilogue: tanh -> bn gmem + fp16 bn smem ----
    {
        int rl = rowA + (lane >> 2);
        #pragma unroll
        for (int j = 0; j < 16; ++j) {
            int c = nh * 128 + 8 * j + 2 * (lane & 3);
            float v00 = ftanh(acc[j][0]), v01 = ftanh(acc[j][1]);
            float v10 = ftanh(acc[j][2]), v11 = ftanh(acc[j][3]);
            *(float2*)&out[BN_OFF + (grow + rl) * 256 + c]     = make_float2(v00, v01);
            *(float2*)&out[BN_OFF + (grow + rl + 8) * 256 + c] = make_float2(v10, v11);
            *(uint32_t*)(smc + P_BN + rl * SBN_STR * 2 + c * 2)       = pack2h(v00, v01);
            *(uint32_t*)(smc + P_BN + (rl + 8) * SBN_STR * 2 + c * 2) = pack2h(v10, v11);
        }
    }
    __syncthreads();   // bn smem tile complete

    // ---- stage B part 1: hd accum (nh==0 warps), W_hd resident ----
    float ahd[2][4];
    #pragma unroll
    for (int j = 0; j < 2; ++j)
        #pragma unroll
        for (int q = 0; q < 4; ++q) ahd[j][q] = 0.0f;

    if (nh == 0) {
        for (int kc = 0; kc < 16; ++kc) {
            int k0 = kc * 16;
            uint32_t aF[4];
            LDSM_X4(aF, sb + P_BN + (rowA + aRow) * SBN_STR * 2 + k0 * 2 + aSeg);
            uint32_t adB = sb + P_WHD + bRowOff * SHD_STR * 2 + (k0 + bColOff) * 2;
            uint32_t bf[4];
            LDSM_X4(bf, adB);
            MMA_F16(ahd[0], aF, bf[0], bf[1]);
            MMA_F16(ahd[1], aF, bf[2], bf[3]);
        }
    }

    // ---- stage B part 2: pc = bn @ W_pc^T (K=256, stream 4 chunks of 64) ----
    #pragma unroll
    for (int j = 0; j < 16; ++j)
        #pragma unroll
        for (int q = 0; q < 4; ++q) acc[j][q] = 0.0f;

    for (int kc2 = 0; kc2 < 4; ++kc2) {
        __syncthreads();   // previous chunk's ldmatrix reads complete
        for (int b = tid; b < 256 * 8; b += 256) {
            int r = b >> 3, c0 = (b & 7) << 3;
            float v[8];
            const float* s = W_pc + (size_t)r * 256 + kc2 * 64 + c0;
            *(float4*)&v[0] = *(const float4*)s;
            *(float4*)&v[4] = *(const float4*)(s + 4);
            pack8h_store(smc, P_WPC + r * SPC_STR * 2 + c0 * 2, v);
        }
        __syncthreads();
        for (int kc = 0; kc < 4; ++kc) {
            int kk = kc2 * 64 + kc * 16;
            uint32_t aF[4];
            LDSM_X4(aF, sb + P_BN + (rowA + aRow) * SBN_STR * 2 + kk * 2 + aSeg);
            #pragma unroll
            for (int j = 0; j < 16; j += 2) {
                uint32_t adB = sb + P_WPC + (nh * 128 + 8 * j + bRowOff) * SPC_STR * 2
                             + (kc * 16 + bColOff) * 2;
                uint32_t bf[4];
                LDSM_X4(bf, adB);
                MMA_F16(acc[j],   aF, bf[0], bf[1]);
                MMA_F16(acc[j+1], aF, bf[2], bf[3]);
            }
        }
    }

    // ---- pc epilogue ----
    {
        int rl = rowA + (lane >> 2);
        #pragma unroll
        for (int j = 0; j < 16; ++j) {
            int c = nh * 128 + 8 * j + 2 * (lane & 3);
            float b0 = __ldg(&b_pc[c]), b1 = __ldg(&b_pc[c + 1]);
            float2* o0 = (float2*)&out[PC_OFF + (grow + rl) * 256 + c];
            float2* o1 = (float2*)&out[PC_OFF + (grow + rl + 8) * 256 + c];
            *o0 = make_float2(acc[j][0] + b0, acc[j][1] + b1);
            *o1 = make_float2(acc[j][2] + b0, acc[j][3] + b1);
        }
    }

    // ---- hd epilogue (nh==0 warps, cols 0..11 valid) ----
    if (nh == 0) {
        int rl = rowA + (lane >> 2);
        #pragma unroll
        for (int j = 0; j < 2; ++j) {
            int cb = 8 * j + 2 * (lane & 3);
            float* o0 = out + HD_OFF + (grow + rl) * 12;
            float* o1 = out + HD_OFF + (grow + rl + 8) * 12;
            if (cb < 12) {
                float bb = __ldg(&b_hd[cb]);
                o0[cb] = ahd[j][0] + bb;
                o1[cb] = ahd[j][2] + bb;
            }
            if (cb + 1 < 12) {
                float bb = __ldg(&b_hd[cb + 1]);
                o0[cb + 1] = ahd[j][1] + bb;
                o1[cb + 1] = ahd[j][3] + bb;
            }
        }
    }
}

// ===========================================================================
extern "C" void kernel_launch(void* const* d_in, const int* in_sizes, int n_in,
                              void* d_out, int out_size)
{
    const float* x       = (const float*)d_in[0];
    const float* init_pc = (const float*)d_in[1];
    const float* init_hd = (const float*)d_in[2];
    const float* W_state = (const float*)d_in[3];
    const float* b_state = (const float*)d_in[4];
    const float* W_cell  = (const float*)d_in[5];
    const float* b_cell  = (const float*)d_in[6];
    const float* W_ih    = (const float*)d_in[7];
    const float* W_hh    = (const float*)d_in[8];
    const float* b_ih    = (const float*)d_in[9];
    const float* b_hh    = (const float*)d_in[10];
    const float* W_bn    = (const float*)d_in[11];
    const float* W_pc    = (const float*)d_in[12];
    const float* b_pc    = (const float*)d_in[13];
    const float* W_hd    = (const float*)d_in[14];
    const float* b_hd    = (const float*)d_in[15];
    float* out = (float*)d_out;

    cudaFuncSetAttribute(recur_tc,      cudaFuncAttributeMaxDynamicSharedMemorySize, (int)RS_TOTAL);
    cudaFuncSetAttribute(phase2_kernel, cudaFuncAttributeMaxDynamicSharedMemorySize, (int)SMEM_PH2);

    recur_tc<<<BATCH / 32, 512, RS_TOTAL>>>(x, init_pc, init_hd,
                                            W_state, b_state, W_cell, b_cell,
                                            W_ih, W_hh, b_ih, b_hh, out);
    phase2_kernel<<<(T_STEPS * BATCH) / MT, 256, SMEM_PH2>>>(
        W_bn, W_pc, b_pc, W_hd, b_hd, out);
}

// round 16
// speedup vs baseline: 3.9739x; 1.0443x over previous
#include <cuda_runtime.h>
#include <cuda_bf16.h>
#include <cuda_fp16.h>
#include <math.h>
#include <stdint.h>

// Problem constants
#define T_STEPS 100
#define BATCH   4096
#define NH      128
#define NG      512
#define NPC     256
#define NHD     12
#define NB      256
#define KIN     268   // NPC + NHD

// Output layout: tuple (hd, pc, bn, hs, cs) flattened in order
#define HD_OFF  ((size_t)0)
#define PC_OFF  ((size_t)T_STEPS * BATCH * NHD)
#define BN_OFF  (PC_OFF + (size_t)T_STEPS * BATCH * NPC)
#define HS_OFF  (BN_OFF + (size_t)T_STEPS * BATCH * NB)
#define CS_OFF  (HS_OFF + (size_t)T_STEPS * BATCH * NH)

__device__ __forceinline__ uint32_t smem_u32(const void* p) {
    uint32_t a;
    asm("{ .reg .u64 t; cvta.to.shared.u64 t, %1; cvt.u32.u64 %0, t; }"
        : "=r"(a) : "l"(p));
    return a;
}

// ---- base-PTX tensor ops (compile for compute_103, no 'a' features) ----
#define LDSM_X4(R, addr) \
    asm volatile("ldmatrix.sync.aligned.m8n8.x4.shared.b16 {%0,%1,%2,%3}, [%4];" \
        : "=r"((R)[0]), "=r"((R)[1]), "=r"((R)[2]), "=r"((R)[3]) : "r"(addr))

#define MMA_F16(D, A, b0, b1) \
    asm volatile("mma.sync.aligned.m16n8k16.row.col.f32.f16.f16.f32 " \
        "{%0,%1,%2,%3}, {%4,%5,%6,%7}, {%8,%9}, {%0,%1,%2,%3};" \
        : "+f"((D)[0]), "+f"((D)[1]), "+f"((D)[2]), "+f"((D)[3]) \
        : "r"((A)[0]), "r"((A)[1]), "r"((A)[2]), "r"((A)[3]), "r"(b0), "r"(b1))

// fast activations: __expf + __fdividef only (~1e-6 accuracy, safe at +-inf)
__device__ __forceinline__ float fsig(float v)  {
    float e = __expf(-v);
    return __fdividef(1.0f, 1.0f + e);
}
__device__ __forceinline__ float ftanh(float v) {
    float e = __expf(2.0f * v);
    return 1.0f - __fdividef(2.0f, e + 1.0f);
}

// ---- fp16 pack / hi-lo split helpers ----
__device__ __forceinline__ uint32_t pack2h(float a, float b) {
    return (uint32_t)__half_as_ushort(__float2half_rn(a))
         | ((uint32_t)__half_as_ushort(__float2half_rn(b)) << 16);
}

__device__ __forceinline__ void pack8h_store(char* sm, uint32_t off, const float* v) {
    *(uint4*)(sm + off) = make_uint4(pack2h(v[0], v[1]), pack2h(v[2], v[3]),
                                     pack2h(v[4], v[5]), pack2h(v[6], v[7]));
}

__device__ __forceinline__ void split8h(char* sm, uint32_t hi_off, uint32_t lo_off,
                                        const float* v) {
    uint32_t H[4], L[4];
    #pragma unroll
    for (int i = 0; i < 4; ++i) {
        __half h0 = __float2half_rn(v[2 * i]);
        __half h1 = __float2half_rn(v[2 * i + 1]);
        __half l0 = __float2half_rn(v[2 * i]     - __half2float(h0));
        __half l1 = __float2half_rn(v[2 * i + 1] - __half2float(h1));
        H[i] = (uint32_t)__half_as_ushort(h0) | ((uint32_t)__half_as_ushort(h1) << 16);
        L[i] = (uint32_t)__half_as_ushort(l0) | ((uint32_t)__half_as_ushort(l1) << 16);
    }
    *(uint4*)(sm + hi_off) = make_uint4(H[0], H[1], H[2], H[3]);
    *(uint4*)(sm + lo_off) = make_uint4(L[0], L[1], L[2], L[3]);
}

__device__ __forceinline__ void split2h(char* sm, uint32_t hi_off, uint32_t lo_off,
                                        float a, float b) {
    __half ha = __float2half_rn(a), hb = __float2half_rn(b);
    __half la = __float2half_rn(a - __half2float(ha));
    __half lb = __float2half_rn(b - __half2float(hb));
    *(uint32_t*)(sm + hi_off) = (uint32_t)__half_as_ushort(ha) | ((uint32_t)__half_as_ushort(hb) << 16);
    *(uint32_t*)(sm + lo_off) = (uint32_t)__half_as_ushort(la) | ((uint32_t)__half_as_ushort(lb) << 16);
}

// ===========================================================================
// Phase 1: recurrence via mma.sync fp16 (2-term split). Unchanged from R15.
// ===========================================================================
#define RS_WH    0                        // [512][128] fp16 swz = 131072
#define RS_AHI   131072                   // [32][128] fp16 swz = 8192
#define RS_ALO   (RS_AHI + 8192)
#define RS_WIH   (RS_ALO + 8192)          // float4[512]: {w0,w1,w2,bias}
#define RS_XS    (RS_WIH + 8192)          // float4[2][32]
#define RS_HC    (RS_XS + 1024)           // fp32 h0/c0 scratch [2][32][128]
#define RS_TOTAL (RS_HC + 32768)          // 189440
// init-phase overlay inside RS_WH region:
#define RS_INITS 0                        // [32][268] fp32
#define RS_WT    34816                    // [64][129] fp32

__global__ void __launch_bounds__(512, 1)
recur_tc(const float* __restrict__ x,
         const float* __restrict__ init_pc,
         const float* __restrict__ init_hd,
         const float* __restrict__ W_state, const float* __restrict__ b_state,
         const float* __restrict__ W_cell,  const float* __restrict__ b_cell,
         const float* __restrict__ W_ih,    const float* __restrict__ W_hh,
         const float* __restrict__ b_ih,    const float* __restrict__ b_hh,
         float* __restrict__ out)
{
    extern __shared__ char smc[];
    const uint32_t sb = smem_u32(smc);
    const int tid  = threadIdx.x;
    const int wid  = tid >> 5;
    const int lane = tid & 31;
    const int mrow = wid & 1;
    const int jgrp = wid >> 1;            // 0..7, 16 j-cols each
    const int gb0  = blockIdx.x * 32;

    // ---------------- init: h0/c0 SIMT GEMM (K=268), runs once ----------------
    {
        float* initS = (float*)(smc + RS_INITS);
        float* wT    = (float*)(smc + RS_WT);
        float* hS    = (float*)(smc + RS_HC);
        float* cS    = hS + 32 * 128;

        for (int i = tid; i < 32 * KIN; i += 512) {
            int r = i / KIN, k = i - r * KIN;
            float v = (k < 256) ? init_pc[(size_t)(gb0 + r) * 256 + k]
                                : init_hd[(size_t)(gb0 + r) * 12 + (k - 256)];
            initS[r * KIN + k] = v;
        }
        __syncthreads();

        for (int p = 0; p < 2; ++p) {
            const float* W  = p ? W_cell : W_state;
            const float* bb = p ? b_cell : b_state;
            float acc[8];
            #pragma unroll
            for (int o = 0; o < 8; ++o) acc[o] = 0.0f;

            for (int kt = 0; kt < KIN; kt += 64) {
                int len = KIN - kt; if (len > 64) len = 64;
                for (int i = tid; i < 128 * 64; i += 512) {
                    int n = i >> 6, kk = i & 63;
                    if (kk < len) wT[kk * 129 + n] = W[n * KIN + kt + kk];
                }
                __syncthreads();
                for (int kk = 0; kk < len; ++kk) {
                    #pragma unroll
                    for (int o = 0; o < 8; ++o) {
                        int idx = o * 512 + tid;
                        int r = idx >> 7, n = idx & 127;
                        acc[o] += initS[r * KIN + kt + kk] * wT[kk * 129 + n];
                    }
                }
                __syncthreads();
            }
            float* dst = p ? cS : hS;
            #pragma unroll
            for (int o = 0; o < 8; ++o) {
                int idx = o * 512 + tid;
                int r = idx >> 7, n = idx & 127;
                dst[r * 128 + n] = acc[o] + bb[n];
            }
            __syncthreads();
        }
    }

    // ---------------- load W_hh fp16 (swizzled), wih+bias, x[0], h0 split ----
    for (int i = tid; i < 512 * 32; i += 512) {
        int row = i >> 5, q = i & 31;
        float4 w = *(const float4*)&W_hh[row * 128 + 4 * q];
        uint2 h4 = make_uint2(pack2h(w.x, w.y), pack2h(w.z, w.w));
        uint32_t off = ((uint32_t)(8 * q)) ^ (uint32_t)((row & 7) << 4);
        *(uint2*)(smc + RS_WH + row * 256 + off) = h4;
    }
    {
        int n = tid;   // exactly 512 threads, one row each
        ((float4*)(smc + RS_WIH))[n] =
            make_float4(W_ih[n * 3 + 0], W_ih[n * 3 + 1], W_ih[n * 3 + 2],
                        b_ih[n] + b_hh[n]);
    }
    if (tid < 96) {
        int r = tid / 3, c = tid - 3 * r;
        ((float*)(smc + RS_XS))[r * 4 + c] = x[((size_t)0 * BATCH + gb0 + r) * 3 + c];
    }
    {
        const float* hS = (const float*)(smc + RS_HC);
        int i = tid;   // 512 groups of 8, one each
        int row = i >> 4, c0 = (i & 15) * 8;
        uint32_t off = row * 256 + (((uint32_t)(c0 * 2)) ^ (uint32_t)((row & 7) << 4));
        split8h(smc, RS_AHI + off, RS_ALO + off, &hS[row * 128 + c0]);
    }

    // ---------------- per-lane constants ----------------
    const int r1  = 16 * mrow + (lane >> 2);       // epilogue rows r1, r1+8
    const int j0a = jgrp * 16 + 2 * (lane & 3);    // epilogue col base (+8b)

    const int aRowL = 16 * mrow + (lane & 15);
    const uint32_t aBaseH = sb + RS_AHI + aRowL * 256;
    const uint32_t aBaseL = sb + RS_ALO + aRowL * 256;
    const uint32_t aXor   = (uint32_t)((aRowL & 7) << 4);
    const uint32_t aSeg   = (uint32_t)((lane >> 4) * 16);
    const int m4 = lane >> 3;
    const int bRowOff = 8 * (m4 >> 1) + (lane & 7);
    const uint32_t bSeg = (uint32_t)((m4 & 1) * 16);
    uint32_t bBase[4], bXor[4];
    #pragma unroll
    for (int g = 0; g < 4; ++g) {
        int n = g * 128 + jgrp * 16 + bRowOff;
        bBase[g] = sb + RS_WH + n * 256;
        bXor[g]  = (uint32_t)((n & 7) << 4);
    }

    // c-state registers
    float cc[2][4];
    {
        const float* cS = (const float*)(smc + RS_HC) + 32 * 128;
        #pragma unroll
        for (int b = 0; b < 2; ++b) {
            int j0 = j0a + 8 * b;
            cc[b][0] = cS[r1 * 128 + j0];
            cc[b][1] = cS[r1 * 128 + j0 + 1];
            cc[b][2] = cS[(r1 + 8) * 128 + j0];
            cc[b][3] = cS[(r1 + 8) * 128 + j0 + 1];
        }
    }
    __syncthreads();

    // ---------------- time loop ----------------
    for (int t = 0; t < T_STEPS; ++t) {
        float acc[8][4];
        #pragma unroll
        for (int j = 0; j < 8; ++j)
            #pragma unroll
            for (int q = 0; q < 4; ++q) acc[j][q] = 0.0f;

        #pragma unroll
        for (int kc = 0; kc < 8; ++kc) {
            uint32_t ao = (uint32_t)(kc * 32) + aSeg;
            uint32_t aH[4], aL[4];
            LDSM_X4(aH, aBaseH + (ao ^ aXor));
            LDSM_X4(aL, aBaseL + (ao ^ aXor));
            uint32_t bo = (uint32_t)(kc * 32) + bSeg;
            #pragma unroll
            for (int g = 0; g < 4; ++g) {
                uint32_t bf[4];
                LDSM_X4(bf, bBase[g] + (bo ^ bXor[g]));
                int tau = g * 2;
                MMA_F16(acc[tau],     aH, bf[0], bf[1]);
                MMA_F16(acc[tau],     aL, bf[0], bf[1]);
                MMA_F16(acc[tau + 1], aH, bf[2], bf[3]);
                MMA_F16(acc[tau + 1], aL, bf[2], bf[3]);
            }
        }
        __syncthreads();    // all A reads done -> safe to overwrite A below

        // ---- in-register LSTM epilogue ----
        const float4* xs4 = (const float4*)(smc + RS_XS) + (t & 1) * 32;
        float4 xv1 = xs4[r1];
        float4 xv2 = xs4[r1 + 8];
        size_t row1 = (size_t)t * BATCH + gb0 + r1;
        size_t row2 = row1 + 8;

        #pragma unroll
        for (int b = 0; b < 2; ++b) {
            int j0 = j0a + 8 * b;
            float4 wq[4][2];
            #pragma unroll
            for (int g = 0; g < 4; ++g) {
                wq[g][0] = ((const float4*)(smc + RS_WIH))[g * 128 + j0];
                wq[g][1] = ((const float4*)(smc + RS_WIH))[g * 128 + j0 + 1];
            }
            float hv[4];
            #pragma unroll
            for (int q = 0; q < 4; ++q) {
                int cp = q & 1;
                float4 xv = (q >= 2) ? xv2 : xv1;
                float pre[4];
                #pragma unroll
                for (int g = 0; g < 4; ++g)
                    pre[g] = acc[g * 2 + b][q]
                           + xv.x * wq[g][cp].x + xv.y * wq[g][cp].y
                           + xv.z * wq[g][cp].z + wq[g][cp].w;
                float ig = fsig(pre[0]), fg = fsig(pre[1]);
                float gg = ftanh(pre[2]), og = fsig(pre[3]);
                float cn = fg * cc[b][q] + ig * gg;
                cc[b][q] = cn;
                hv[q] = og * ftanh(cn);
            }
            *(float2*)&out[HS_OFF + row1 * 128 + j0] = make_float2(hv[0], hv[1]);
            *(float2*)&out[HS_OFF + row2 * 128 + j0] = make_float2(hv[2], hv[3]);
            *(float2*)&out[CS_OFF + row1 * 128 + j0] = make_float2(cc[b][0], cc[b][1]);
            *(float2*)&out[CS_OFF + row2 * 128 + j0] = make_float2(cc[b][2], cc[b][3]);
            uint32_t o1 = r1 * 256 + (((uint32_t)(j0 * 2)) ^ (uint32_t)((r1 & 7) << 4));
            split2h(smc, RS_AHI + o1, RS_ALO + o1, hv[0], hv[1]);
            split2h(smc, RS_AHI + o1 + 2048, RS_ALO + o1 + 2048, hv[2], hv[3]);
        }
        if (t + 1 < T_STEPS && tid < 96) {
            int r = tid / 3, c = tid - 3 * r;
            ((float*)(smc + RS_XS))[((t + 1) & 1) * 128 + r * 4 + c] =
                x[((size_t)(t + 1) * BATCH + gb0 + r) * 3 + c];
        }
        __syncthreads();
    }
}

// ===========================================================================
// Phase 2: fused bn + pc + hd via mma.sync fp16, 1-term.
// R16: warp tile rebalanced 16x128 -> 32x64 (mw = wid&1 row group of 32,
// nh = wid>>1 col group of 64). Per K16 chunk: 2 A-LDSM + 4 B-LDSM for
// 16 MMAs (was 1+8) -> 33% LDSM traffic cut (L1 was the 70% ceiling).
// ===========================================================================
#define MT 64
#define SA_STR  136   // fp16 elems/row -> 272 B (16 mod 128, conflict-free)
#define SW_STR  136
#define SBN_STR 264   // 528 B
#define SPC_STR 72    // 144 B
#define SHD_STR 264

#define P_A     0u
#define P_WBN   (P_A + MT*SA_STR*2)        // 17408
#define P_WHD   (P_WBN + 256*SW_STR*2)     // 87040
#define SMEM_PH2 (P_WHD + 16*SHD_STR*2)    // 95488

// stage-B overlay (A / W_bn regions dead after stage A)
#define P_BN    0u
#define P_WPC   (P_BN + MT*SBN_STR*2)      // 33792 .. 70656 (W_hd untouched)

__global__ void __launch_bounds__(256, 2)
phase2_kernel(const float* __restrict__ W_bn,
              const float* __restrict__ W_pc, const float* __restrict__ b_pc,
              const float* __restrict__ W_hd, const float* __restrict__ b_hd,
              float* __restrict__ out)
{
    extern __shared__ char smc[];
    const uint32_t sb = smem_u32(smc);
    const int tid  = threadIdx.x;
    const int wid  = tid >> 5;
    const int lane = tid & 31;
    const int mw   = wid & 1;          // row group (32 rows)
    const int nh   = wid >> 1;         // col group (64 cols)
    const int rowA = 32 * mw;
    const size_t grow = (size_t)blockIdx.x * MT;

    const int aRow    = lane & 15;
    const int aSeg    = (lane >> 4) * 16;
    const int m4      = lane >> 3;
    const int bRowOff = 8 * (m4 >> 1) + (lane & 7);
    const int bColOff = 8 * (m4 & 1);

    // ---- prologue: A, W_bn, W_hd single fp16 ----
    {
        uint4 z = make_uint4(0, 0, 0, 0);
        for (int i = tid; i < (16 * SHD_STR * 2) / 16; i += 256)
            ((uint4*)(smc + P_WHD))[i] = z;
    }
    for (int b = tid; b < MT * 16; b += 256) {
        int r = b >> 4, c0 = (b & 15) << 3;
        float v[8];
        const float* s = out + HS_OFF + (grow + r) * 128 + c0;
        *(float4*)&v[0] = *(const float4*)s;
        *(float4*)&v[4] = *(const float4*)(s + 4);
        pack8h_store(smc, P_A + r * SA_STR * 2 + c0 * 2, v);
    }
    for (int b = tid; b < 256 * 16; b += 256) {
        int r = b >> 4, c0 = (b & 15) << 3;
        float v[8];
        const float* s = W_bn + (size_t)r * 128 + c0;
        *(float4*)&v[0] = *(const float4*)s;
        *(float4*)&v[4] = *(const float4*)(s + 4);
        pack8h_store(smc, P_WBN + r * SW_STR * 2 + c0 * 2, v);
    }
    __syncthreads();   // W_hd zero done before row writes
    for (int b = tid; b < 12 * 32; b += 256) {
        int r = b >> 5, c0 = (b & 31) << 3;
        float v[8];
        const float* s = W_hd + (size_t)r * 256 + c0;
        *(float4*)&v[0] = *(const float4*)s;
        *(float4*)&v[4] = *(const float4*)(s + 4);
        pack8h_store(smc, P_WHD + r * SHD_STR * 2 + c0 * 2, v);
    }
    __syncthreads();

    float acc[2][8][4];
    #pragma unroll
    for (int m = 0; m < 2; ++m)
        #pragma unroll
        for (int j = 0; j < 8; ++j)
            #pragma unroll
            for (int q = 0; q < 4; ++q) acc[m][j][q] = 0.0f;

    // ---- stage A: D[MT,256] = HS @ W_bn^T  (K=128, 8 chunks) ----
    for (int kc = 0; kc < 8; ++kc) {
        int k0 = kc * 16;
        uint32_t aF0[4], aF1[4];
        LDSM_X4(aF0, sb + P_A + (rowA + aRow) * SA_STR * 2 + k0 * 2 + aSeg);
        LDSM_X4(aF1, sb + P_A + (rowA + 16 + aRow) * SA_STR * 2 + k0 * 2 + aSeg);
        #pragma unroll
        for (int jp = 0; jp < 4; ++jp) {
            uint32_t adB = sb + P_WBN + (nh * 64 + 16 * jp + bRowOff) * SW_STR * 2
                         + (k0 + bColOff) * 2;
            uint32_t bf[4];
            LDSM_X4(bf, adB);
            MMA_F16(acc[0][2*jp],   aF0, bf[0], bf[1]);
            MMA_F16(acc[0][2*jp+1], aF0, bf[2], bf[3]);
            MMA_F16(acc[1][2*jp],   aF1, bf[0], bf[1]);
            MMA_F16(acc[1][2*jp+1], aF1, bf[2], bf[3]);
        }
    }
    __syncthreads();   // all A/W_bn reads done -> overlay safe

    // ---- stage A epilogue: tanh -> bn gmem + fp16 bn smem ----
    {
        int rl0 = rowA + (lane >> 2);
        #pragma unroll
        for (int m = 0; m < 2; ++m) {
            int rl = rl0 + 16 * m;
            #pragma unroll
            for (int j = 0; j < 8; ++j) {
                int c = nh * 64 + 8 * j + 2 * (lane & 3);
                float v00 = ftanh(acc[m][j][0]), v01 = ftanh(acc[m][j][1]);
                float v10 = ftanh(acc[m][j][2]), v11 = ftanh(acc[m][j][3]);
                *(float2*)&out[BN_OFF + (grow + rl) * 256 + c]     = make_float2(v00, v01);
                *(float2*)&out[BN_OFF + (grow + rl + 8) * 256 + c] = make_float2(v10, v11);
                *(uint32_t*)(smc + P_BN + rl * SBN_STR * 2 + c * 2)       = pack2h(v00, v01);
                *(uint32_t*)(smc + P_BN + (rl + 8) * SBN_STR * 2 + c * 2) = pack2h(v10, v11);
            }
        }
    }
    __syncthreads();   // bn smem tile complete

    // ---- stage B part 1: hd accum (nh==0 warps: mw 0/1 cover all 64 rows) --
    float ahd[2][2][4];
    #pragma unroll
    for (int m = 0; m < 2; ++m)
        #pragma unroll
        for (int j = 0; j < 2; ++j)
            #pragma unroll
            for (int q = 0; q < 4; ++q) ahd[m][j][q] = 0.0f;

    if (nh == 0) {
        for (int kc = 0; kc < 16; ++kc) {
            int k0 = kc * 16;
            uint32_t aF0[4], aF1[4];
            LDSM_X4(aF0, sb + P_BN + (rowA + aRow) * SBN_STR * 2 + k0 * 2 + aSeg);
            LDSM_X4(aF1, sb + P_BN + (rowA + 16 + aRow) * SBN_STR * 2 + k0 * 2 + aSeg);
            uint32_t adB = sb + P_WHD + bRowOff * SHD_STR * 2 + (k0 + bColOff) * 2;
            uint32_t bf[4];
            LDSM_X4(bf, adB);
            MMA_F16(ahd[0][0], aF0, bf[0], bf[1]);
            MMA_F16(ahd[0][1], aF0, bf[2], bf[3]);
            MMA_F16(ahd[1][0], aF1, bf[0], bf[1]);
            MMA_F16(ahd[1][1], aF1, bf[2], bf[3]);
        }
    }

    // ---- stage B part 2: pc = bn @ W_pc^T (K=256, stream 4 chunks of 64) ----
    #pragma unroll
    for (int m = 0; m < 2; ++m)
        #pragma unroll
        for (int j = 0; j < 8; ++j)
            #pragma unroll
            for (int q = 0; q < 4; ++q) acc[m][j][q] = 0.0f;

    for (int kc2 = 0; kc2 < 4; ++kc2) {
        __syncthreads();   // previous chunk's ldmatrix reads complete
        for (int b = tid; b < 256 * 8; b += 256) {
            int r = b >> 3, c0 = (b & 7) << 3;
            float v[8];
            const float* s = W_pc + (size_t)r * 256 + kc2 * 64 + c0;
            *(float4*)&v[0] = *(const float4*)s;
            *(float4*)&v[4] = *(const float4*)(s + 4);
            pack8h_store(smc, P_WPC + r * SPC_STR * 2 + c0 * 2, v);
        }
        __syncthreads();
        for (int kc = 0; kc < 4; ++kc) {
            int kk = kc2 * 64 + kc * 16;
            uint32_t aF0[4], aF1[4];
            LDSM_X4(aF0, sb + P_BN + (rowA + aRow) * SBN_STR * 2 + kk * 2 + aSeg);
            LDSM_X4(aF1, sb + P_BN + (rowA + 16 + aRow) * SBN_STR * 2 + kk * 2 + aSeg);
            #pragma unroll
            for (int jp = 0; jp < 4; ++jp) {
                uint32_t adB = sb + P_WPC + (nh * 64 + 16 * jp + bRowOff) * SPC_STR * 2
                             + (kc * 16 + bColOff) * 2;
                uint32_t bf[4];
                LDSM_X4(bf, adB);
                MMA_F16(acc[0][2*jp],   aF0, bf[0], bf[1]);
                MMA_F16(acc[0][2*jp+1], aF0, bf[2], bf[3]);
                MMA_F16(acc[1][2*jp],   aF1, bf[0], bf[1]);
                MMA_F16(acc[1][2*jp+1], aF1, bf[2], bf[3]);
            }
        }
    }

    // ---- pc epilogue ----
    {
        int rl0 = rowA + (lane >> 2);
        #pragma unroll
        for (int m = 0; m < 2; ++m) {
            int rl = rl0 + 16 * m;
            #pragma unroll
            for (int j = 0; j < 8; ++j) {
                int c = nh * 64 + 8 * j + 2 * (lane & 3);
                float b0 = __ldg(&b_pc[c]), b1 = __ldg(&b_pc[c + 1]);
                float2* o0 = (float2*)&out[PC_OFF + (grow + rl) * 256 + c];
                float2* o1 = (float2*)&out[PC_OFF + (grow + rl + 8) * 256 + c];
                *o0 = make_float2(acc[m][j][0] + b0, acc[m][j][1] + b1);
                *o1 = make_float2(acc[m][j][2] + b0, acc[m][j][3] + b1);
            }
        }
    }

    // ---- hd epilogue (nh==0 warps, cols 0..11 valid) ----
    if (nh == 0) {
        int rl0 = rowA + (lane >> 2);
        #pragma unroll
        for (int m = 0; m < 2; ++m) {
            int rl = rl0 + 16 * m;
            #pragma unroll
            for (int j = 0; j < 2; ++j) {
                int cb = 8 * j + 2 * (lane & 3);
                float* o0 = out + HD_OFF + (grow + rl) * 12;
                float* o1 = out + HD_OFF + (grow + rl + 8) * 12;
                if (cb < 12) {
                    float bb = __ldg(&b_hd[cb]);
                    o0[cb] = ahd[m][j][0] + bb;
                    o1[cb] = ahd[m][j][2] + bb;
                }
                if (cb + 1 < 12) {
                    float bb = __ldg(&b_hd[cb + 1]);
                    o0[cb + 1] = ahd[m][j][1] + bb;
                    o1[cb + 1] = ahd[m][j][3] + bb;
                }
            }
        }
    }
}

// ===========================================================================
extern "C" void kernel_launch(void* const* d_in, const int* in_sizes, int n_in,
                              void* d_out, int out_size)
{
    const float* x       = (const float*)d_in[0];
    const float* init_pc = (const float*)d_in[1];
    const float* init_hd = (const float*)d_in[2];
    const float* W_state = (const float*)d_in[3];
    const float* b_state = (const float*)d_in[4];
    const float* W_cell  = (const float*)d_in[5];
    const float* b_cell  = (const float*)d_in[6];
    const float* W_ih    = (const float*)d_in[7];
    const float* W_hh    = (const float*)d_in[8];
    const float* b_ih    = (const float*)d_in[9];
    const float* b_hh    = (const float*)d_in[10];
    const float* W_bn    = (const float*)d_in[11];
    const float* W_pc    = (const float*)d_in[12];
    const float* b_pc    = (const float*)d_in[13];
    const float* W_hd    = (const float*)d_in[14];
    const float* b_hd    = (const float*)d_in[15];
    float* out = (float*)d_out;

    cudaFuncSetAttribute(recur_tc,      cudaFuncAttributeMaxDynamicSharedMemorySize, (int)RS_TOTAL);
    cudaFuncSetAttribute(phase2_kernel, cudaFuncAttributeMaxDynamicSharedMemorySize, (int)SMEM_PH2);

    recur_tc<<<BATCH / 32, 512, RS_TOTAL>>>(x, init_pc, init_hd,
                                            W_state, b_state, W_cell, b_cell,
                                            W_ih, W_hh, b_ih, b_hh, out);
    phase2_kernel<<<(T_STEPS * BATCH) / MT, 256, SMEM_PH2>>>(
        W_bn, W_pc, b_pc, W_hd, b_hd, out);
}

// round 17
// speedup vs baseline: 4.4442x; 1.1183x over previous
#include <cuda_runtime.h>
#include <cuda_bf16.h>
#include <cuda_fp16.h>
#include <math.h>
#include <stdint.h>

// Problem constants
#define T_STEPS 100
#define BATCH   4096
#define NH      128
#define NG      512
#define NPC     256
#define NHD     12
#define NB      256
#define KIN     268   // NPC + NHD

// Output layout: tuple (hd, pc, bn, hs, cs) flattened in order
#define HD_OFF  ((size_t)0)
#define PC_OFF  ((size_t)T_STEPS * BATCH * NHD)
#define BN_OFF  (PC_OFF + (size_t)T_STEPS * BATCH * NPC)
#define HS_OFF  (BN_OFF + (size_t)T_STEPS * BATCH * NB)
#define CS_OFF  (HS_OFF + (size_t)T_STEPS * BATCH * NH)

// Phase-2 tiling constants (needed for image layouts)
#define MT 64
#define SA_STR  136   // fp16 elems/row -> 272 B
#define SW_STR  136
#define SBN_STR 264   // 528 B
#define SPC_STR 72    // 144 B
#define SHD_STR 264

#define A_IMG_BYTES   (MT * SA_STR * 2)        // 17408 per tile
#define WBN_IMG_BYTES (256 * SW_STR * 2)       // 69632
#define WPC_IMG_BYTES (256 * SPC_STR * 2)      // 36864 per K-chunk
#define WHD_IMG_BYTES (16 * SHD_STR * 2)       // 8448
#define N_TILES ((T_STEPS * BATCH) / MT)       // 6400

// Pre-converted fp16 weight images (exact smem layout) + hs fp16 tile images
__device__ __align__(16) unsigned char g_wbn[WBN_IMG_BYTES];
__device__ __align__(16) unsigned char g_wpc[4 * WPC_IMG_BYTES];
__device__ __align__(16) unsigned char g_whd[WHD_IMG_BYTES];
__device__ __align__(16) unsigned char g_hs16[(size_t)N_TILES * A_IMG_BYTES]; // ~111 MB

__device__ __forceinline__ uint32_t smem_u32(const void* p) {
    uint32_t a;
    asm("{ .reg .u64 t; cvta.to.shared.u64 t, %1; cvt.u32.u64 %0, t; }"
        : "=r"(a) : "l"(p));
    return a;
}

// ---- base-PTX tensor ops (compile for compute_103, no 'a' features) ----
#define LDSM_X4(R, addr) \
    asm volatile("ldmatrix.sync.aligned.m8n8.x4.shared.b16 {%0,%1,%2,%3}, [%4];" \
        : "=r"((R)[0]), "=r"((R)[1]), "=r"((R)[2]), "=r"((R)[3]) : "r"(addr))

#define MMA_F16(D, A, b0, b1) \
    asm volatile("mma.sync.aligned.m16n8k16.row.col.f32.f16.f16.f32 " \
        "{%0,%1,%2,%3}, {%4,%5,%6,%7}, {%8,%9}, {%0,%1,%2,%3};" \
        : "+f"((D)[0]), "+f"((D)[1]), "+f"((D)[2]), "+f"((D)[3]) \
        : "r"((A)[0]), "r"((A)[1]), "r"((A)[2]), "r"((A)[3]), "r"(b0), "r"(b1))

// fast activations: __expf + __fdividef only (~1e-6 accuracy, safe at +-inf)
__device__ __forceinline__ float fsig(float v)  {
    float e = __expf(-v);
    return __fdividef(1.0f, 1.0f + e);
}
__device__ __forceinline__ float ftanh(float v) {
    float e = __expf(2.0f * v);
    return 1.0f - __fdividef(2.0f, e + 1.0f);
}

// ---- fp16 pack / hi-lo split helpers ----
__device__ __forceinline__ uint32_t pack2h(float a, float b) {
    return (uint32_t)__half_as_ushort(__float2half_rn(a))
         | ((uint32_t)__half_as_ushort(__float2half_rn(b)) << 16);
}

__device__ __forceinline__ void pack8h_store(unsigned char* dst, const float* v) {
    *(uint4*)dst = make_uint4(pack2h(v[0], v[1]), pack2h(v[2], v[3]),
                              pack2h(v[4], v[5]), pack2h(v[6], v[7]));
}

__device__ __forceinline__ void split8h(char* sm, uint32_t hi_off, uint32_t lo_off,
                                        const float* v) {
    uint32_t H[4], L[4];
    #pragma unroll
    for (int i = 0; i < 4; ++i) {
        __half h0 = __float2half_rn(v[2 * i]);
        __half h1 = __float2half_rn(v[2 * i + 1]);
        __half l0 = __float2half_rn(v[2 * i]     - __half2float(h0));
        __half l1 = __float2half_rn(v[2 * i + 1] - __half2float(h1));
        H[i] = (uint32_t)__half_as_ushort(h0) | ((uint32_t)__half_as_ushort(h1) << 16);
        L[i] = (uint32_t)__half_as_ushort(l0) | ((uint32_t)__half_as_ushort(l1) << 16);
    }
    *(uint4*)(sm + hi_off) = make_uint4(H[0], H[1], H[2], H[3]);
    *(uint4*)(sm + lo_off) = make_uint4(L[0], L[1], L[2], L[3]);
}

__device__ __forceinline__ void split2h(char* sm, uint32_t hi_off, uint32_t lo_off,
                                        float a, float b) {
    __half ha = __float2half_rn(a), hb = __float2half_rn(b);
    __half la = __float2half_rn(a - __half2float(ha));
    __half lb = __float2half_rn(b - __half2float(hb));
    *(uint32_t*)(sm + hi_off) = (uint32_t)__half_as_ushort(ha) | ((uint32_t)__half_as_ushort(hb) << 16);
    *(uint32_t*)(sm + lo_off) = (uint32_t)__half_as_ushort(la) | ((uint32_t)__half_as_ushort(lb) << 16);
}

// ===========================================================================
// prep_kernel: convert W_bn / W_pc / W_hd fp32 -> fp16 smem-image layouts.
// Runs once per launch (~250 KB of writes). No overlap between zeroed pad
// rows (12-15 of W_hd) and filled rows (0-11) -> no race.
// ===========================================================================
__global__ void __launch_bounds__(256)
prep_kernel(const float* __restrict__ W_bn, const float* __restrict__ W_pc,
            const float* __restrict__ W_hd)
{
    const int tid = blockIdx.x * 256 + threadIdx.x;
    const int NT  = gridDim.x * 256;

    // W_bn [256][128] -> g_wbn, row stride 272 B
    for (int b = tid; b < 256 * 16; b += NT) {
        int r = b >> 4, c0 = (b & 15) << 3;
        float v[8];
        *(float4*)&v[0] = *(const float4*)(W_bn + (size_t)r * 128 + c0);
        *(float4*)&v[4] = *(const float4*)(W_bn + (size_t)r * 128 + c0 + 4);
        pack8h_store(g_wbn + r * (SW_STR * 2) + c0 * 2, v);
    }
    // W_pc [256][256] -> 4 chunk images, row stride 144 B
    for (int b = tid; b < 4 * 256 * 8; b += NT) {
        int kc2 = b >> 11, rb = b & 2047;
        int r = rb >> 3, c0 = (rb & 7) << 3;
        float v[8];
        const float* s = W_pc + (size_t)r * 256 + kc2 * 64 + c0;
        *(float4*)&v[0] = *(const float4*)s;
        *(float4*)&v[4] = *(const float4*)(s + 4);
        pack8h_store(g_wpc + kc2 * WPC_IMG_BYTES + r * (SPC_STR * 2) + c0 * 2, v);
    }
    // W_hd pad rows 12..15 zero
    {
        uint4 z = make_uint4(0, 0, 0, 0);
        for (int i = tid; i < (4 * SHD_STR * 2) / 16; i += NT)
            ((uint4*)(g_whd + 12 * (SHD_STR * 2)))[i] = z;
    }
    // W_hd rows 0..11, row stride 528 B
    for (int b = tid; b < 12 * 32; b += NT) {
        int r = b >> 5, c0 = (b & 31) << 3;
        float v[8];
        const float* s = W_hd + (size_t)r * 256 + c0;
        *(float4*)&v[0] = *(const float4*)s;
        *(float4*)&v[4] = *(const float4*)(s + 4);
        pack8h_store(g_whd + r * (SHD_STR * 2) + c0 * 2, v);
    }
}

// ===========================================================================
// Phase 1: recurrence via mma.sync fp16 (2-term split). Same as R16 plus:
// epilogue also writes h in fp16 to g_hs16 in the phase-2 A-tile image layout.
// ===========================================================================
#define RS_WH    0                        // [512][128] fp16 swz = 131072
#define RS_AHI   131072                   // [32][128] fp16 swz = 8192
#define RS_ALO   (RS_AHI + 8192)
#define RS_WIH   (RS_ALO + 8192)          // float4[512]: {w0,w1,w2,bias}
#define RS_XS    (RS_WIH + 8192)          // float4[2][32]
#define RS_HC    (RS_XS + 1024)           // fp32 h0/c0 scratch [2][32][128]
#define RS_TOTAL (RS_HC + 32768)          // 189440
// init-phase overlay inside RS_WH region:
#define RS_INITS 0                        // [32][268] fp32
#define RS_WT    34816                    // [64][129] fp32

__global__ void __launch_bounds__(512, 1)
recur_tc(const float* __restrict__ x,
         const float* __restrict__ init_pc,
         const float* __restrict__ init_hd,
         const float* __restrict__ W_state, const float* __restrict__ b_state,
         const float* __restrict__ W_cell,  const float* __restrict__ b_cell,
         const float* __restrict__ W_ih,    const float* __restrict__ W_hh,
         const float* __restrict__ b_ih,    const float* __restrict__ b_hh,
         float* __restrict__ out)
{
    extern __shared__ char smc[];
    const uint32_t sb = smem_u32(smc);
    const int tid  = threadIdx.x;
    const int wid  = tid >> 5;
    const int lane = tid & 31;
    const int mrow = wid & 1;
    const int jgrp = wid >> 1;            // 0..7, 16 j-cols each
    const int gb0  = blockIdx.x * 32;

    // ---------------- init: h0/c0 SIMT GEMM (K=268), runs once ----------------
    {
        float* initS = (float*)(smc + RS_INITS);
        float* wT    = (float*)(smc + RS_WT);
        float* hS    = (float*)(smc + RS_HC);
        float* cS    = hS + 32 * 128;

        for (int i = tid; i < 32 * KIN; i += 512) {
            int r = i / KIN, k = i - r * KIN;
            float v = (k < 256) ? init_pc[(size_t)(gb0 + r) * 256 + k]
                                : init_hd[(size_t)(gb0 + r) * 12 + (k - 256)];
            initS[r * KIN + k] = v;
        }
        __syncthreads();

        for (int p = 0; p < 2; ++p) {
            const float* W  = p ? W_cell : W_state;
            const float* bb = p ? b_cell : b_state;
            float acc[8];
            #pragma unroll
            for (int o = 0; o < 8; ++o) acc[o] = 0.0f;

            for (int kt = 0; kt < KIN; kt += 64) {
                int len = KIN - kt; if (len > 64) len = 64;
                for (int i = tid; i < 128 * 64; i += 512) {
                    int n = i >> 6, kk = i & 63;
                    if (kk < len) wT[kk * 129 + n] = W[n * KIN + kt + kk];
                }
                __syncthreads();
                for (int kk = 0; kk < len; ++kk) {
                    #pragma unroll
                    for (int o = 0; o < 8; ++o) {
                        int idx = o * 512 + tid;
                        int r = idx >> 7, n = idx & 127;
                        acc[o] += initS[r * KIN + kt + kk] * wT[kk * 129 + n];
                    }
                }
                __syncthreads();
            }
            float* dst = p ? cS : hS;
            #pragma unroll
            for (int o = 0; o < 8; ++o) {
                int idx = o * 512 + tid;
                int r = idx >> 7, n = idx & 127;
                dst[r * 128 + n] = acc[o] + bb[n];
            }
            __syncthreads();
        }
    }

    // ---------------- load W_hh fp16 (swizzled), wih+bias, x[0], h0 split ----
    for (int i = tid; i < 512 * 32; i += 512) {
        int row = i >> 5, q = i & 31;
        float4 w = *(const float4*)&W_hh[row * 128 + 4 * q];
        uint2 h4 = make_uint2(pack2h(w.x, w.y), pack2h(w.z, w.w));
        uint32_t off = ((uint32_t)(8 * q)) ^ (uint32_t)((row & 7) << 4);
        *(uint2*)(smc + RS_WH + row * 256 + off) = h4;
    }
    {
        int n = tid;
        ((float4*)(smc + RS_WIH))[n] =
            make_float4(W_ih[n * 3 + 0], W_ih[n * 3 + 1], W_ih[n * 3 + 2],
                        b_ih[n] + b_hh[n]);
    }
    if (tid < 96) {
        int r = tid / 3, c = tid - 3 * r;
        ((float*)(smc + RS_XS))[r * 4 + c] = x[((size_t)0 * BATCH + gb0 + r) * 3 + c];
    }
    {
        const float* hS = (const float*)(smc + RS_HC);
        int i = tid;
        int row = i >> 4, c0 = (i & 15) * 8;
        uint32_t off = row * 256 + (((uint32_t)(c0 * 2)) ^ (uint32_t)((row & 7) << 4));
        split8h(smc, RS_AHI + off, RS_ALO + off, &hS[row * 128 + c0]);
    }

    // ---------------- per-lane constants ----------------
    const int r1  = 16 * mrow + (lane >> 2);       // epilogue rows r1, r1+8
    const int j0a = jgrp * 16 + 2 * (lane & 3);    // epilogue col base (+8b)

    const int aRowL = 16 * mrow + (lane & 15);
    const uint32_t aBaseH = sb + RS_AHI + aRowL * 256;
    const uint32_t aBaseL = sb + RS_ALO + aRowL * 256;
    const uint32_t aXor   = (uint32_t)((aRowL & 7) << 4);
    const uint32_t aSeg   = (uint32_t)((lane >> 4) * 16);
    const int m4 = lane >> 3;
    const int bRowOff = 8 * (m4 >> 1) + (lane & 7);
    const uint32_t bSeg = (uint32_t)((m4 & 1) * 16);
    uint32_t bBase[4], bXor[4];
    #pragma unroll
    for (int g = 0; g < 4; ++g) {
        int n = g * 128 + jgrp * 16 + bRowOff;
        bBase[g] = sb + RS_WH + n * 256;
        bXor[g]  = (uint32_t)((n & 7) << 4);
    }

    // c-state registers
    float cc[2][4];
    {
        const float* cS = (const float*)(smc + RS_HC) + 32 * 128;
        #pragma unroll
        for (int b = 0; b < 2; ++b) {
            int j0 = j0a + 8 * b;
            cc[b][0] = cS[r1 * 128 + j0];
            cc[b][1] = cS[r1 * 128 + j0 + 1];
            cc[b][2] = cS[(r1 + 8) * 128 + j0];
            cc[b][3] = cS[(r1 + 8) * 128 + j0 + 1];
        }
    }
    __syncthreads();

    // ---------------- time loop ----------------
    for (int t = 0; t < T_STEPS; ++t) {
        float acc[8][4];
        #pragma unroll
        for (int j = 0; j < 8; ++j)
            #pragma unroll
            for (int q = 0; q < 4; ++q) acc[j][q] = 0.0f;

        #pragma unroll
        for (int kc = 0; kc < 8; ++kc) {
            uint32_t ao = (uint32_t)(kc * 32) + aSeg;
            uint32_t aH[4], aL[4];
            LDSM_X4(aH, aBaseH + (ao ^ aXor));
            LDSM_X4(aL, aBaseL + (ao ^ aXor));
            uint32_t bo = (uint32_t)(kc * 32) + bSeg;
            #pragma unroll
            for (int g = 0; g < 4; ++g) {
                uint32_t bf[4];
                LDSM_X4(bf, bBase[g] + (bo ^ bXor[g]));
                int tau = g * 2;
                MMA_F16(acc[tau],     aH, bf[0], bf[1]);
                MMA_F16(acc[tau],     aL, bf[0], bf[1]);
                MMA_F16(acc[tau + 1], aH, bf[2], bf[3]);
                MMA_F16(acc[tau + 1], aL, bf[2], bf[3]);
            }
        }
        __syncthreads();    // all A reads done -> safe to overwrite A below

        // ---- in-register LSTM epilogue ----
        const float4* xs4 = (const float4*)(smc + RS_XS) + (t & 1) * 32;
        float4 xv1 = xs4[r1];
        float4 xv2 = xs4[r1 + 8];
        size_t row1 = (size_t)t * BATCH + gb0 + r1;
        size_t row2 = row1 + 8;

        #pragma unroll
        for (int b = 0; b < 2; ++b) {
            int j0 = j0a + 8 * b;
            float4 wq[4][2];
            #pragma unroll
            for (int g = 0; g < 4; ++g) {
                wq[g][0] = ((const float4*)(smc + RS_WIH))[g * 128 + j0];
                wq[g][1] = ((const float4*)(smc + RS_WIH))[g * 128 + j0 + 1];
            }
            float hv[4];
            #pragma unroll
            for (int q = 0; q < 4; ++q) {
                int cp = q & 1;
                float4 xv = (q >= 2) ? xv2 : xv1;
                float pre[4];
                #pragma unroll
                for (int g = 0; g < 4; ++g)
                    pre[g] = acc[g * 2 + b][q]
                           + xv.x * wq[g][cp].x + xv.y * wq[g][cp].y
                           + xv.z * wq[g][cp].z + wq[g][cp].w;
                float ig = fsig(pre[0]), fg = fsig(pre[1]);
                float gg = ftanh(pre[2]), og = fsig(pre[3]);
                float cn = fg * cc[b][q] + ig * gg;
                cc[b][q] = cn;
                hv[q] = og * ftanh(cn);
            }
            *(float2*)&out[HS_OFF + row1 * 128 + j0] = make_float2(hv[0], hv[1]);
            *(float2*)&out[HS_OFF + row2 * 128 + j0] = make_float2(hv[2], hv[3]);
            *(float2*)&out[CS_OFF + row1 * 128 + j0] = make_float2(cc[b][0], cc[b][1]);
            *(float2*)&out[CS_OFF + row2 * 128 + j0] = make_float2(cc[b][2], cc[b][3]);
            // fp16 copy into phase-2 A-tile image (row stride 272 B)
            {
                size_t i1 = (row1 >> 6) * (size_t)A_IMG_BYTES + (row1 & 63) * 272 + j0 * 2;
                size_t i2 = (row2 >> 6) * (size_t)A_IMG_BYTES + (row2 & 63) * 272 + j0 * 2;
                *(uint32_t*)(g_hs16 + i1) = pack2h(hv[0], hv[1]);
                *(uint32_t*)(g_hs16 + i2) = pack2h(hv[2], hv[3]);
            }
            // next step's A (h split fp16) at swizzled offsets
            uint32_t o1 = r1 * 256 + (((uint32_t)(j0 * 2)) ^ (uint32_t)((r1 & 7) << 4));
            split2h(smc, RS_AHI + o1, RS_ALO + o1, hv[0], hv[1]);
            split2h(smc, RS_AHI + o1 + 2048, RS_ALO + o1 + 2048, hv[2], hv[3]);
        }
        if (t + 1 < T_STEPS && tid < 96) {
            int r = tid / 3, c = tid - 3 * r;
            ((float*)(smc + RS_XS))[((t + 1) & 1) * 128 + r * 4 + c] =
                x[((size_t)(t + 1) * BATCH + gb0 + r) * 3 + c];
        }
        __syncthreads();
    }
}

// ===========================================================================
// Phase 2: fused bn + pc + hd via mma.sync fp16, 1-term, 32x64 warp tiles.
// R17: all inputs arrive as pre-converted fp16 images -> prologue is pure
// uint4 copies (bytes x0.5, conversions x0 vs R16).
// ===========================================================================
#define P_A     0u
#define P_WBN   (P_A + A_IMG_BYTES)        // 17408
#define P_WHD   (P_WBN + WBN_IMG_BYTES)    // 87040
#define SMEM_PH2 (P_WHD + WHD_IMG_BYTES)   // 95488

// stage-B overlay (A / W_bn regions dead after stage A)
#define P_BN    0u
#define P_WPC   (P_BN + MT*SBN_STR*2)      // 33792 .. 70656 (W_hd untouched)

__global__ void __launch_bounds__(256, 2)
phase2_kernel(const float* __restrict__ b_pc, const float* __restrict__ b_hd,
              float* __restrict__ out)
{
    extern __shared__ char smc[];
    const uint32_t sb = smem_u32(smc);
    const int tid  = threadIdx.x;
    const int wid  = tid >> 5;
    const int lane = tid & 31;
    const int mw   = wid & 1;          // row group (32 rows)
    const int nh   = wid >> 1;         // col group (64 cols)
    const int rowA = 32 * mw;
    const size_t grow = (size_t)blockIdx.x * MT;

    const int aRow    = lane & 15;
    const int aSeg    = (lane >> 4) * 16;
    const int m4      = lane >> 3;
    const int bRowOff = 8 * (m4 >> 1) + (lane & 7);
    const int bColOff = 8 * (m4 & 1);

    // ---- prologue: straight image copies (A, W_bn, W_hd) ----
    {
        const uint4* srcA = (const uint4*)(g_hs16 + (size_t)blockIdx.x * A_IMG_BYTES);
        uint4* dstA = (uint4*)(smc + P_A);
        #pragma unroll 2
        for (int i = tid; i < A_IMG_BYTES / 16; i += 256) dstA[i] = srcA[i];

        const uint4* srcW = (const uint4*)g_wbn;
        uint4* dstW = (uint4*)(smc + P_WBN);
        for (int i = tid; i < WBN_IMG_BYTES / 16; i += 256) dstW[i] = srcW[i];

        const uint4* srcH = (const uint4*)g_whd;
        uint4* dstH = (uint4*)(smc + P_WHD);
        #pragma unroll 2
        for (int i = tid; i < WHD_IMG_BYTES / 16; i += 256) dstH[i] = srcH[i];
    }
    __syncthreads();

    float acc[2][8][4];
    #pragma unroll
    for (int m = 0; m < 2; ++m)
        #pragma unroll
        for (int j = 0; j < 8; ++j)
            #pragma unroll
            for (int q = 0; q < 4; ++q) acc[m][j][q] = 0.0f;

    // ---- stage A: D[MT,256] = HS @ W_bn^T  (K=128, 8 chunks) ----
    for (int kc = 0; kc < 8; ++kc) {
        int k0 = kc * 16;
        uint32_t aF0[4], aF1[4];
        LDSM_X4(aF0, sb + P_A + (rowA + aRow) * SA_STR * 2 + k0 * 2 + aSeg);
        LDSM_X4(aF1, sb + P_A + (rowA + 16 + aRow) * SA_STR * 2 + k0 * 2 + aSeg);
        #pragma unroll
        for (int jp = 0; jp < 4; ++jp) {
            uint32_t adB = sb + P_WBN + (nh * 64 + 16 * jp + bRowOff) * SW_STR * 2
                         + (k0 + bColOff) * 2;
            uint32_t bf[4];
            LDSM_X4(bf, adB);
            MMA_F16(acc[0][2*jp],   aF0, bf[0], bf[1]);
            MMA_F16(acc[0][2*jp+1], aF0, bf[2], bf[3]);
            MMA_F16(acc[1][2*jp],   aF1, bf[0], bf[1]);
            MMA_F16(acc[1][2*jp+1], aF1, bf[2], bf[3]);
        }
    }
    __syncthreads();   // all A/W_bn reads done -> overlay safe

    // ---- stage A epilogue: tanh -> bn gmem + fp16 bn smem ----
    {
        int rl0 = rowA + (lane >> 2);
        #pragma unroll
        for (int m = 0; m < 2; ++m) {
            int rl = rl0 + 16 * m;
            #pragma unroll
            for (int j = 0; j < 8; ++j) {
                int c = nh * 64 + 8 * j + 2 * (lane & 3);
                float v00 = ftanh(acc[m][j][0]), v01 = ftanh(acc[m][j][1]);
                float v10 = ftanh(acc[m][j][2]), v11 = ftanh(acc[m][j][3]);
                *(float2*)&out[BN_OFF + (grow + rl) * 256 + c]     = make_float2(v00, v01);
                *(float2*)&out[BN_OFF + (grow + rl + 8) * 256 + c] = make_float2(v10, v11);
                *(uint32_t*)(smc + P_BN + rl * SBN_STR * 2 + c * 2)       = pack2h(v00, v01);
                *(uint32_t*)(smc + P_BN + (rl + 8) * SBN_STR * 2 + c * 2) = pack2h(v10, v11);
            }
        }
    }
    __syncthreads();   // bn smem tile complete

    // ---- stage B part 1: hd accum (nh==0 warps: mw 0/1 cover all 64 rows) --
    float ahd[2][2][4];
    #pragma unroll
    for (int m = 0; m < 2; ++m)
        #pragma unroll
        for (int j = 0; j < 2; ++j)
            #pragma unroll
            for (int q = 0; q < 4; ++q) ahd[m][j][q] = 0.0f;

    if (nh == 0) {
        for (int kc = 0; kc < 16; ++kc) {
            int k0 = kc * 16;
            uint32_t aF0[4], aF1[4];
            LDSM_X4(aF0, sb + P_BN + (rowA + aRow) * SBN_STR * 2 + k0 * 2 + aSeg);
            LDSM_X4(aF1, sb + P_BN + (rowA + 16 + aRow) * SBN_STR * 2 + k0 * 2 + aSeg);
            uint32_t adB = sb + P_WHD + bRowOff * SHD_STR * 2 + (k0 + bColOff) * 2;
            uint32_t bf[4];
            LDSM_X4(bf, adB);
            MMA_F16(ahd[0][0], aF0, bf[0], bf[1]);
            MMA_F16(ahd[0][1], aF0, bf[2], bf[3]);
            MMA_F16(ahd[1][0], aF1, bf[0], bf[1]);
            MMA_F16(ahd[1][1], aF1, bf[2], bf[3]);
        }
    }

    // ---- stage B part 2: pc = bn @ W_pc^T (K=256, stream 4 image chunks) ----
    #pragma unroll
    for (int m = 0; m < 2; ++m)
        #pragma unroll
        for (int j = 0; j < 8; ++j)
            #pragma unroll
            for (int q = 0; q < 4; ++q) acc[m][j][q] = 0.0f;

    for (int kc2 = 0; kc2 < 4; ++kc2) {
        __syncthreads();   // previous chunk's ldmatrix reads complete
        {
            const uint4* src = (const uint4*)(g_wpc + kc2 * WPC_IMG_BYTES);
            uint4* dst = (uint4*)(smc + P_WPC);
            for (int i = tid; i < WPC_IMG_BYTES / 16; i += 256) dst[i] = src[i];
        }
        __syncthreads();
        for (int kc = 0; kc < 4; ++kc) {
            int kk = kc2 * 64 + kc * 16;
            uint32_t aF0[4], aF1[4];
            LDSM_X4(aF0, sb + P_BN + (rowA + aRow) * SBN_STR * 2 + kk * 2 + aSeg);
            LDSM_X4(aF1, sb + P_BN + (rowA + 16 + aRow) * SBN_STR * 2 + kk * 2 + aSeg);
            #pragma unroll
            for (int jp = 0; jp < 4; ++jp) {
                uint32_t adB = sb + P_WPC + (nh * 64 + 16 * jp + bRowOff) * SPC_STR * 2
                             + (kc * 16 + bColOff) * 2;
                uint32_t bf[4];
                LDSM_X4(bf, adB);
                MMA_F16(acc[0][2*jp],   aF0, bf[0], bf[1]);
                MMA_F16(acc[0][2*jp+1], aF0, bf[2], bf[3]);
                MMA_F16(acc[1][2*jp],   aF1, bf[0], bf[1]);
                MMA_F16(acc[1][2*jp+1], aF1, bf[2], bf[3]);
            }
        }
    }

    // ---- pc epilogue ----
    {
        int rl0 = rowA + (lane >> 2);
        #pragma unroll
        for (int m = 0; m < 2; ++m) {
            int rl = rl0 + 16 * m;
            #pragma unroll
            for (int j = 0; j < 8; ++j) {
                int c = nh * 64 + 8 * j + 2 * (lane & 3);
                float b0 = __ldg(&b_pc[c]), b1 = __ldg(&b_pc[c + 1]);
                float2* o0 = (float2*)&out[PC_OFF + (grow + rl) * 256 + c];
                float2* o1 = (float2*)&out[PC_OFF + (grow + rl + 8) * 256 + c];
                *o0 = make_float2(acc[m][j][0] + b0, acc[m][j][1] + b1);
                *o1 = make_float2(acc[m][j][2] + b0, acc[m][j][3] + b1);
            }
        }
    }

    // ---- hd epilogue (nh==0 warps, cols 0..11 valid) ----
    if (nh == 0) {
        int rl0 = rowA + (lane >> 2);
        #pragma unroll
        for (int m = 0; m < 2; ++m) {
            int rl = rl0 + 16 * m;
            #pragma unroll
            for (int j = 0; j < 2; ++j) {
                int cb = 8 * j + 2 * (lane & 3);
                float* o0 = out + HD_OFF + (grow + rl) * 12;
                float* o1 = out + HD_OFF + (grow + rl + 8) * 12;
                if (cb < 12) {
                    float bb = __ldg(&b_hd[cb]);
                    o0[cb] = ahd[m][j][0] + bb;
                    o1[cb] = ahd[m][j][2] + bb;
                }
                if (cb + 1 < 12) {
                    float bb = __ldg(&b_hd[cb + 1]);
                    o0[cb + 1] = ahd[m][j][1] + bb;
                    o1[cb + 1] = ahd[m][j][3] + bb;
                }
            }
        }
    }
}

// ===========================================================================
extern "C" void kernel_launch(void* const* d_in, const int* in_sizes, int n_in,
                              void* d_out, int out_size)
{
    const float* x       = (const float*)d_in[0];
    const float* init_pc = (const float*)d_in[1];
    const float* init_hd = (const float*)d_in[2];
    const float* W_state = (const float*)d_in[3];
    const float* b_state = (const float*)d_in[4];
    const float* W_cell  = (const float*)d_in[5];
    const float* b_cell  = (const float*)d_in[6];
    const float* W_ih    = (const float*)d_in[7];
    const float* W_hh    = (const float*)d_in[8];
    const float* b_ih    = (const float*)d_in[9];
    const float* b_hh    = (const float*)d_in[10];
    const float* W_bn    = (const float*)d_in[11];
    const float* W_pc    = (const float*)d_in[12];
    const float* b_pc    = (const float*)d_in[13];
    const float* W_hd    = (const float*)d_in[14];
    const float* b_hd    = (const float*)d_in[15];
    float* out = (float*)d_out;

    cudaFuncSetAttribute(recur_tc,      cudaFuncAttributeMaxDynamicSharedMemorySize, (int)RS_TOTAL);
    cudaFuncSetAttribute(phase2_kernel, cudaFuncAttributeMaxDynamicSharedMemorySize, (int)SMEM_PH2);

    prep_kernel<<<48, 256>>>(W_bn, W_pc, W_hd);
    recur_tc<<<BATCH / 32, 512, RS_TOTAL>>>(x, init_pc, init_hd,
                                            W_state, b_state, W_cell, b_cell,
                                            W_ih, W_hh, b_ih, b_hh, out);
    phase2_kernel<<<(T_STEPS * BATCH) / MT, 256, SMEM_PH2>>>(b_pc, b_hd, out);
}